// round 3
// baseline (speedup 1.0000x reference)
#include <cuda_runtime.h>
#include <cuda_bf16.h>
#include <cstdint>

#define NN 50000
#define NE 800000
#define DD 128
#define BN_EPS 1e-5f

// ---------------- scratch (device globals; no allocation allowed) ----------------
__device__ float g_h[NN * DD];        // current node features
__device__ float g_agg[NN * DD];      // aggregated messages
__device__ float g_mid[NN * 2 * DD];  // after first MLP linear (relu)
__device__ float g_h2[NN * DD];       // after second linear (pre-BN)
__device__ int   g_deg[NN];
__device__ int   g_rowptr[NN + 1];
__device__ int   g_wr[NN];
__device__ int   g_col[NE];
__device__ int   g_cnt1[NN * 7];
__device__ int   g_cnt2[NN * 3];
__device__ float g_colsum[DD];
__device__ float g_colsq[DD];

// ---------------- zero counters ----------------
__global__ void zero_counts_kernel() {
    int idx = blockIdx.x * blockDim.x + threadIdx.x;
    int total = NN + NN * 7 + NN * 3;
    for (int i = idx; i < total; i += gridDim.x * blockDim.x) {
        if (i < NN) g_deg[i] = 0;
        else if (i < NN + NN * 7) g_cnt1[i - NN] = 0;
        else g_cnt2[i - NN - NN * 7] = 0;
    }
}

__global__ void zero_bn_kernel() {
    int t = threadIdx.x;
    if (t < DD) { g_colsum[t] = 0.f; g_colsq[t] = 0.f; }
}

// ---------------- input embedding: h = xemb1[x0] + xemb2[x1] ----------------
__global__ void embed_kernel(const int* __restrict__ x,
                             const float* __restrict__ xemb1,
                             const float* __restrict__ xemb2) {
    int idx = blockIdx.x * blockDim.x + threadIdx.x;   // one thread per (node, float4)
    if (idx >= NN * (DD / 4)) return;
    int v = idx >> 5;
    int c4 = idx & 31;
    int a = x[2 * v];
    int b = x[2 * v + 1];
    float4 va = ((const float4*)(xemb1 + (size_t)a * DD))[c4];
    float4 vb = ((const float4*)(xemb2 + (size_t)b * DD))[c4];
    float4 o;
    o.x = va.x + vb.x; o.y = va.y + vb.y; o.z = va.z + vb.z; o.w = va.w + vb.w;
    ((float4*)(g_h + (size_t)v * DD))[c4] = o;
}

// ---------------- histogram: degree + attr counts per dst ----------------
__global__ void hist_kernel(const int* __restrict__ edge_index,
                            const int* __restrict__ edge_attr) {
    int e = blockIdx.x * blockDim.x + threadIdx.x;
    if (e >= NE) return;
    int dst = edge_index[NE + e];
    atomicAdd(&g_deg[dst], 1);
    atomicAdd(&g_cnt1[dst * 7 + edge_attr[2 * e]], 1);
    atomicAdd(&g_cnt2[dst * 3 + edge_attr[2 * e + 1]], 1);
}

// ---------------- exclusive scan of degrees (single block) ----------------
__global__ void scan_kernel() {
    __shared__ int ssum[1024];
    int t = threadIdx.x;
    const int CH = (NN + 1023) / 1024;  // 49
    int start = t * CH;
    int stop = min(start + CH, NN);
    int s = 0;
    for (int i = start; i < stop; i++) s += g_deg[i];
    ssum[t] = s;
    __syncthreads();
    for (int off = 1; off < 1024; off <<= 1) {
        int v = (t >= off) ? ssum[t - off] : 0;
        __syncthreads();
        ssum[t] += v;
        __syncthreads();
    }
    int base = (t == 0) ? 0 : ssum[t - 1];
    for (int i = start; i < stop; i++) {
        g_rowptr[i] = base;
        g_wr[i] = base;
        base += g_deg[i];
    }
    if (t == 1023) g_rowptr[NN] = ssum[1023];
}

// ---------------- scatter src indices into CSR ----------------
__global__ void scatter_kernel(const int* __restrict__ edge_index) {
    int e = blockIdx.x * blockDim.x + threadIdx.x;
    if (e >= NE) return;
    int src = edge_index[e];
    int dst = edge_index[NE + e];
    int pos = atomicAdd(&g_wr[dst], 1);
    g_col[pos] = src;
}

// ---------------- aggregation: one warp per node, atomic-free ----------------
// agg[v] = h[v] + e1[4] + e2[0]  (self loop)
//        + sum_{j in csr[v]} h[col[j]]
//        + sum_t cnt1[v][t]*e1[t] + sum_t cnt2[v][t]*e2[t]
__global__ __launch_bounds__(256) void aggregate_kernel(
        const float* __restrict__ e1l, const float* __restrict__ e2l) {
    __shared__ float4 se[(7 + 3) * 32];  // e1: [0..224), e2: [224..320)
    for (int i = threadIdx.x; i < (7 + 3) * 32; i += blockDim.x) {
        se[i] = (i < 7 * 32) ? ((const float4*)e1l)[i]
                             : ((const float4*)e2l)[i - 7 * 32];
    }
    __syncthreads();

    int tid = threadIdx.x;
    int warp = tid >> 5;
    int lane = tid & 31;
    int v = blockIdx.x * 8 + warp;
    if (v >= NN) return;

    // self node + self-loop edge embedding e1[4], e2[0]
    float4 acc = ((const float4*)(g_h + (size_t)v * DD))[lane];
    float4 t4 = se[4 * 32 + lane];
    acc.x += t4.x; acc.y += t4.y; acc.z += t4.z; acc.w += t4.w;
    t4 = se[7 * 32 + lane];
    acc.x += t4.x; acc.y += t4.y; acc.z += t4.z; acc.w += t4.w;

    int beg = g_rowptr[v];
    int end = g_rowptr[v + 1];
    for (int j = beg; j < end; j++) {
        int s = g_col[j];
        float4 hv = ((const float4*)(g_h + (size_t)s * DD))[lane];
        acc.x += hv.x; acc.y += hv.y; acc.z += hv.z; acc.w += hv.w;
    }

#pragma unroll
    for (int t = 0; t < 7; t++) {
        int c = g_cnt1[v * 7 + t];
        if (c) {
            float fc = (float)c;
            float4 ev = se[t * 32 + lane];
            acc.x += fc * ev.x; acc.y += fc * ev.y; acc.z += fc * ev.z; acc.w += fc * ev.w;
        }
    }
#pragma unroll
    for (int t = 0; t < 3; t++) {
        int c = g_cnt2[v * 3 + t];
        if (c) {
            float fc = (float)c;
            float4 ev = se[(7 + t) * 32 + lane];
            acc.x += fc * ev.x; acc.y += fc * ev.y; acc.z += fc * ev.z; acc.w += fc * ev.w;
        }
    }
    ((float4*)(g_agg + (size_t)v * DD))[lane] = acc;
}

// ---------------- SGEMM: C = op(A @ B + bias), 128x128x16 tile, 8x8 microtile ----
template <bool RELU>
__global__ __launch_bounds__(256) void gemm_kernel(
        const float* __restrict__ A, const float* __restrict__ B,
        const float* __restrict__ bias, float* __restrict__ C,
        int M, int N, int K) {
    constexpr int BM = 128, BN = 128, BK = 16;
    __shared__ float As[BK][BM];
    __shared__ float Bs[BK][BN];
    int tid = threadIdx.x;
    int tx = tid & 15;
    int ty = tid >> 4;
    int rowBase = blockIdx.y * BM;
    int colBase = blockIdx.x * BN;

    float acc[8][8];
#pragma unroll
    for (int i = 0; i < 8; i++)
#pragma unroll
        for (int j = 0; j < 8; j++) acc[i][j] = 0.f;

    int la_r = tid >> 2;          // 0..63
    int la_c = (tid & 3) * 4;     // 0,4,8,12
    int lb_r = tid >> 5;          // 0..7
    int lb_c = (tid & 31) * 4;    // 0..124

    for (int k0 = 0; k0 < K; k0 += BK) {
#pragma unroll
        for (int i = 0; i < 2; i++) {
            int r = rowBase + la_r + i * 64;
            float4 v = (r < M) ? *(const float4*)(A + (size_t)r * K + k0 + la_c)
                               : make_float4(0.f, 0.f, 0.f, 0.f);
            As[la_c + 0][la_r + i * 64] = v.x;
            As[la_c + 1][la_r + i * 64] = v.y;
            As[la_c + 2][la_r + i * 64] = v.z;
            As[la_c + 3][la_r + i * 64] = v.w;
        }
#pragma unroll
        for (int i = 0; i < 2; i++) {
            int r = k0 + lb_r + i * 8;
            *(float4*)&Bs[lb_r + i * 8][lb_c] =
                *(const float4*)(B + (size_t)r * N + colBase + lb_c);
        }
        __syncthreads();
#pragma unroll
        for (int kk = 0; kk < BK; kk++) {
            float a[8], b[8];
            ((float4*)a)[0] = *(float4*)&As[kk][ty * 8];
            ((float4*)a)[1] = *(float4*)&As[kk][ty * 8 + 4];
            ((float4*)b)[0] = *(float4*)&Bs[kk][tx * 8];
            ((float4*)b)[1] = *(float4*)&Bs[kk][tx * 8 + 4];
#pragma unroll
            for (int i = 0; i < 8; i++)
#pragma unroll
                for (int j = 0; j < 8; j++) acc[i][j] += a[i] * b[j];
        }
        __syncthreads();
    }

#pragma unroll
    for (int i = 0; i < 8; i++) {
        int r = rowBase + ty * 8 + i;
        if (r >= M) continue;
#pragma unroll
        for (int j = 0; j < 8; j += 4) {
            int c = colBase + tx * 8 + j;
            float4 v;
            v.x = acc[i][j + 0] + bias[c + 0];
            v.y = acc[i][j + 1] + bias[c + 1];
            v.z = acc[i][j + 2] + bias[c + 2];
            v.w = acc[i][j + 3] + bias[c + 3];
            if (RELU) {
                v.x = fmaxf(v.x, 0.f); v.y = fmaxf(v.y, 0.f);
                v.z = fmaxf(v.z, 0.f); v.w = fmaxf(v.w, 0.f);
            }
            *(float4*)(C + (size_t)r * N + c) = v;
        }
    }
}

// ---------------- BN column reduce ----------------
__global__ void bn_reduce_kernel(const float* __restrict__ X) {
    int c = threadIdx.x;  // 128 threads
    int r0 = blockIdx.x * 128;
    float s = 0.f, s2 = 0.f;
    int rmax = min(r0 + 128, NN);
    for (int r = r0; r < rmax; r++) {
        float v = X[(size_t)r * DD + c];
        s += v;
        s2 += v * v;
    }
    atomicAdd(&g_colsum[c], s);
    atomicAdd(&g_colsq[c], s2);
}

// ---------------- BN apply (+ optional relu) ----------------
__global__ void bn_apply_kernel(const float* __restrict__ X,
                                const float* __restrict__ gamma,
                                const float* __restrict__ beta,
                                float* __restrict__ Y, int do_relu) {
    int idx = blockIdx.x * blockDim.x + threadIdx.x;
    if (idx >= NN * (DD / 4)) return;
    int v = idx >> 5;
    int c4 = idx & 31;
    int c = c4 * 4;
    float4 x = ((const float4*)(X + (size_t)v * DD))[c4];
    float invn = 1.0f / (float)NN;
    float o[4];
    float xi[4] = {x.x, x.y, x.z, x.w};
#pragma unroll
    for (int k = 0; k < 4; k++) {
        float mu = g_colsum[c + k] * invn;
        float var = g_colsq[c + k] * invn - mu * mu;
        float rs = rsqrtf(var + BN_EPS);
        float y = gamma[c + k] * (xi[k] - mu) * rs + beta[c + k];
        if (do_relu) y = fmaxf(y, 0.f);
        o[k] = y;
    }
    float4 yo = make_float4(o[0], o[1], o[2], o[3]);
    ((float4*)(Y + (size_t)v * DD))[c4] = yo;
}

// ---------------- launch ----------------
extern "C" void kernel_launch(void* const* d_in, const int* in_sizes, int n_in,
                              void* d_out, int out_size) {
    const int* x          = (const int*)d_in[0];
    const int* edge_index = (const int*)d_in[1];
    const int* edge_attr  = (const int*)d_in[2];
    // d_in[3] = batch (unused)
    const float* xemb1 = (const float*)d_in[4];
    const float* xemb2 = (const float*)d_in[5];
    const float* e1    = (const float*)d_in[6];
    const float* e2    = (const float*)d_in[7];
    const float* W1    = (const float*)d_in[8];
    const float* b1    = (const float*)d_in[9];
    const float* W2    = (const float*)d_in[10];
    const float* b2    = (const float*)d_in[11];
    const float* gamma = (const float*)d_in[12];
    const float* beta  = (const float*)d_in[13];
    float* out = (float*)d_out;

    // CRITICAL: resolve REAL device addresses of the __device__ scratch symbols.
    // Passing the symbol name directly from host code hands the kernel the host
    // shadow address (silently "valid" on GB300 via ATS -> reads zeros).
    float *p_h, *p_agg, *p_mid, *p_h2;
    cudaGetSymbolAddress((void**)&p_h,   g_h);
    cudaGetSymbolAddress((void**)&p_agg, g_agg);
    cudaGetSymbolAddress((void**)&p_mid, g_mid);
    cudaGetSymbolAddress((void**)&p_h2,  g_h2);

    // build graph structure (layer-independent)
    zero_counts_kernel<<<1024, 256>>>();
    embed_kernel<<<(NN * 32 + 255) / 256, 256>>>(x, xemb1, xemb2);
    hist_kernel<<<(NE + 255) / 256, 256>>>(edge_index, edge_attr);
    scan_kernel<<<1, 1024>>>();
    scatter_kernel<<<(NE + 255) / 256, 256>>>(edge_index);

    for (int l = 0; l < 2; l++) {
        const float* e1l = e1 + (size_t)l * 7 * DD;
        const float* e2l = e2 + (size_t)l * 3 * DD;
        const float* W1l = W1 + (size_t)l * DD * 2 * DD;
        const float* b1l = b1 + (size_t)l * 2 * DD;
        const float* W2l = W2 + (size_t)l * 2 * DD * DD;
        const float* b2l = b2 + (size_t)l * DD;
        const float* gl = gamma + (size_t)l * DD;
        const float* bl = beta + (size_t)l * DD;

        aggregate_kernel<<<(NN + 7) / 8, 256>>>(e1l, e2l);
        gemm_kernel<true><<<dim3(2, (NN + 127) / 128), 256>>>(
            p_agg, W1l, b1l, p_mid, NN, 2 * DD, DD);
        gemm_kernel<false><<<dim3(1, (NN + 127) / 128), 256>>>(
            p_mid, W2l, b2l, p_h2, NN, DD, 2 * DD);
        zero_bn_kernel<<<1, 128>>>();
        bn_reduce_kernel<<<(NN + 127) / 128, 128>>>(p_h2);
        bn_apply_kernel<<<(NN * 32 + 255) / 256, 256>>>(
            p_h2, gl, bl, (l == 0) ? p_h : out, (l == 0) ? 1 : 0);
    }
}

// round 4
// speedup vs baseline: 1.0814x; 1.0814x over previous
#include <cuda_runtime.h>
#include <cuda_bf16.h>
#include <cstdint>

#define NN 50000
#define NE 800000
#define DD 128
#define BN_EPS 1e-5f

#define SCAN_B 256
#define SCAN_G ((NN + SCAN_B - 1) / SCAN_B)   // 196

// ---------------- scratch (device globals; no allocation allowed) ----------------
__device__ float g_h[NN * DD];
__device__ float g_agg[NN * DD];
__device__ float g_mid[NN * 2 * DD];
__device__ float g_h2[NN * DD];
__device__ int   g_deg[NN];
__device__ int   g_rowptr[NN + 1];
__device__ int   g_wr[NN];
__device__ int   g_col[NE];
__device__ int   g_cnt1[NN * 7];
__device__ int   g_cnt2[NN * 3];
__device__ float g_colsum[DD];
__device__ float g_colsq[DD];
__device__ int   g_bsum[SCAN_G];
__device__ int   g_boff[SCAN_G];

// ---------------- f32x2 packed helpers ----------------
__device__ __forceinline__ unsigned long long pack2(float x, float y) {
    unsigned long long r;
    asm("mov.b64 %0, {%1, %2};" : "=l"(r) : "f"(x), "f"(y));
    return r;
}
__device__ __forceinline__ unsigned long long ffma2(
        unsigned long long a, unsigned long long b, unsigned long long c) {
    unsigned long long d;
    asm("fma.rn.f32x2 %0, %1, %2, %3;" : "=l"(d) : "l"(a), "l"(b), "l"(c));
    return d;
}
__device__ __forceinline__ void unpack2(unsigned long long v, float& x, float& y) {
    asm("mov.b64 {%0, %1}, %2;" : "=f"(x), "=f"(y) : "l"(v));
}

// ---------------- zero counters ----------------
__global__ void zero_counts_kernel() {
    int idx = blockIdx.x * blockDim.x + threadIdx.x;
    int total = NN + NN * 7 + NN * 3;
    for (int i = idx; i < total; i += gridDim.x * blockDim.x) {
        if (i < NN) g_deg[i] = 0;
        else if (i < NN + NN * 7) g_cnt1[i - NN] = 0;
        else g_cnt2[i - NN - NN * 7] = 0;
    }
}

__global__ void zero_bn_kernel() {
    int t = threadIdx.x;
    if (t < DD) { g_colsum[t] = 0.f; g_colsq[t] = 0.f; }
}

// ---------------- input embedding ----------------
__global__ void embed_kernel(const int* __restrict__ x,
                             const float* __restrict__ xemb1,
                             const float* __restrict__ xemb2) {
    int idx = blockIdx.x * blockDim.x + threadIdx.x;
    if (idx >= NN * (DD / 4)) return;
    int v = idx >> 5;
    int c4 = idx & 31;
    int a = x[2 * v];
    int b = x[2 * v + 1];
    float4 va = ((const float4*)(xemb1 + (size_t)a * DD))[c4];
    float4 vb = ((const float4*)(xemb2 + (size_t)b * DD))[c4];
    float4 o;
    o.x = va.x + vb.x; o.y = va.y + vb.y; o.z = va.z + vb.z; o.w = va.w + vb.w;
    ((float4*)(g_h + (size_t)v * DD))[c4] = o;
}

// ---------------- histogram ----------------
__global__ void hist_kernel(const int* __restrict__ edge_index,
                            const int* __restrict__ edge_attr) {
    int e = blockIdx.x * blockDim.x + threadIdx.x;
    if (e >= NE) return;
    int dst = edge_index[NE + e];
    atomicAdd(&g_deg[dst], 1);
    atomicAdd(&g_cnt1[dst * 7 + edge_attr[2 * e]], 1);
    atomicAdd(&g_cnt2[dst * 3 + edge_attr[2 * e + 1]], 1);
}

// ---------------- multi-block scan (3 kernels) ----------------
__global__ void scan1_kernel() {   // per-block sums of degrees
    __shared__ int sh[SCAN_B];
    int t = threadIdx.x;
    int i = blockIdx.x * SCAN_B + t;
    sh[t] = (i < NN) ? g_deg[i] : 0;
    __syncthreads();
    for (int off = SCAN_B / 2; off > 0; off >>= 1) {
        if (t < off) sh[t] += sh[t + off];
        __syncthreads();
    }
    if (t == 0) g_bsum[blockIdx.x] = sh[0];
}

__global__ void scan2_kernel() {   // exclusive scan of 196 block sums (1 block)
    __shared__ int sh[SCAN_B];
    int t = threadIdx.x;
    sh[t] = (t < SCAN_G) ? g_bsum[t] : 0;
    __syncthreads();
    for (int off = 1; off < SCAN_B; off <<= 1) {
        int v = (t >= off) ? sh[t - off] : 0;
        __syncthreads();
        sh[t] += v;
        __syncthreads();
    }
    if (t < SCAN_G) g_boff[t] = (t == 0) ? 0 : sh[t - 1];
}

__global__ void scan3_kernel() {   // local exclusive scan + block offset
    __shared__ int sh[SCAN_B];
    int t = threadIdx.x;
    int i = blockIdx.x * SCAN_B + t;
    int d = (i < NN) ? g_deg[i] : 0;
    sh[t] = d;
    __syncthreads();
    for (int off = 1; off < SCAN_B; off <<= 1) {
        int v = (t >= off) ? sh[t - off] : 0;
        __syncthreads();
        sh[t] += v;
        __syncthreads();
    }
    if (i < NN) {
        int excl = g_boff[blockIdx.x] + sh[t] - d;
        g_rowptr[i] = excl;
        g_wr[i] = excl;
        if (i == NN - 1) g_rowptr[NN] = excl + d;
    }
}

// ---------------- scatter src indices into CSR ----------------
__global__ void scatter_kernel(const int* __restrict__ edge_index) {
    int e = blockIdx.x * blockDim.x + threadIdx.x;
    if (e >= NE) return;
    int src = edge_index[e];
    int dst = edge_index[NE + e];
    int pos = atomicAdd(&g_wr[dst], 1);
    g_col[pos] = src;
}

// ---------------- aggregation: one warp per node ----------------
__global__ __launch_bounds__(256) void aggregate_kernel(
        const float* __restrict__ e1l, const float* __restrict__ e2l) {
    __shared__ float4 se[(7 + 3) * 32];
    for (int i = threadIdx.x; i < (7 + 3) * 32; i += blockDim.x) {
        se[i] = (i < 7 * 32) ? ((const float4*)e1l)[i]
                             : ((const float4*)e2l)[i - 7 * 32];
    }
    __syncthreads();

    int tid = threadIdx.x;
    int warp = tid >> 5;
    int lane = tid & 31;
    int v = blockIdx.x * 8 + warp;
    if (v >= NN) return;

    float4 acc = ((const float4*)(g_h + (size_t)v * DD))[lane];
    float4 t4 = se[4 * 32 + lane];
    acc.x += t4.x; acc.y += t4.y; acc.z += t4.z; acc.w += t4.w;
    t4 = se[7 * 32 + lane];
    acc.x += t4.x; acc.y += t4.y; acc.z += t4.z; acc.w += t4.w;

    int beg = g_rowptr[v];
    int end = g_rowptr[v + 1];
    for (int j = beg; j < end; j++) {
        int s = g_col[j];
        float4 hv = ((const float4*)(g_h + (size_t)s * DD))[lane];
        acc.x += hv.x; acc.y += hv.y; acc.z += hv.z; acc.w += hv.w;
    }

#pragma unroll
    for (int t = 0; t < 7; t++) {
        int c = g_cnt1[v * 7 + t];
        if (c) {
            float fc = (float)c;
            float4 ev = se[t * 32 + lane];
            acc.x += fc * ev.x; acc.y += fc * ev.y; acc.z += fc * ev.z; acc.w += fc * ev.w;
        }
    }
#pragma unroll
    for (int t = 0; t < 3; t++) {
        int c = g_cnt2[v * 3 + t];
        if (c) {
            float fc = (float)c;
            float4 ev = se[(7 + t) * 32 + lane];
            acc.x += fc * ev.x; acc.y += fc * ev.y; acc.z += fc * ev.z; acc.w += fc * ev.w;
        }
    }
    ((float4*)(g_agg + (size_t)v * DD))[lane] = acc;
}

// ---------------- SGEMM with f32x2 packed FMA ----------------
// C = op(A @ B + bias); 128x128x16 tile, 8x8 microtile, FFMA2 inner loop.
template <bool RELU>
__global__ __launch_bounds__(256) void gemm_kernel(
        const float* __restrict__ A, const float* __restrict__ B,
        const float* __restrict__ bias, float* __restrict__ C,
        int M, int N, int K) {
    constexpr int BM = 128, BN = 128, BK = 16;
    constexpr int AS = 132;   // padded stride to break transpose-store conflicts
    __shared__ float As[BK][AS];
    __shared__ float Bs[BK][BN];
    int tid = threadIdx.x;
    int tx = tid & 15;
    int ty = tid >> 4;
    int rowBase = blockIdx.y * BM;
    int colBase = blockIdx.x * BN;

    unsigned long long acc2[8][4];
#pragma unroll
    for (int i = 0; i < 8; i++)
#pragma unroll
        for (int j = 0; j < 4; j++) acc2[i][j] = 0ull;

    int la_r = tid >> 2;
    int la_c = (tid & 3) * 4;
    int lb_r = tid >> 5;
    int lb_c = (tid & 31) * 4;

    for (int k0 = 0; k0 < K; k0 += BK) {
#pragma unroll
        for (int i = 0; i < 2; i++) {
            int r = rowBase + la_r + i * 64;
            float4 v = (r < M) ? *(const float4*)(A + (size_t)r * K + k0 + la_c)
                               : make_float4(0.f, 0.f, 0.f, 0.f);
            As[la_c + 0][la_r + i * 64] = v.x;
            As[la_c + 1][la_r + i * 64] = v.y;
            As[la_c + 2][la_r + i * 64] = v.z;
            As[la_c + 3][la_r + i * 64] = v.w;
        }
#pragma unroll
        for (int i = 0; i < 2; i++) {
            int r = k0 + lb_r + i * 8;
            *(float4*)&Bs[lb_r + i * 8][lb_c] =
                *(const float4*)(B + (size_t)r * N + colBase + lb_c);
        }
        __syncthreads();
#pragma unroll
        for (int kk = 0; kk < BK; kk++) {
            float a[8], b[8];
            ((float4*)a)[0] = *(float4*)&As[kk][ty * 8];
            ((float4*)a)[1] = *(float4*)&As[kk][ty * 8 + 4];
            ((float4*)b)[0] = *(float4*)&Bs[kk][tx * 8];
            ((float4*)b)[1] = *(float4*)&Bs[kk][tx * 8 + 4];
            unsigned long long a2[8], b2[4];
#pragma unroll
            for (int i = 0; i < 8; i++) a2[i] = pack2(a[i], a[i]);
#pragma unroll
            for (int j = 0; j < 4; j++) b2[j] = pack2(b[2 * j], b[2 * j + 1]);
#pragma unroll
            for (int i = 0; i < 8; i++)
#pragma unroll
                for (int j = 0; j < 4; j++)
                    acc2[i][j] = ffma2(a2[i], b2[j], acc2[i][j]);
        }
        __syncthreads();
    }

#pragma unroll
    for (int i = 0; i < 8; i++) {
        int r = rowBase + ty * 8 + i;
        if (r >= M) continue;
#pragma unroll
        for (int j = 0; j < 8; j += 4) {
            int c = colBase + tx * 8 + j;
            float f0, f1, f2, f3;
            unpack2(acc2[i][j / 2], f0, f1);
            unpack2(acc2[i][j / 2 + 1], f2, f3);
            float4 v;
            v.x = f0 + bias[c + 0];
            v.y = f1 + bias[c + 1];
            v.z = f2 + bias[c + 2];
            v.w = f3 + bias[c + 3];
            if (RELU) {
                v.x = fmaxf(v.x, 0.f); v.y = fmaxf(v.y, 0.f);
                v.z = fmaxf(v.z, 0.f); v.w = fmaxf(v.w, 0.f);
            }
            *(float4*)(C + (size_t)r * N + c) = v;
        }
    }
}

// ---------------- BN column reduce ----------------
__global__ void bn_reduce_kernel(const float* __restrict__ X) {
    int c = threadIdx.x;
    int r0 = blockIdx.x * 128;
    float s = 0.f, s2 = 0.f;
    int rmax = min(r0 + 128, NN);
    for (int r = r0; r < rmax; r++) {
        float v = X[(size_t)r * DD + c];
        s += v;
        s2 += v * v;
    }
    atomicAdd(&g_colsum[c], s);
    atomicAdd(&g_colsq[c], s2);
}

// ---------------- BN apply (+ optional relu) ----------------
__global__ void bn_apply_kernel(const float* __restrict__ X,
                                const float* __restrict__ gamma,
                                const float* __restrict__ beta,
                                float* __restrict__ Y, int do_relu) {
    int idx = blockIdx.x * blockDim.x + threadIdx.x;
    if (idx >= NN * (DD / 4)) return;
    int v = idx >> 5;
    int c4 = idx & 31;
    int c = c4 * 4;
    float4 x = ((const float4*)(X + (size_t)v * DD))[c4];
    float invn = 1.0f / (float)NN;
    float o[4];
    float xi[4] = {x.x, x.y, x.z, x.w};
#pragma unroll
    for (int k = 0; k < 4; k++) {
        float mu = g_colsum[c + k] * invn;
        float var = g_colsq[c + k] * invn - mu * mu;
        float rs = rsqrtf(var + BN_EPS);
        float y = gamma[c + k] * (xi[k] - mu) * rs + beta[c + k];
        if (do_relu) y = fmaxf(y, 0.f);
        o[k] = y;
    }
    ((float4*)(Y + (size_t)v * DD))[c4] = make_float4(o[0], o[1], o[2], o[3]);
}

// ---------------- launch ----------------
extern "C" void kernel_launch(void* const* d_in, const int* in_sizes, int n_in,
                              void* d_out, int out_size) {
    const int* x          = (const int*)d_in[0];
    const int* edge_index = (const int*)d_in[1];
    const int* edge_attr  = (const int*)d_in[2];
    const float* xemb1 = (const float*)d_in[4];
    const float* xemb2 = (const float*)d_in[5];
    const float* e1    = (const float*)d_in[6];
    const float* e2    = (const float*)d_in[7];
    const float* W1    = (const float*)d_in[8];
    const float* b1    = (const float*)d_in[9];
    const float* W2    = (const float*)d_in[10];
    const float* b2    = (const float*)d_in[11];
    const float* gamma = (const float*)d_in[12];
    const float* beta  = (const float*)d_in[13];
    float* out = (float*)d_out;

    // resolve REAL device addresses of __device__ scratch symbols
    float *p_h, *p_agg, *p_mid, *p_h2;
    cudaGetSymbolAddress((void**)&p_h,   g_h);
    cudaGetSymbolAddress((void**)&p_agg, g_agg);
    cudaGetSymbolAddress((void**)&p_mid, g_mid);
    cudaGetSymbolAddress((void**)&p_h2,  g_h2);

    zero_counts_kernel<<<1024, 256>>>();
    embed_kernel<<<(NN * 32 + 255) / 256, 256>>>(x, xemb1, xemb2);
    hist_kernel<<<(NE + 255) / 256, 256>>>(edge_index, edge_attr);
    scan1_kernel<<<SCAN_G, SCAN_B>>>();
    scan2_kernel<<<1, SCAN_B>>>();
    scan3_kernel<<<SCAN_G, SCAN_B>>>();
    scatter_kernel<<<(NE + 255) / 256, 256>>>(edge_index);

    for (int l = 0; l < 2; l++) {
        const float* e1l = e1 + (size_t)l * 7 * DD;
        const float* e2l = e2 + (size_t)l * 3 * DD;
        const float* W1l = W1 + (size_t)l * DD * 2 * DD;
        const float* b1l = b1 + (size_t)l * 2 * DD;
        const float* W2l = W2 + (size_t)l * 2 * DD * DD;
        const float* b2l = b2 + (size_t)l * DD;
        const float* gl = gamma + (size_t)l * DD;
        const float* bl = beta + (size_t)l * DD;

        aggregate_kernel<<<(NN + 7) / 8, 256>>>(e1l, e2l);
        gemm_kernel<true><<<dim3(2, (NN + 127) / 128), 256>>>(
            p_agg, W1l, b1l, p_mid, NN, 2 * DD, DD);
        gemm_kernel<false><<<dim3(1, (NN + 127) / 128), 256>>>(
            p_mid, W2l, b2l, p_h2, NN, DD, 2 * DD);
        zero_bn_kernel<<<1, 128>>>();
        bn_reduce_kernel<<<(NN + 127) / 128, 128>>>(p_h2);
        bn_apply_kernel<<<(NN * 32 + 255) / 256, 256>>>(
            p_h2, gl, bl, (l == 0) ? p_h : out, (l == 0) ? 1 : 0);
    }
}

// round 7
// speedup vs baseline: 1.6292x; 1.5066x over previous
#include <cuda_runtime.h>
#include <cuda_bf16.h>
#include <cstdint>

#define NN 50000
#define NE 800000
#define DD 128
#define MP 50048              // 391 * 128 padded rows
#define BN_EPS 1e-5f

#define SCAN_B 256
#define SCAN_G ((NN + SCAN_B - 1) / SCAN_B)   // 196

// ---------------- scratch (device globals) ----------------
__device__ float g_h[NN * DD];
__device__ float g_h2[NN * DD];
__device__ __nv_bfloat16 g_a1[(size_t)MP * 256];   // GEMM1 A: [hi(128)|lo(128)]
__device__ __nv_bfloat16 g_a2[(size_t)MP * 512];   // GEMM2 A: [hi(256)|lo(256)]
__device__ __nv_bfloat16 g_b1[256 * 384];          // GEMM1 B: [n, hi|hi|lo]
__device__ __nv_bfloat16 g_b2[128 * 768];          // GEMM2 B: [n, hi|hi|lo]
__device__ int   g_deg[NN];
__device__ int   g_rowptr[NN + 1];
__device__ int   g_wr[NN];
__device__ int   g_col[NE];
__device__ int   g_cnt1[NN * 7];
__device__ int   g_cnt2[NN * 3];
__device__ float g_colsum[DD];
__device__ float g_colsq[DD];
__device__ int   g_bsum[SCAN_G];
__device__ int   g_boff[SCAN_G];

// ---------------- helpers ----------------
__device__ __forceinline__ uint32_t s2u(const void* p) {
    uint32_t a;
    asm("{ .reg .u64 t; cvta.to.shared.u64 t, %1; cvt.u32.u64 %0, t; }" : "=r"(a) : "l"(p));
    return a;
}
#define SWZ(x) ((x) ^ (((x) >> 3) & 0x70))

#define CP_A16(dst, src) \
    asm volatile("cp.async.cg.shared.global [%0], [%1], 16;" :: "r"(dst), "l"(src))
#define CP_COMMIT() asm volatile("cp.async.commit_group;")
#define CP_WAIT(n)  asm volatile("cp.async.wait_group %0;" :: "n"(n))

#define LDSM_X4(r0, r1, r2, r3, addr) \
    asm volatile("ldmatrix.sync.aligned.m8n8.x4.shared.b16 {%0,%1,%2,%3}, [%4];" \
        : "=r"(r0), "=r"(r1), "=r"(r2), "=r"(r3) : "r"(addr))
#define MMA16816(d, a, b) \
    asm volatile("mma.sync.aligned.m16n8k16.row.col.f32.bf16.bf16.f32 " \
        "{%0,%1,%2,%3}, {%4,%5,%6,%7}, {%8,%9}, {%0,%1,%2,%3};" \
        : "+f"((d)[0]), "+f"((d)[1]), "+f"((d)[2]), "+f"((d)[3]) \
        : "r"((a)[0]), "r"((a)[1]), "r"((a)[2]), "r"((a)[3]), \
          "r"((b)[0]), "r"((b)[1]))

__device__ __forceinline__ void split_bf16(float v, uint16_t& hi, uint16_t& lo) {
    __nv_bfloat16 h = __float2bfloat16_rn(v);
    float rem = v - __bfloat162float(h);
    __nv_bfloat16 l = __float2bfloat16_rn(rem);
    hi = __nv_bfloat16_raw(h).x;
    lo = __nv_bfloat16_raw(l).x;
}

// ---------------- preprocessing ----------------
__global__ void zero_counts_kernel() {
    int idx = blockIdx.x * blockDim.x + threadIdx.x;
    int total = NN + NN * 7 + NN * 3;
    for (int i = idx; i < total; i += gridDim.x * blockDim.x) {
        if (i < NN) g_deg[i] = 0;
        else if (i < NN + NN * 7) g_cnt1[i - NN] = 0;
        else g_cnt2[i - NN - NN * 7] = 0;
    }
}
__global__ void zero_bn_kernel() {
    int t = threadIdx.x;
    if (t < DD) { g_colsum[t] = 0.f; g_colsq[t] = 0.f; }
}
__global__ void zero_pad_a1_kernel() {
    int idx = blockIdx.x * blockDim.x + threadIdx.x;
    int total = (MP - NN) * 256;
    if (idx < total) g_a1[(size_t)NN * 256 + idx] = __float2bfloat16(0.f);
}
__global__ void embed_kernel(const int* __restrict__ x,
                             const float* __restrict__ xemb1,
                             const float* __restrict__ xemb2) {
    int idx = blockIdx.x * blockDim.x + threadIdx.x;
    if (idx >= NN * (DD / 4)) return;
    int v = idx >> 5;
    int c4 = idx & 31;
    int a = x[2 * v];
    int b = x[2 * v + 1];
    float4 va = ((const float4*)(xemb1 + (size_t)a * DD))[c4];
    float4 vb = ((const float4*)(xemb2 + (size_t)b * DD))[c4];
    float4 o;
    o.x = va.x + vb.x; o.y = va.y + vb.y; o.z = va.z + vb.z; o.w = va.w + vb.w;
    ((float4*)(g_h + (size_t)v * DD))[c4] = o;
}
__global__ void hist_kernel(const int* __restrict__ edge_index,
                            const int* __restrict__ edge_attr) {
    int e = blockIdx.x * blockDim.x + threadIdx.x;
    if (e >= NE) return;
    int dst = edge_index[NE + e];
    atomicAdd(&g_deg[dst], 1);
    atomicAdd(&g_cnt1[dst * 7 + edge_attr[2 * e]], 1);
    atomicAdd(&g_cnt2[dst * 3 + edge_attr[2 * e + 1]], 1);
}
__global__ void scan1_kernel() {
    __shared__ int sh[SCAN_B];
    int t = threadIdx.x;
    int i = blockIdx.x * SCAN_B + t;
    sh[t] = (i < NN) ? g_deg[i] : 0;
    __syncthreads();
    for (int off = SCAN_B / 2; off > 0; off >>= 1) {
        if (t < off) sh[t] += sh[t + off];
        __syncthreads();
    }
    if (t == 0) g_bsum[blockIdx.x] = sh[0];
}
__global__ void scan2_kernel() {
    __shared__ int sh[SCAN_B];
    int t = threadIdx.x;
    sh[t] = (t < SCAN_G) ? g_bsum[t] : 0;
    __syncthreads();
    for (int off = 1; off < SCAN_B; off <<= 1) {
        int v = (t >= off) ? sh[t - off] : 0;
        __syncthreads();
        sh[t] += v;
        __syncthreads();
    }
    if (t < SCAN_G) g_boff[t] = (t == 0) ? 0 : sh[t - 1];
}
__global__ void scan3_kernel() {
    __shared__ int sh[SCAN_B];
    int t = threadIdx.x;
    int i = blockIdx.x * SCAN_B + t;
    int d = (i < NN) ? g_deg[i] : 0;
    sh[t] = d;
    __syncthreads();
    for (int off = 1; off < SCAN_B; off <<= 1) {
        int v = (t >= off) ? sh[t - off] : 0;
        __syncthreads();
        sh[t] += v;
        __syncthreads();
    }
    if (i < NN) {
        int excl = g_boff[blockIdx.x] + sh[t] - d;
        g_rowptr[i] = excl;
        g_wr[i] = excl;
        if (i == NN - 1) g_rowptr[NN] = excl + d;
    }
}
__global__ void scatter_kernel(const int* __restrict__ edge_index) {
    int e = blockIdx.x * blockDim.x + threadIdx.x;
    if (e >= NE) return;
    int src = edge_index[e];
    int dst = edge_index[NE + e];
    int pos = atomicAdd(&g_wr[dst], 1);
    g_col[pos] = src;
}

// ---------------- aggregation: writes bf16 hi/lo split A1 ----------------
__global__ __launch_bounds__(256) void aggregate_kernel(
        const float* __restrict__ e1l, const float* __restrict__ e2l) {
    __shared__ float4 se[(7 + 3) * 32];
    for (int i = threadIdx.x; i < (7 + 3) * 32; i += blockDim.x) {
        se[i] = (i < 7 * 32) ? ((const float4*)e1l)[i]
                             : ((const float4*)e2l)[i - 7 * 32];
    }
    __syncthreads();

    int tid = threadIdx.x;
    int warp = tid >> 5;
    int lane = tid & 31;
    int v = blockIdx.x * 8 + warp;
    if (v >= NN) return;

    float4 acc = ((const float4*)(g_h + (size_t)v * DD))[lane];
    float4 t4 = se[4 * 32 + lane];
    acc.x += t4.x; acc.y += t4.y; acc.z += t4.z; acc.w += t4.w;
    t4 = se[7 * 32 + lane];
    acc.x += t4.x; acc.y += t4.y; acc.z += t4.z; acc.w += t4.w;

    int beg = g_rowptr[v];
    int end = g_rowptr[v + 1];
    for (int j = beg; j < end; j++) {
        int s = g_col[j];
        float4 hv = ((const float4*)(g_h + (size_t)s * DD))[lane];
        acc.x += hv.x; acc.y += hv.y; acc.z += hv.z; acc.w += hv.w;
    }
#pragma unroll
    for (int t = 0; t < 7; t++) {
        int c = g_cnt1[v * 7 + t];
        if (c) {
            float fc = (float)c;
            float4 ev = se[t * 32 + lane];
            acc.x += fc * ev.x; acc.y += fc * ev.y; acc.z += fc * ev.z; acc.w += fc * ev.w;
        }
    }
#pragma unroll
    for (int t = 0; t < 3; t++) {
        int c = g_cnt2[v * 3 + t];
        if (c) {
            float fc = (float)c;
            float4 ev = se[(7 + t) * 32 + lane];
            acc.x += fc * ev.x; acc.y += fc * ev.y; acc.z += fc * ev.z; acc.w += fc * ev.w;
        }
    }
    uint16_t h0, h1, h2, h3, l0, l1, l2, l3;
    split_bf16(acc.x, h0, l0);
    split_bf16(acc.y, h1, l1);
    split_bf16(acc.z, h2, l2);
    split_bf16(acc.w, h3, l3);
    uint2 hv2, lv2;
    hv2.x = (uint32_t)h0 | ((uint32_t)h1 << 16);
    hv2.y = (uint32_t)h2 | ((uint32_t)h3 << 16);
    lv2.x = (uint32_t)l0 | ((uint32_t)l1 << 16);
    lv2.y = (uint32_t)l2 | ((uint32_t)l3 << 16);
    *(uint2*)(g_a1 + (size_t)v * 256 + lane * 4) = hv2;
    *(uint2*)(g_a1 + (size_t)v * 256 + 128 + lane * 4) = lv2;
}

// ---------------- weight conversion ----------------
__global__ void build_b1_kernel(const float* __restrict__ W1) {   // W1 [128,256]
    int idx = blockIdx.x * blockDim.x + threadIdx.x;
    if (idx >= 128 * 256) return;
    int k = idx >> 8;
    int n = idx & 255;
    uint16_t hi, lo;
    split_bf16(W1[idx], hi, lo);
    __nv_bfloat16_raw rh; rh.x = hi;
    __nv_bfloat16_raw rl; rl.x = lo;
    g_b1[(size_t)n * 384 + k]       = __nv_bfloat16(rh);
    g_b1[(size_t)n * 384 + 128 + k] = __nv_bfloat16(rh);
    g_b1[(size_t)n * 384 + 256 + k] = __nv_bfloat16(rl);
}
__global__ void build_b2_kernel(const float* __restrict__ W2) {   // W2 [256,128]
    int idx = blockIdx.x * blockDim.x + threadIdx.x;
    if (idx >= 256 * 128) return;
    int k = idx >> 7;
    int n = idx & 127;
    uint16_t hi, lo;
    split_bf16(W2[idx], hi, lo);
    __nv_bfloat16_raw rh; rh.x = hi;
    __nv_bfloat16_raw rl; rl.x = lo;
    g_b2[(size_t)n * 768 + k]       = __nv_bfloat16(rh);
    g_b2[(size_t)n * 768 + 256 + k] = __nv_bfloat16(rh);
    g_b2[(size_t)n * 768 + 512 + k] = __nv_bfloat16(rl);
}

// ---------------- warp-MMA GEMM (HMMA bf16, fp32 accum) ----------------
// D[128, 128-col block] = A_tile[128, NC*64] * B[128, NC*64]^T
// A physical [MP, KA] ([hi|lo]); logical chunk remap reuses hi blocks.
// B physical [Ntot, KB] (already tripled [hi|hi|lo]).
// G1: epilogue +bias, relu, split -> outHL [MP, 512]. G2: +bias -> outF [m,128].
template <int NC, int KA, int KB, bool G1>
__global__ void __launch_bounds__(256)
gemm_mma_kernel(const __nv_bfloat16* __restrict__ A,
                const __nv_bfloat16* __restrict__ Bm,
                const float* __restrict__ bias,
                __nv_bfloat16* __restrict__ outHL,
                float* __restrict__ outF) {
    extern __shared__ char smem[];
    float* sBias = (float*)smem;                  // 1024 B
    char* Abuf = smem + 1024;                     // 2 x 16 KB
    char* Bbuf = smem + 1024 + 2 * 16384;         // 2 x 16 KB
    const int tid = threadIdx.x;
    const int wid = tid >> 5;
    const int lane = tid & 31;
    const int m0 = blockIdx.x * 128;
    const int n0 = blockIdx.y * 128;
    const int wm = (wid >> 2) * 64;
    const int wn = (wid & 3) * 32;

    if (tid < 128) sBias[tid] = bias[n0 + tid];

    float acc[4][4][4];
#pragma unroll
    for (int i = 0; i < 4; i++)
#pragma unroll
        for (int j = 0; j < 4; j++)
#pragma unroll
            for (int k = 0; k < 4; k++) acc[i][j][k] = 0.f;

    auto loadChunk = [&](int c, int buf) {
        int pc = G1 ? (c < 4 ? c : c - 4) : (c < 8 ? c : c - 8);
        const __nv_bfloat16* Ag = A + (size_t)m0 * KA + pc * 64;
        const __nv_bfloat16* Bg = Bm + (size_t)n0 * KB + c * 64;
        uint32_t ab = s2u(Abuf + buf * 16384);
        uint32_t bb = s2u(Bbuf + buf * 16384);
#pragma unroll
        for (int i = 0; i < 4; i++) {
            int idx = tid + i * 256;            // 0..1023
            int r = idx >> 3, c16 = idx & 7;
            CP_A16(ab + SWZ(r * 128 + c16 * 16), Ag + (size_t)r * KA + c16 * 8);
        }
#pragma unroll
        for (int i = 0; i < 4; i++) {
            int idx = tid + i * 256;
            int r = idx >> 3, c16 = idx & 7;
            CP_A16(bb + SWZ(r * 128 + c16 * 16), Bg + (size_t)r * KB + c16 * 8);
        }
    };

    loadChunk(0, 0);
    CP_COMMIT();
    for (int c = 0; c < NC; c++) {
        int buf = c & 1;
        if (c + 1 < NC) {
            loadChunk(c + 1, buf ^ 1);
            CP_COMMIT();
            CP_WAIT(1);
        } else {
            CP_WAIT(0);
        }
        __syncthreads();
        uint32_t aBase = s2u(Abuf + buf * 16384);
        uint32_t bBase = s2u(Bbuf + buf * 16384);
#pragma unroll
        for (int ks = 0; ks < 4; ks++) {
            int k0b = ks * 32;                       // k offset in bytes
            uint32_t af[4][4];
#pragma unroll
            for (int mt = 0; mt < 4; mt++) {
                int row = wm + mt * 16 + (lane & 15);
                uint32_t addr = aBase + SWZ(row * 128 + k0b + ((lane >> 4) << 4));
                LDSM_X4(af[mt][0], af[mt][1], af[mt][2], af[mt][3], addr);
            }
            uint32_t bfr[4][2];
#pragma unroll
            for (int p = 0; p < 2; p++) {
                int g = lane >> 3;
                int nrow = wn + p * 16 + (lane & 7) + ((g >> 1) << 3);
                uint32_t addr = bBase + SWZ(nrow * 128 + k0b + ((g & 1) << 4));
                uint32_t r0, r1, r2, r3;
                // B stored [n][k] (k-contiguous) == col-major KxN -> NO trans
                LDSM_X4(r0, r1, r2, r3, addr);
                bfr[2 * p][0] = r0; bfr[2 * p][1] = r1;
                bfr[2 * p + 1][0] = r2; bfr[2 * p + 1][1] = r3;
            }
#pragma unroll
            for (int mt = 0; mt < 4; mt++)
#pragma unroll
                for (int nt = 0; nt < 4; nt++)
                    MMA16816(acc[mt][nt], af[mt], bfr[nt]);
        }
        __syncthreads();
    }

    // ---- epilogue ----
#pragma unroll
    for (int mt = 0; mt < 4; mt++) {
#pragma unroll
        for (int nt = 0; nt < 4; nt++) {
            int cl = wn + nt * 8 + 2 * (lane & 3);
            int cg = n0 + cl;
            float b0 = sBias[cl], b1 = sBias[cl + 1];
#pragma unroll
            for (int h = 0; h < 2; h++) {
                int m = m0 + wm + mt * 16 + (lane >> 2) + h * 8;
                float v0 = acc[mt][nt][2 * h] + b0;
                float v1 = acc[mt][nt][2 * h + 1] + b1;
                if (G1) {
                    v0 = fmaxf(v0, 0.f);
                    v1 = fmaxf(v1, 0.f);
                    uint16_t h0, l0, h1, l1;
                    split_bf16(v0, h0, l0);
                    split_bf16(v1, h1, l1);
                    if (m >= NN) { h0 = l0 = h1 = l1 = 0; }
                    *(uint32_t*)(outHL + (size_t)m * 512 + cg) =
                        (uint32_t)h0 | ((uint32_t)h1 << 16);
                    *(uint32_t*)(outHL + (size_t)m * 512 + 256 + cg) =
                        (uint32_t)l0 | ((uint32_t)l1 << 16);
                } else {
                    if (m < NN) {
                        float2 v; v.x = v0; v.y = v1;
                        *(float2*)(outF + (size_t)m * 128 + cg) = v;
                    }
                }
            }
        }
    }
}

// ---------------- BN ----------------
__global__ void bn_reduce_kernel(const float* __restrict__ X) {
    int c = threadIdx.x;
    int r0 = blockIdx.x * 128;
    float s = 0.f, s2 = 0.f;
    int rmax = min(r0 + 128, NN);
    for (int r = r0; r < rmax; r++) {
        float v = X[(size_t)r * DD + c];
        s += v;
        s2 += v * v;
    }
    atomicAdd(&g_colsum[c], s);
    atomicAdd(&g_colsq[c], s2);
}
__global__ void bn_apply_kernel(const float* __restrict__ X,
                                const float* __restrict__ gamma,
                                const float* __restrict__ beta,
                                float* __restrict__ Y, int do_relu) {
    int idx = blockIdx.x * blockDim.x + threadIdx.x;
    if (idx >= NN * (DD / 4)) return;
    int v = idx >> 5;
    int c4 = idx & 31;
    int c = c4 * 4;
    float4 x = ((const float4*)(X + (size_t)v * DD))[c4];
    float invn = 1.0f / (float)NN;
    float o[4];
    float xi[4] = {x.x, x.y, x.z, x.w};
#pragma unroll
    for (int k = 0; k < 4; k++) {
        float mu = g_colsum[c + k] * invn;
        float var = g_colsq[c + k] * invn - mu * mu;
        float rs = rsqrtf(var + BN_EPS);
        float y = gamma[c + k] * (xi[k] - mu) * rs + beta[c + k];
        if (do_relu) y = fmaxf(y, 0.f);
        o[k] = y;
    }
    ((float4*)(Y + (size_t)v * DD))[c4] = make_float4(o[0], o[1], o[2], o[3]);
}

// ---------------- launch ----------------
extern "C" void kernel_launch(void* const* d_in, const int* in_sizes, int n_in,
                              void* d_out, int out_size) {
    const int* x          = (const int*)d_in[0];
    const int* edge_index = (const int*)d_in[1];
    const int* edge_attr  = (const int*)d_in[2];
    const float* xemb1 = (const float*)d_in[4];
    const float* xemb2 = (const float*)d_in[5];
    const float* e1    = (const float*)d_in[6];
    const float* e2    = (const float*)d_in[7];
    const float* W1    = (const float*)d_in[8];
    const float* b1    = (const float*)d_in[9];
    const float* W2    = (const float*)d_in[10];
    const float* b2    = (const float*)d_in[11];
    const float* gamma = (const float*)d_in[12];
    const float* beta  = (const float*)d_in[13];
    float* out = (float*)d_out;

    float *p_h, *p_h2;
    __nv_bfloat16 *p_a1, *p_a2, *p_b1, *p_b2;
    cudaGetSymbolAddress((void**)&p_h,  g_h);
    cudaGetSymbolAddress((void**)&p_h2, g_h2);
    cudaGetSymbolAddress((void**)&p_a1, g_a1);
    cudaGetSymbolAddress((void**)&p_a2, g_a2);
    cudaGetSymbolAddress((void**)&p_b1, g_b1);
    cudaGetSymbolAddress((void**)&p_b2, g_b2);

    constexpr int SMEM_SZ = 1024 + 4 * 16384;   // 66560
    cudaFuncSetAttribute(gemm_mma_kernel<6, 256, 384, true>,
                         cudaFuncAttributeMaxDynamicSharedMemorySize, SMEM_SZ);
    cudaFuncSetAttribute(gemm_mma_kernel<12, 512, 768, false>,
                         cudaFuncAttributeMaxDynamicSharedMemorySize, SMEM_SZ);

    zero_counts_kernel<<<1024, 256>>>();
    zero_pad_a1_kernel<<<((MP - NN) * 256 + 255) / 256, 256>>>();
    embed_kernel<<<(NN * 32 + 255) / 256, 256>>>(x, xemb1, xemb2);
    hist_kernel<<<(NE + 255) / 256, 256>>>(edge_index, edge_attr);
    scan1_kernel<<<SCAN_G, SCAN_B>>>();
    scan2_kernel<<<1, SCAN_B>>>();
    scan3_kernel<<<SCAN_G, SCAN_B>>>();
    scatter_kernel<<<(NE + 255) / 256, 256>>>(edge_index);

    for (int l = 0; l < 2; l++) {
        const float* e1l = e1 + (size_t)l * 7 * DD;
        const float* e2l = e2 + (size_t)l * 3 * DD;
        const float* W1l = W1 + (size_t)l * DD * 2 * DD;
        const float* b1l = b1 + (size_t)l * 2 * DD;
        const float* W2l = W2 + (size_t)l * 2 * DD * DD;
        const float* b2l = b2 + (size_t)l * DD;
        const float* gl = gamma + (size_t)l * DD;
        const float* bl = beta + (size_t)l * DD;

        build_b1_kernel<<<(128 * 256 + 255) / 256, 256>>>(W1l);
        build_b2_kernel<<<(256 * 128 + 255) / 256, 256>>>(W2l);
        aggregate_kernel<<<(NN + 7) / 8, 256>>>(e1l, e2l);
        gemm_mma_kernel<6, 256, 384, true><<<dim3(MP / 128, 2), 256, SMEM_SZ>>>(
            p_a1, p_b1, b1l, p_a2, nullptr);
        gemm_mma_kernel<12, 512, 768, false><<<dim3(MP / 128, 1), 256, SMEM_SZ>>>(
            p_a2, p_b2, b2l, nullptr, p_h2);
        zero_bn_kernel<<<1, 128>>>();
        bn_reduce_kernel<<<(NN + 127) / 128, 128>>>(p_h2);
        bn_apply_kernel<<<(NN * 32 + 255) / 256, 256>>>(
            p_h2, gl, bl, (l == 0) ? p_h : out, (l == 0) ? 1 : 0);
    }
}

// round 8
// speedup vs baseline: 2.0169x; 1.2379x over previous
#include <cuda_runtime.h>
#include <cuda_fp16.h>
#include <cstdint>

#define NN 50000
#define NE 800000
#define DD 128
#define MP 50048              // 391 * 128 padded rows
#define BN_EPS 1e-5f

#define SCAN_B 256
#define SCAN_G ((NN + SCAN_B - 1) / SCAN_B)   // 196

// ---------------- scratch (device globals) ----------------
__device__ float g_h[NN * DD];
__device__ float g_h2[NN * DD];
__device__ uint16_t g_a1[(size_t)MP * 256];   // GEMM1 A fp16: [hi(128)|lo(128)]
__device__ uint16_t g_a2[(size_t)MP * 512];   // GEMM2 A fp16: [hi(256)|lo(256)]
__device__ uint16_t g_b1[256 * 256];          // GEMM1 B fp16: [n, hi|hi]
__device__ uint16_t g_b2[128 * 512];          // GEMM2 B fp16: [n, hi|hi]
__device__ int   g_deg[NN];
__device__ int   g_rowptr[NN + 1];
__device__ int   g_wr[NN];
__device__ int   g_col[NE];
__device__ int   g_cnt1[NN * 7];
__device__ int   g_cnt2[NN * 3];
__device__ float g_colsum[DD];
__device__ float g_colsq[DD];
__device__ int   g_bsum[SCAN_G];
__device__ int   g_boff[SCAN_G];

// ---------------- helpers ----------------
__device__ __forceinline__ uint32_t s2u(const void* p) {
    uint32_t a;
    asm("{ .reg .u64 t; cvta.to.shared.u64 t, %1; cvt.u32.u64 %0, t; }" : "=r"(a) : "l"(p));
    return a;
}
#define SWZ(x) ((x) ^ (((x) >> 3) & 0x70))

#define CP_A16(dst, src) \
    asm volatile("cp.async.cg.shared.global [%0], [%1], 16;" :: "r"(dst), "l"(src))
#define CP_COMMIT() asm volatile("cp.async.commit_group;")
#define CP_WAIT(n)  asm volatile("cp.async.wait_group %0;" :: "n"(n))

#define LDSM_X4(r0, r1, r2, r3, addr) \
    asm volatile("ldmatrix.sync.aligned.m8n8.x4.shared.b16 {%0,%1,%2,%3}, [%4];" \
        : "=r"(r0), "=r"(r1), "=r"(r2), "=r"(r3) : "r"(addr))
#define MMA16816(d, a, b) \
    asm volatile("mma.sync.aligned.m16n8k16.row.col.f32.f16.f16.f32 " \
        "{%0,%1,%2,%3}, {%4,%5,%6,%7}, {%8,%9}, {%0,%1,%2,%3};" \
        : "+f"((d)[0]), "+f"((d)[1]), "+f"((d)[2]), "+f"((d)[3]) \
        : "r"((a)[0]), "r"((a)[1]), "r"((a)[2]), "r"((a)[3]), \
          "r"((b)[0]), "r"((b)[1]))

__device__ __forceinline__ void split_f16(float v, uint16_t& hi, uint16_t& lo) {
    __half h = __float2half_rn(v);
    float rem = v - __half2float(h);
    __half l = __float2half_rn(rem);
    hi = __half_as_ushort(h);
    lo = __half_as_ushort(l);
}

// ---------------- preprocessing ----------------
__global__ void zero_counts_kernel() {
    int idx = blockIdx.x * blockDim.x + threadIdx.x;
    int total = NN + NN * 7 + NN * 3;
    for (int i = idx; i < total; i += gridDim.x * blockDim.x) {
        if (i < NN) g_deg[i] = 0;
        else if (i < NN + NN * 7) g_cnt1[i - NN] = 0;
        else g_cnt2[i - NN - NN * 7] = 0;
    }
}
__global__ void zero_pad_a1_kernel() {
    int idx = blockIdx.x * blockDim.x + threadIdx.x;
    int total = (MP - NN) * 256;
    if (idx < total) g_a1[(size_t)NN * 256 + idx] = 0;
}
__global__ void embed_kernel(const int* __restrict__ x,
                             const float* __restrict__ xemb1,
                             const float* __restrict__ xemb2) {
    int idx = blockIdx.x * blockDim.x + threadIdx.x;
    if (idx >= NN * (DD / 4)) return;
    int v = idx >> 5;
    int c4 = idx & 31;
    int a = x[2 * v];
    int b = x[2 * v + 1];
    float4 va = ((const float4*)(xemb1 + (size_t)a * DD))[c4];
    float4 vb = ((const float4*)(xemb2 + (size_t)b * DD))[c4];
    float4 o;
    o.x = va.x + vb.x; o.y = va.y + vb.y; o.z = va.z + vb.z; o.w = va.w + vb.w;
    ((float4*)(g_h + (size_t)v * DD))[c4] = o;
}
__global__ void hist_kernel(const int* __restrict__ edge_index,
                            const int* __restrict__ edge_attr) {
    int e = blockIdx.x * blockDim.x + threadIdx.x;
    if (e >= NE) return;
    int dst = edge_index[NE + e];
    atomicAdd(&g_deg[dst], 1);
    atomicAdd(&g_cnt1[dst * 7 + edge_attr[2 * e]], 1);
    atomicAdd(&g_cnt2[dst * 3 + edge_attr[2 * e + 1]], 1);
}
__global__ void scan1_kernel() {
    __shared__ int sh[SCAN_B];
    int t = threadIdx.x;
    int i = blockIdx.x * SCAN_B + t;
    sh[t] = (i < NN) ? g_deg[i] : 0;
    __syncthreads();
    for (int off = SCAN_B / 2; off > 0; off >>= 1) {
        if (t < off) sh[t] += sh[t + off];
        __syncthreads();
    }
    if (t == 0) g_bsum[blockIdx.x] = sh[0];
}
__global__ void scan2_kernel() {
    __shared__ int sh[SCAN_B];
    int t = threadIdx.x;
    sh[t] = (t < SCAN_G) ? g_bsum[t] : 0;
    __syncthreads();
    for (int off = 1; off < SCAN_B; off <<= 1) {
        int v = (t >= off) ? sh[t - off] : 0;
        __syncthreads();
        sh[t] += v;
        __syncthreads();
    }
    if (t < SCAN_G) g_boff[t] = (t == 0) ? 0 : sh[t - 1];
}
__global__ void scan3_kernel() {
    __shared__ int sh[SCAN_B];
    int t = threadIdx.x;
    int i = blockIdx.x * SCAN_B + t;
    int d = (i < NN) ? g_deg[i] : 0;
    sh[t] = d;
    __syncthreads();
    for (int off = 1; off < SCAN_B; off <<= 1) {
        int v = (t >= off) ? sh[t - off] : 0;
        __syncthreads();
        sh[t] += v;
        __syncthreads();
    }
    if (i < NN) {
        int excl = g_boff[blockIdx.x] + sh[t] - d;
        g_rowptr[i] = excl;
        g_wr[i] = excl;
        if (i == NN - 1) g_rowptr[NN] = excl + d;
    }
}
__global__ void scatter_kernel(const int* __restrict__ edge_index) {
    int e = blockIdx.x * blockDim.x + threadIdx.x;
    if (e >= NE) return;
    int src = edge_index[e];
    int dst = edge_index[NE + e];
    int pos = atomicAdd(&g_wr[dst], 1);
    g_col[pos] = src;
}

// ---------------- aggregation: writes fp16 hi/lo split A1 ----------------
__global__ __launch_bounds__(256) void aggregate_kernel(
        const float* __restrict__ e1l, const float* __restrict__ e2l) {
    __shared__ float4 se[(7 + 3) * 32];
    for (int i = threadIdx.x; i < (7 + 3) * 32; i += blockDim.x) {
        se[i] = (i < 7 * 32) ? ((const float4*)e1l)[i]
                             : ((const float4*)e2l)[i - 7 * 32];
    }
    __syncthreads();

    int tid = threadIdx.x;
    int warp = tid >> 5;
    int lane = tid & 31;
    int v = blockIdx.x * 8 + warp;
    if (v >= NN) return;

    float4 acc = ((const float4*)(g_h + (size_t)v * DD))[lane];
    float4 t4 = se[4 * 32 + lane];
    acc.x += t4.x; acc.y += t4.y; acc.z += t4.z; acc.w += t4.w;
    t4 = se[7 * 32 + lane];
    acc.x += t4.x; acc.y += t4.y; acc.z += t4.z; acc.w += t4.w;

    float4 acc2 = make_float4(0.f, 0.f, 0.f, 0.f);
    int beg = g_rowptr[v];
    int end = g_rowptr[v + 1];
    int j = beg;
    for (; j + 3 < end; j += 4) {
        int s0 = g_col[j], s1 = g_col[j + 1], s2 = g_col[j + 2], s3 = g_col[j + 3];
        float4 a0 = ((const float4*)(g_h + (size_t)s0 * DD))[lane];
        float4 a1 = ((const float4*)(g_h + (size_t)s1 * DD))[lane];
        float4 a2 = ((const float4*)(g_h + (size_t)s2 * DD))[lane];
        float4 a3 = ((const float4*)(g_h + (size_t)s3 * DD))[lane];
        acc.x += a0.x + a1.x; acc.y += a0.y + a1.y;
        acc.z += a0.z + a1.z; acc.w += a0.w + a1.w;
        acc2.x += a2.x + a3.x; acc2.y += a2.y + a3.y;
        acc2.z += a2.z + a3.z; acc2.w += a2.w + a3.w;
    }
    for (; j < end; j++) {
        int s = g_col[j];
        float4 hv = ((const float4*)(g_h + (size_t)s * DD))[lane];
        acc.x += hv.x; acc.y += hv.y; acc.z += hv.z; acc.w += hv.w;
    }
    acc.x += acc2.x; acc.y += acc2.y; acc.z += acc2.z; acc.w += acc2.w;

#pragma unroll
    for (int t = 0; t < 7; t++) {
        int c = g_cnt1[v * 7 + t];
        if (c) {
            float fc = (float)c;
            float4 ev = se[t * 32 + lane];
            acc.x += fc * ev.x; acc.y += fc * ev.y; acc.z += fc * ev.z; acc.w += fc * ev.w;
        }
    }
#pragma unroll
    for (int t = 0; t < 3; t++) {
        int c = g_cnt2[v * 3 + t];
        if (c) {
            float fc = (float)c;
            float4 ev = se[(7 + t) * 32 + lane];
            acc.x += fc * ev.x; acc.y += fc * ev.y; acc.z += fc * ev.z; acc.w += fc * ev.w;
        }
    }
    uint16_t h0, h1, h2, h3, l0, l1, l2, l3;
    split_f16(acc.x, h0, l0);
    split_f16(acc.y, h1, l1);
    split_f16(acc.z, h2, l2);
    split_f16(acc.w, h3, l3);
    uint2 hv2, lv2;
    hv2.x = (uint32_t)h0 | ((uint32_t)h1 << 16);
    hv2.y = (uint32_t)h2 | ((uint32_t)h3 << 16);
    lv2.x = (uint32_t)l0 | ((uint32_t)l1 << 16);
    lv2.y = (uint32_t)l2 | ((uint32_t)l3 << 16);
    *(uint2*)(g_a1 + (size_t)v * 256 + lane * 4) = hv2;
    *(uint2*)(g_a1 + (size_t)v * 256 + 128 + lane * 4) = lv2;
}

// ---------------- weight conversion (fp16, duplicated hi) ----------------
__global__ void build_b1_kernel(const float* __restrict__ W1) {   // W1 [128,256]
    int idx = blockIdx.x * blockDim.x + threadIdx.x;
    if (idx < 128) { g_colsum[idx] = 0.f; g_colsq[idx] = 0.f; }   // zero BN stats
    if (idx >= 128 * 256) return;
    int k = idx >> 8;          // 0..127
    int n = idx & 255;         // 0..255
    uint16_t hv = __half_as_ushort(__float2half_rn(W1[idx]));
    g_b1[(size_t)n * 256 + k]       = hv;
    g_b1[(size_t)n * 256 + 128 + k] = hv;
}
__global__ void build_b2_kernel(const float* __restrict__ W2) {   // W2 [256,128]
    int idx = blockIdx.x * blockDim.x + threadIdx.x;
    if (idx >= 256 * 128) return;
    int k = idx >> 7;          // 0..255
    int n = idx & 127;         // 0..127
    uint16_t hv = __half_as_ushort(__float2half_rn(W2[idx]));
    g_b2[(size_t)n * 512 + k]       = hv;
    g_b2[(size_t)n * 512 + 256 + k] = hv;
}

// ---------------- warp-MMA GEMM (HMMA fp16, fp32 accum) ----------------
// A physical [MP, KA] fp16 ([hi|lo]); B physical [Ntot, KB] fp16 ([hi|hi]).
// Direct chunk mapping (A hi<->B hi copy1, A lo<->B hi copy2).
// G1: epilogue +bias, relu, fp16-split -> outHL [MP, 512].
// G2: +bias -> outF [m,128], fused BN column sum/sumsq atomics.
template <int NC, int KA, int KB, bool G1>
__global__ void __launch_bounds__(256)
gemm_mma_kernel(const uint16_t* __restrict__ A,
                const uint16_t* __restrict__ Bm,
                const float* __restrict__ bias,
                uint16_t* __restrict__ outHL,
                float* __restrict__ outF) {
    extern __shared__ char smem[];
    float* sBias = (float*)smem;                  // 1024 B
    char* Abuf = smem + 1024;                     // 2 x 16 KB
    char* Bbuf = smem + 1024 + 2 * 16384;         // 2 x 16 KB
    const int tid = threadIdx.x;
    const int wid = tid >> 5;
    const int lane = tid & 31;
    const int m0 = blockIdx.x * 128;
    const int n0 = blockIdx.y * 128;
    const int wm = (wid >> 2) * 64;
    const int wn = (wid & 3) * 32;

    if (tid < 128) sBias[tid] = bias[n0 + tid];

    float acc[4][4][4];
#pragma unroll
    for (int i = 0; i < 4; i++)
#pragma unroll
        for (int j = 0; j < 4; j++)
#pragma unroll
            for (int k = 0; k < 4; k++) acc[i][j][k] = 0.f;

    auto loadChunk = [&](int c, int buf) {
        const uint16_t* Ag = A + (size_t)m0 * KA + c * 64;
        const uint16_t* Bg = Bm + (size_t)n0 * KB + c * 64;
        uint32_t ab = s2u(Abuf + buf * 16384);
        uint32_t bb = s2u(Bbuf + buf * 16384);
#pragma unroll
        for (int i = 0; i < 4; i++) {
            int idx = tid + i * 256;            // 0..1023
            int r = idx >> 3, c16 = idx & 7;
            CP_A16(ab + SWZ(r * 128 + c16 * 16), Ag + (size_t)r * KA + c16 * 8);
        }
#pragma unroll
        for (int i = 0; i < 4; i++) {
            int idx = tid + i * 256;
            int r = idx >> 3, c16 = idx & 7;
            CP_A16(bb + SWZ(r * 128 + c16 * 16), Bg + (size_t)r * KB + c16 * 8);
        }
    };

    loadChunk(0, 0);
    CP_COMMIT();
    for (int c = 0; c < NC; c++) {
        int buf = c & 1;
        if (c + 1 < NC) {
            loadChunk(c + 1, buf ^ 1);
            CP_COMMIT();
            CP_WAIT(1);
        } else {
            CP_WAIT(0);
        }
        __syncthreads();
        uint32_t aBase = s2u(Abuf + buf * 16384);
        uint32_t bBase = s2u(Bbuf + buf * 16384);
#pragma unroll
        for (int ks = 0; ks < 4; ks++) {
            int k0b = ks * 32;                       // k offset in bytes
            uint32_t af[4][4];
#pragma unroll
            for (int mt = 0; mt < 4; mt++) {
                int row = wm + mt * 16 + (lane & 15);
                uint32_t addr = aBase + SWZ(row * 128 + k0b + ((lane >> 4) << 4));
                LDSM_X4(af[mt][0], af[mt][1], af[mt][2], af[mt][3], addr);
            }
            uint32_t bfr[4][2];
#pragma unroll
            for (int p = 0; p < 2; p++) {
                int g = lane >> 3;
                int nrow = wn + p * 16 + (lane & 7) + ((g >> 1) << 3);
                uint32_t addr = bBase + SWZ(nrow * 128 + k0b + ((g & 1) << 4));
                uint32_t r0, r1, r2, r3;
                LDSM_X4(r0, r1, r2, r3, addr);   // B [n][k] == col-major KxN, no trans
                bfr[2 * p][0] = r0; bfr[2 * p][1] = r1;
                bfr[2 * p + 1][0] = r2; bfr[2 * p + 1][1] = r3;
            }
#pragma unroll
            for (int mt = 0; mt < 4; mt++)
#pragma unroll
                for (int nt = 0; nt < 4; nt++)
                    MMA16816(acc[mt][nt], af[mt], bfr[nt]);
        }
        __syncthreads();
    }

    // ---- epilogue (nt outer for fused BN stats in G2) ----
#pragma unroll
    for (int nt = 0; nt < 4; nt++) {
        int cl = wn + nt * 8 + 2 * (lane & 3);
        int cg = n0 + cl;
        float b0 = sBias[cl], b1 = sBias[cl + 1];
        float s0 = 0.f, s1 = 0.f, q0 = 0.f, q1 = 0.f;
#pragma unroll
        for (int mt = 0; mt < 4; mt++) {
#pragma unroll
            for (int h = 0; h < 2; h++) {
                int m = m0 + wm + mt * 16 + (lane >> 2) + h * 8;
                float v0 = acc[mt][nt][2 * h] + b0;
                float v1 = acc[mt][nt][2 * h + 1] + b1;
                if (G1) {
                    v0 = fmaxf(v0, 0.f);
                    v1 = fmaxf(v1, 0.f);
                    uint16_t h0, l0, h1, l1;
                    split_f16(v0, h0, l0);
                    split_f16(v1, h1, l1);
                    if (m >= NN) { h0 = l0 = h1 = l1 = 0; }
                    *(uint32_t*)(outHL + (size_t)m * 512 + cg) =
                        (uint32_t)h0 | ((uint32_t)h1 << 16);
                    *(uint32_t*)(outHL + (size_t)m * 512 + 256 + cg) =
                        (uint32_t)l0 | ((uint32_t)l1 << 16);
                } else {
                    if (m < NN) {
                        float2 v; v.x = v0; v.y = v1;
                        *(float2*)(outF + (size_t)m * 128 + cg) = v;
                        s0 += v0; s1 += v1;
                        q0 += v0 * v0; q1 += v1 * v1;
                    }
                }
            }
        }
        if (!G1) {
#pragma unroll
            for (int off = 16; off >= 4; off >>= 1) {
                s0 += __shfl_down_sync(0xffffffff, s0, off);
                s1 += __shfl_down_sync(0xffffffff, s1, off);
                q0 += __shfl_down_sync(0xffffffff, q0, off);
                q1 += __shfl_down_sync(0xffffffff, q1, off);
            }
            if (lane < 4) {
                atomicAdd(&g_colsum[cg], s0);
                atomicAdd(&g_colsum[cg + 1], s1);
                atomicAdd(&g_colsq[cg], q0);
                atomicAdd(&g_colsq[cg + 1], q1);
            }
        }
    }
}

// ---------------- BN apply (+ optional relu) ----------------
__global__ void bn_apply_kernel(const float* __restrict__ X,
                                const float* __restrict__ gamma,
                                const float* __restrict__ beta,
                                float* __restrict__ Y, int do_relu) {
    int idx = blockIdx.x * blockDim.x + threadIdx.x;
    if (idx >= NN * (DD / 4)) return;
    int v = idx >> 5;
    int c4 = idx & 31;
    int c = c4 * 4;
    float4 x = ((const float4*)(X + (size_t)v * DD))[c4];
    float invn = 1.0f / (float)NN;
    float o[4];
    float xi[4] = {x.x, x.y, x.z, x.w};
#pragma unroll
    for (int k = 0; k < 4; k++) {
        float mu = g_colsum[c + k] * invn;
        float var = g_colsq[c + k] * invn - mu * mu;
        float rs = rsqrtf(var + BN_EPS);
        float y = gamma[c + k] * (xi[k] - mu) * rs + beta[c + k];
        if (do_relu) y = fmaxf(y, 0.f);
        o[k] = y;
    }
    ((float4*)(Y + (size_t)v * DD))[c4] = make_float4(o[0], o[1], o[2], o[3]);
}

// ---------------- launch ----------------
extern "C" void kernel_launch(void* const* d_in, const int* in_sizes, int n_in,
                              void* d_out, int out_size) {
    const int* x          = (const int*)d_in[0];
    const int* edge_index = (const int*)d_in[1];
    const int* edge_attr  = (const int*)d_in[2];
    const float* xemb1 = (const float*)d_in[4];
    const float* xemb2 = (const float*)d_in[5];
    const float* e1    = (const float*)d_in[6];
    const float* e2    = (const float*)d_in[7];
    const float* W1    = (const float*)d_in[8];
    const float* b1    = (const float*)d_in[9];
    const float* W2    = (const float*)d_in[10];
    const float* b2    = (const float*)d_in[11];
    const float* gamma = (const float*)d_in[12];
    const float* beta  = (const float*)d_in[13];
    float* out = (float*)d_out;

    float *p_h, *p_h2;
    uint16_t *p_a1, *p_a2, *p_b1, *p_b2;
    cudaGetSymbolAddress((void**)&p_h,  g_h);
    cudaGetSymbolAddress((void**)&p_h2, g_h2);
    cudaGetSymbolAddress((void**)&p_a1, g_a1);
    cudaGetSymbolAddress((void**)&p_a2, g_a2);
    cudaGetSymbolAddress((void**)&p_b1, g_b1);
    cudaGetSymbolAddress((void**)&p_b2, g_b2);

    constexpr int SMEM_SZ = 1024 + 4 * 16384;   // 66560
    cudaFuncSetAttribute(gemm_mma_kernel<4, 256, 256, true>,
                         cudaFuncAttributeMaxDynamicSharedMemorySize, SMEM_SZ);
    cudaFuncSetAttribute(gemm_mma_kernel<8, 512, 512, false>,
                         cudaFuncAttributeMaxDynamicSharedMemorySize, SMEM_SZ);

    zero_counts_kernel<<<1024, 256>>>();
    zero_pad_a1_kernel<<<((MP - NN) * 256 + 255) / 256, 256>>>();
    embed_kernel<<<(NN * 32 + 255) / 256, 256>>>(x, xemb1, xemb2);
    hist_kernel<<<(NE + 255) / 256, 256>>>(edge_index, edge_attr);
    scan1_kernel<<<SCAN_G, SCAN_B>>>();
    scan2_kernel<<<1, SCAN_B>>>();
    scan3_kernel<<<SCAN_G, SCAN_B>>>();
    scatter_kernel<<<(NE + 255) / 256, 256>>>(edge_index);

    for (int l = 0; l < 2; l++) {
        const float* e1l = e1 + (size_t)l * 7 * DD;
        const float* e2l = e2 + (size_t)l * 3 * DD;
        const float* W1l = W1 + (size_t)l * DD * 2 * DD;
        const float* b1l = b1 + (size_t)l * 2 * DD;
        const float* W2l = W2 + (size_t)l * 2 * DD * DD;
        const float* b2l = b2 + (size_t)l * DD;
        const float* gl = gamma + (size_t)l * DD;
        const float* bl = beta + (size_t)l * DD;

        build_b1_kernel<<<(128 * 256 + 255) / 256, 256>>>(W1l);   // also zeroes BN stats
        build_b2_kernel<<<(256 * 128 + 255) / 256, 256>>>(W2l);
        aggregate_kernel<<<(NN + 7) / 8, 256>>>(e1l, e2l);
        gemm_mma_kernel<4, 256, 256, true><<<dim3(MP / 128, 2), 256, SMEM_SZ>>>(
            p_a1, p_b1, b1l, p_a2, nullptr);
        gemm_mma_kernel<8, 512, 512, false><<<dim3(MP / 128, 1), 256, SMEM_SZ>>>(
            p_a2, p_b2, b2l, nullptr, p_h2);
        bn_apply_kernel<<<(NN * 32 + 255) / 256, 256>>>(
            p_h2, gl, bl, (l == 0) ? p_h : out, (l == 0) ? 1 : 0);
    }
}

// round 9
// speedup vs baseline: 2.0457x; 1.0143x over previous
#include <cuda_runtime.h>
#include <cuda_fp16.h>
#include <cstdint>

#define NN 50000
#define NE 800000
#define DD 128
#define MP 50048              // 391 * 128 padded rows
#define BN_EPS 1e-5f

#define SCAN_B 256
#define SCAN_G ((NN + SCAN_B - 1) / SCAN_B)   // 196

// ---------------- scratch (device globals) ----------------
__device__ float g_h[NN * DD];
__device__ float g_h2[NN * DD];
__device__ uint16_t g_a1[(size_t)MP * 256];   // GEMM1 A fp16: [hi(128)|lo(128)]
__device__ uint16_t g_a2[(size_t)MP * 512];   // GEMM2 A fp16: [hi(256)|lo(256)]
__device__ uint16_t g_b1[256 * 256];          // GEMM1 B fp16: [n, hi|hi]
__device__ uint16_t g_b2[128 * 512];          // GEMM2 B fp16: [n, hi|hi]
__device__ int   g_rowptr[NN + 1];
__device__ int   g_wr[NN];
__device__ int   g_col[NE];
__device__ int   g_cnt1[NN * 7];
__device__ int   g_cnt2[NN * 3];
__device__ float g_colsum[2 * DD];            // per-layer BN stats
__device__ float g_colsq[2 * DD];
__device__ int   g_bsum[SCAN_G];
__device__ int   g_boff[SCAN_G];

// ---------------- helpers ----------------
__device__ __forceinline__ uint32_t s2u(const void* p) {
    uint32_t a;
    asm("{ .reg .u64 t; cvta.to.shared.u64 t, %1; cvt.u32.u64 %0, t; }" : "=r"(a) : "l"(p));
    return a;
}
#define SWZ(x) ((x) ^ (((x) >> 3) & 0x70))

#define CP_A16(dst, src) \
    asm volatile("cp.async.cg.shared.global [%0], [%1], 16;" :: "r"(dst), "l"(src))
#define CP_COMMIT() asm volatile("cp.async.commit_group;")
#define CP_WAIT(n)  asm volatile("cp.async.wait_group %0;" :: "n"(n))

#define LDSM_X4(r0, r1, r2, r3, addr) \
    asm volatile("ldmatrix.sync.aligned.m8n8.x4.shared.b16 {%0,%1,%2,%3}, [%4];" \
        : "=r"(r0), "=r"(r1), "=r"(r2), "=r"(r3) : "r"(addr))
#define MMA16816(d, a, b) \
    asm volatile("mma.sync.aligned.m16n8k16.row.col.f32.f16.f16.f32 " \
        "{%0,%1,%2,%3}, {%4,%5,%6,%7}, {%8,%9}, {%0,%1,%2,%3};" \
        : "+f"((d)[0]), "+f"((d)[1]), "+f"((d)[2]), "+f"((d)[3]) \
        : "r"((a)[0]), "r"((a)[1]), "r"((a)[2]), "r"((a)[3]), \
          "r"((b)[0]), "r"((b)[1]))

__device__ __forceinline__ void split_f16(float v, uint16_t& hi, uint16_t& lo) {
    __half h = __float2half_rn(v);
    float rem = v - __half2float(h);
    __half l = __float2half_rn(rem);
    hi = __half_as_ushort(h);
    lo = __half_as_ushort(l);
}

// ---------------- preprocessing ----------------
__global__ void zero_counts_kernel() {
    int idx = blockIdx.x * blockDim.x + threadIdx.x;
    int total = NN * 7 + NN * 3;
    for (int i = idx; i < total; i += gridDim.x * blockDim.x) {
        if (i < NN * 7) g_cnt1[i] = 0;
        else g_cnt2[i - NN * 7] = 0;
    }
}
__global__ void zero_pad_a1_kernel() {
    int idx = blockIdx.x * blockDim.x + threadIdx.x;
    int total = (MP - NN) * 256;
    if (idx < total) g_a1[(size_t)NN * 256 + idx] = 0;
}
__global__ void embed_kernel(const int* __restrict__ x,
                             const float* __restrict__ xemb1,
                             const float* __restrict__ xemb2) {
    int idx = blockIdx.x * blockDim.x + threadIdx.x;
    if (idx >= NN * (DD / 4)) return;
    int v = idx >> 5;
    int c4 = idx & 31;
    int a = x[2 * v];
    int b = x[2 * v + 1];
    float4 va = ((const float4*)(xemb1 + (size_t)a * DD))[c4];
    float4 vb = ((const float4*)(xemb2 + (size_t)b * DD))[c4];
    float4 o;
    o.x = va.x + vb.x; o.y = va.y + vb.y; o.z = va.z + vb.z; o.w = va.w + vb.w;
    ((float4*)(g_h + (size_t)v * DD))[c4] = o;
}
__global__ void hist_kernel(const int* __restrict__ edge_index,
                            const int* __restrict__ edge_attr) {
    int e = blockIdx.x * blockDim.x + threadIdx.x;
    if (e >= NE) return;
    int dst = edge_index[NE + e];
    atomicAdd(&g_cnt1[dst * 7 + edge_attr[2 * e]], 1);
    atomicAdd(&g_cnt2[dst * 3 + edge_attr[2 * e + 1]], 1);
}
__device__ __forceinline__ int node_deg(int i) {
    int d = 0;
#pragma unroll
    for (int t = 0; t < 7; t++) d += g_cnt1[i * 7 + t];
    return d;
}
__global__ void scan1_kernel() {
    __shared__ int sh[SCAN_B];
    int t = threadIdx.x;
    int i = blockIdx.x * SCAN_B + t;
    sh[t] = (i < NN) ? node_deg(i) : 0;
    __syncthreads();
    for (int off = SCAN_B / 2; off > 0; off >>= 1) {
        if (t < off) sh[t] += sh[t + off];
        __syncthreads();
    }
    if (t == 0) g_bsum[blockIdx.x] = sh[0];
}
__global__ void scan2_kernel() {
    __shared__ int sh[SCAN_B];
    int t = threadIdx.x;
    sh[t] = (t < SCAN_G) ? g_bsum[t] : 0;
    __syncthreads();
    for (int off = 1; off < SCAN_B; off <<= 1) {
        int v = (t >= off) ? sh[t - off] : 0;
        __syncthreads();
        sh[t] += v;
        __syncthreads();
    }
    if (t < SCAN_G) g_boff[t] = (t == 0) ? 0 : sh[t - 1];
}
__global__ void scan3_kernel() {
    __shared__ int sh[SCAN_B];
    int t = threadIdx.x;
    int i = blockIdx.x * SCAN_B + t;
    int d = (i < NN) ? node_deg(i) : 0;
    sh[t] = d;
    __syncthreads();
    for (int off = 1; off < SCAN_B; off <<= 1) {
        int v = (t >= off) ? sh[t - off] : 0;
        __syncthreads();
        sh[t] += v;
        __syncthreads();
    }
    if (i < NN) {
        int excl = g_boff[blockIdx.x] + sh[t] - d;
        g_rowptr[i] = excl;
        g_wr[i] = excl;
        if (i == NN - 1) g_rowptr[NN] = excl + d;
    }
}
__global__ void scatter_kernel(const int* __restrict__ edge_index) {
    int e = blockIdx.x * blockDim.x + threadIdx.x;
    if (e >= NE) return;
    int src = edge_index[e];
    int dst = edge_index[NE + e];
    int pos = atomicAdd(&g_wr[dst], 1);
    g_col[pos] = src;
}

// ---------------- aggregation (optionally fusing BN+relu of input) ----------
template <bool BN>
__global__ __launch_bounds__(256) void aggregate_kernel(
        const float* __restrict__ H,
        const float* __restrict__ e1l, const float* __restrict__ e2l,
        const float* __restrict__ gamma, const float* __restrict__ beta,
        const float* __restrict__ ssum, const float* __restrict__ ssq) {
    __shared__ float4 se[(7 + 3) * 32];
    for (int i = threadIdx.x; i < (7 + 3) * 32; i += blockDim.x) {
        se[i] = (i < 7 * 32) ? ((const float4*)e1l)[i]
                             : ((const float4*)e2l)[i - 7 * 32];
    }
    __syncthreads();

    int tid = threadIdx.x;
    int warp = tid >> 5;
    int lane = tid & 31;
    int v = blockIdx.x * 8 + warp;
    if (v >= NN) return;

    float4 scl = make_float4(0, 0, 0, 0), sft = make_float4(0, 0, 0, 0);
    if (BN) {
        int c = lane * 4;
        float invn = 1.0f / (float)NN;
        float s[4], f[4];
#pragma unroll
        for (int k = 0; k < 4; k++) {
            float mu = ssum[c + k] * invn;
            float var = ssq[c + k] * invn - mu * mu;
            float rs = rsqrtf(var + BN_EPS);
            s[k] = gamma[c + k] * rs;
            f[k] = beta[c + k] - mu * s[k];
        }
        scl = make_float4(s[0], s[1], s[2], s[3]);
        sft = make_float4(f[0], f[1], f[2], f[3]);
    }

    auto ldT = [&](int s) -> float4 {
        float4 x = ((const float4*)(H + (size_t)s * DD))[lane];
        if (BN) {
            x.x = fmaxf(fmaf(x.x, scl.x, sft.x), 0.f);
            x.y = fmaxf(fmaf(x.y, scl.y, sft.y), 0.f);
            x.z = fmaxf(fmaf(x.z, scl.z, sft.z), 0.f);
            x.w = fmaxf(fmaf(x.w, scl.w, sft.w), 0.f);
        }
        return x;
    };

    float4 acc = ldT(v);
    float4 t4 = se[4 * 32 + lane];
    acc.x += t4.x; acc.y += t4.y; acc.z += t4.z; acc.w += t4.w;
    t4 = se[7 * 32 + lane];
    acc.x += t4.x; acc.y += t4.y; acc.z += t4.z; acc.w += t4.w;

    float4 acc2 = make_float4(0.f, 0.f, 0.f, 0.f);
    int beg = g_rowptr[v];
    int end = g_rowptr[v + 1];
    int j = beg;
    for (; j + 3 < end; j += 4) {
        int s0 = g_col[j], s1 = g_col[j + 1], s2 = g_col[j + 2], s3 = g_col[j + 3];
        float4 a0 = ldT(s0);
        float4 a1 = ldT(s1);
        float4 a2 = ldT(s2);
        float4 a3 = ldT(s3);
        acc.x += a0.x + a1.x; acc.y += a0.y + a1.y;
        acc.z += a0.z + a1.z; acc.w += a0.w + a1.w;
        acc2.x += a2.x + a3.x; acc2.y += a2.y + a3.y;
        acc2.z += a2.z + a3.z; acc2.w += a2.w + a3.w;
    }
    for (; j < end; j++) {
        float4 hv = ldT(g_col[j]);
        acc.x += hv.x; acc.y += hv.y; acc.z += hv.z; acc.w += hv.w;
    }
    acc.x += acc2.x; acc.y += acc2.y; acc.z += acc2.z; acc.w += acc2.w;

#pragma unroll
    for (int t = 0; t < 7; t++) {
        int c = g_cnt1[v * 7 + t];
        if (c) {
            float fc = (float)c;
            float4 ev = se[t * 32 + lane];
            acc.x += fc * ev.x; acc.y += fc * ev.y; acc.z += fc * ev.z; acc.w += fc * ev.w;
        }
    }
#pragma unroll
    for (int t = 0; t < 3; t++) {
        int c = g_cnt2[v * 3 + t];
        if (c) {
            float fc = (float)c;
            float4 ev = se[(7 + t) * 32 + lane];
            acc.x += fc * ev.x; acc.y += fc * ev.y; acc.z += fc * ev.z; acc.w += fc * ev.w;
        }
    }
    uint16_t h0, h1, h2, h3, l0, l1, l2, l3;
    split_f16(acc.x, h0, l0);
    split_f16(acc.y, h1, l1);
    split_f16(acc.z, h2, l2);
    split_f16(acc.w, h3, l3);
    uint2 hv2, lv2;
    hv2.x = (uint32_t)h0 | ((uint32_t)h1 << 16);
    hv2.y = (uint32_t)h2 | ((uint32_t)h3 << 16);
    lv2.x = (uint32_t)l0 | ((uint32_t)l1 << 16);
    lv2.y = (uint32_t)l2 | ((uint32_t)l3 << 16);
    *(uint2*)(g_a1 + (size_t)v * 256 + lane * 4) = hv2;
    *(uint2*)(g_a1 + (size_t)v * 256 + 128 + lane * 4) = lv2;
}

// ---------------- weight conversion (fp16, duplicated hi) ----------------
__global__ void build_b1_kernel(const float* __restrict__ W1,
                                float* __restrict__ zsum, float* __restrict__ zsq) {
    int idx = blockIdx.x * blockDim.x + threadIdx.x;
    if (idx < 128) { zsum[idx] = 0.f; zsq[idx] = 0.f; }
    if (idx >= 128 * 256) return;
    int k = idx >> 8;
    int n = idx & 255;
    uint16_t hv = __half_as_ushort(__float2half_rn(W1[idx]));
    g_b1[(size_t)n * 256 + k]       = hv;
    g_b1[(size_t)n * 256 + 128 + k] = hv;
}
__global__ void build_b2_kernel(const float* __restrict__ W2) {
    int idx = blockIdx.x * blockDim.x + threadIdx.x;
    if (idx >= 256 * 128) return;
    int k = idx >> 7;
    int n = idx & 127;
    uint16_t hv = __half_as_ushort(__float2half_rn(W2[idx]));
    g_b2[(size_t)n * 512 + k]       = hv;
    g_b2[(size_t)n * 512 + 256 + k] = hv;
}

// ---------------- warp-MMA GEMM (HMMA fp16, fp32 accum, 3-stage) ----------
template <int NC, int KA, int KB, bool G1>
__global__ void __launch_bounds__(256)
gemm_mma_kernel(const uint16_t* __restrict__ A,
                const uint16_t* __restrict__ Bm,
                const float* __restrict__ bias,
                uint16_t* __restrict__ outHL,
                float* __restrict__ outF,
                float* __restrict__ statSum,
                float* __restrict__ statSq) {
    extern __shared__ char smem[];
    float* sBias = (float*)smem;                  // 1024 B
    char* Abuf = smem + 1024;                     // 3 x 16 KB
    char* Bbuf = smem + 1024 + 3 * 16384;         // 3 x 16 KB
    const int tid = threadIdx.x;
    const int wid = tid >> 5;
    const int lane = tid & 31;
    const int m0 = blockIdx.x * 128;
    const int n0 = blockIdx.y * 128;
    const int wm = (wid >> 2) * 64;
    const int wn = (wid & 3) * 32;

    if (tid < 128) sBias[tid] = bias[n0 + tid];

    float acc[4][4][4];
#pragma unroll
    for (int i = 0; i < 4; i++)
#pragma unroll
        for (int j = 0; j < 4; j++)
#pragma unroll
            for (int k = 0; k < 4; k++) acc[i][j][k] = 0.f;

    auto loadChunk = [&](int c, int buf) {
        const uint16_t* Ag = A + (size_t)m0 * KA + c * 64;
        const uint16_t* Bg = Bm + (size_t)n0 * KB + c * 64;
        uint32_t ab = s2u(Abuf + buf * 16384);
        uint32_t bb = s2u(Bbuf + buf * 16384);
#pragma unroll
        for (int i = 0; i < 4; i++) {
            int idx = tid + i * 256;
            int r = idx >> 3, c16 = idx & 7;
            CP_A16(ab + SWZ(r * 128 + c16 * 16), Ag + (size_t)r * KA + c16 * 8);
        }
#pragma unroll
        for (int i = 0; i < 4; i++) {
            int idx = tid + i * 256;
            int r = idx >> 3, c16 = idx & 7;
            CP_A16(bb + SWZ(r * 128 + c16 * 16), Bg + (size_t)r * KB + c16 * 8);
        }
    };

    loadChunk(0, 0);
    CP_COMMIT();
    loadChunk(1, 1);
    CP_COMMIT();
    for (int c = 0; c < NC; c++) {
        int buf = c % 3;
        if (c + 2 < NC) {
            loadChunk(c + 2, (c + 2) % 3);
            CP_COMMIT();
            CP_WAIT(2);
        } else if (c + 1 < NC) {
            CP_WAIT(1);
        } else {
            CP_WAIT(0);
        }
        __syncthreads();
        uint32_t aBase = s2u(Abuf + buf * 16384);
        uint32_t bBase = s2u(Bbuf + buf * 16384);
#pragma unroll
        for (int ks = 0; ks < 4; ks++) {
            int k0b = ks * 32;
            uint32_t af[4][4];
#pragma unroll
            for (int mt = 0; mt < 4; mt++) {
                int row = wm + mt * 16 + (lane & 15);
                uint32_t addr = aBase + SWZ(row * 128 + k0b + ((lane >> 4) << 4));
                LDSM_X4(af[mt][0], af[mt][1], af[mt][2], af[mt][3], addr);
            }
            uint32_t bfr[4][2];
#pragma unroll
            for (int p = 0; p < 2; p++) {
                int g = lane >> 3;
                int nrow = wn + p * 16 + (lane & 7) + ((g >> 1) << 3);
                uint32_t addr = bBase + SWZ(nrow * 128 + k0b + ((g & 1) << 4));
                uint32_t r0, r1, r2, r3;
                LDSM_X4(r0, r1, r2, r3, addr);
                bfr[2 * p][0] = r0; bfr[2 * p][1] = r1;
                bfr[2 * p + 1][0] = r2; bfr[2 * p + 1][1] = r3;
            }
#pragma unroll
            for (int mt = 0; mt < 4; mt++)
#pragma unroll
                for (int nt = 0; nt < 4; nt++)
                    MMA16816(acc[mt][nt], af[mt], bfr[nt]);
        }
        __syncthreads();
    }

    // ---- epilogue ----
#pragma unroll
    for (int nt = 0; nt < 4; nt++) {
        int cl = wn + nt * 8 + 2 * (lane & 3);
        int cg = n0 + cl;
        float b0 = sBias[cl], b1 = sBias[cl + 1];
        float s0 = 0.f, s1 = 0.f, q0 = 0.f, q1 = 0.f;
#pragma unroll
        for (int mt = 0; mt < 4; mt++) {
#pragma unroll
            for (int h = 0; h < 2; h++) {
                int m = m0 + wm + mt * 16 + (lane >> 2) + h * 8;
                float v0 = acc[mt][nt][2 * h] + b0;
                float v1 = acc[mt][nt][2 * h + 1] + b1;
                if (G1) {
                    v0 = fmaxf(v0, 0.f);
                    v1 = fmaxf(v1, 0.f);
                    uint16_t h0, l0, h1, l1;
                    split_f16(v0, h0, l0);
                    split_f16(v1, h1, l1);
                    if (m >= NN) { h0 = l0 = h1 = l1 = 0; }
                    *(uint32_t*)(outHL + (size_t)m * 512 + cg) =
                        (uint32_t)h0 | ((uint32_t)h1 << 16);
                    *(uint32_t*)(outHL + (size_t)m * 512 + 256 + cg) =
                        (uint32_t)l0 | ((uint32_t)l1 << 16);
                } else {
                    if (m < NN) {
                        float2 v; v.x = v0; v.y = v1;
                        *(float2*)(outF + (size_t)m * 128 + cg) = v;
                        s0 += v0; s1 += v1;
                        q0 += v0 * v0; q1 += v1 * v1;
                    }
                }
            }
        }
        if (!G1) {
#pragma unroll
            for (int off = 16; off >= 4; off >>= 1) {
                s0 += __shfl_down_sync(0xffffffff, s0, off);
                s1 += __shfl_down_sync(0xffffffff, s1, off);
                q0 += __shfl_down_sync(0xffffffff, q0, off);
                q1 += __shfl_down_sync(0xffffffff, q1, off);
            }
            if (lane < 4) {
                atomicAdd(&statSum[cg], s0);
                atomicAdd(&statSum[cg + 1], s1);
                atomicAdd(&statSq[cg], q0);
                atomicAdd(&statSq[cg + 1], q1);
            }
        }
    }
}

// ---------------- final BN apply (no relu) ----------------
__global__ void bn_apply_kernel(const float* __restrict__ X,
                                const float* __restrict__ gamma,
                                const float* __restrict__ beta,
                                const float* __restrict__ ssum,
                                const float* __restrict__ ssq,
                                float* __restrict__ Y) {
    int idx = blockIdx.x * blockDim.x + threadIdx.x;
    if (idx >= NN * (DD / 4)) return;
    int v = idx >> 5;
    int c4 = idx & 31;
    int c = c4 * 4;
    float4 x = ((const float4*)(X + (size_t)v * DD))[c4];
    float invn = 1.0f / (float)NN;
    float o[4];
    float xi[4] = {x.x, x.y, x.z, x.w};
#pragma unroll
    for (int k = 0; k < 4; k++) {
        float mu = ssum[c + k] * invn;
        float var = ssq[c + k] * invn - mu * mu;
        float rs = rsqrtf(var + BN_EPS);
        o[k] = gamma[c + k] * (xi[k] - mu) * rs + beta[c + k];
    }
    ((float4*)(Y + (size_t)v * DD))[c4] = make_float4(o[0], o[1], o[2], o[3]);
}

// ---------------- launch ----------------
extern "C" void kernel_launch(void* const* d_in, const int* in_sizes, int n_in,
                              void* d_out, int out_size) {
    const int* x          = (const int*)d_in[0];
    const int* edge_index = (const int*)d_in[1];
    const int* edge_attr  = (const int*)d_in[2];
    const float* xemb1 = (const float*)d_in[4];
    const float* xemb2 = (const float*)d_in[5];
    const float* e1    = (const float*)d_in[6];
    const float* e2    = (const float*)d_in[7];
    const float* W1    = (const float*)d_in[8];
    const float* b1    = (const float*)d_in[9];
    const float* W2    = (const float*)d_in[10];
    const float* b2    = (const float*)d_in[11];
    const float* gamma = (const float*)d_in[12];
    const float* beta  = (const float*)d_in[13];
    float* out = (float*)d_out;

    float *p_h, *p_h2, *p_sum, *p_sq;
    uint16_t *p_a1, *p_a2, *p_b1, *p_b2;
    cudaGetSymbolAddress((void**)&p_h,   g_h);
    cudaGetSymbolAddress((void**)&p_h2,  g_h2);
    cudaGetSymbolAddress((void**)&p_a1,  g_a1);
    cudaGetSymbolAddress((void**)&p_a2,  g_a2);
    cudaGetSymbolAddress((void**)&p_b1,  g_b1);
    cudaGetSymbolAddress((void**)&p_b2,  g_b2);
    cudaGetSymbolAddress((void**)&p_sum, g_colsum);
    cudaGetSymbolAddress((void**)&p_sq,  g_colsq);

    constexpr int SMEM_SZ = 1024 + 6 * 16384;   // 99328 (3-stage)
    cudaFuncSetAttribute(gemm_mma_kernel<4, 256, 256, true>,
                         cudaFuncAttributeMaxDynamicSharedMemorySize, SMEM_SZ);
    cudaFuncSetAttribute(gemm_mma_kernel<8, 512, 512, false>,
                         cudaFuncAttributeMaxDynamicSharedMemorySize, SMEM_SZ);

    zero_counts_kernel<<<1024, 256>>>();
    zero_pad_a1_kernel<<<((MP - NN) * 256 + 255) / 256, 256>>>();
    embed_kernel<<<(NN * 32 + 255) / 256, 256>>>(x, xemb1, xemb2);
    hist_kernel<<<(NE + 255) / 256, 256>>>(edge_index, edge_attr);
    scan1_kernel<<<SCAN_G, SCAN_B>>>();
    scan2_kernel<<<1, SCAN_B>>>();
    scan3_kernel<<<SCAN_G, SCAN_B>>>();
    scatter_kernel<<<(NE + 255) / 256, 256>>>(edge_index);

    for (int l = 0; l < 2; l++) {
        const float* e1l = e1 + (size_t)l * 7 * DD;
        const float* e2l = e2 + (size_t)l * 3 * DD;
        const float* W1l = W1 + (size_t)l * DD * 2 * DD;
        const float* b1l = b1 + (size_t)l * 2 * DD;
        const float* W2l = W2 + (size_t)l * 2 * DD * DD;
        const float* b2l = b2 + (size_t)l * DD;
        float* sumL = p_sum + l * DD;
        float* sqL  = p_sq + l * DD;

        build_b1_kernel<<<(128 * 256 + 255) / 256, 256>>>(W1l, sumL, sqL);
        build_b2_kernel<<<(256 * 128 + 255) / 256, 256>>>(W2l);
        if (l == 0) {
            aggregate_kernel<false><<<(NN + 7) / 8, 256>>>(
                p_h, e1l, e2l, nullptr, nullptr, nullptr, nullptr);
        } else {
            aggregate_kernel<true><<<(NN + 7) / 8, 256>>>(
                p_h2, e1l, e2l, gamma, beta, p_sum, p_sq);   // layer-0 stats/params
        }
        gemm_mma_kernel<4, 256, 256, true><<<dim3(MP / 128, 2), 256, SMEM_SZ>>>(
            p_a1, p_b1, b1l, p_a2, nullptr, nullptr, nullptr);
        gemm_mma_kernel<8, 512, 512, false><<<dim3(MP / 128, 1), 256, SMEM_SZ>>>(
            p_a2, p_b2, b2l, nullptr, p_h2, sumL, sqL);
    }
    bn_apply_kernel<<<(NN * 32 + 255) / 256, 256>>>(
        p_h2, gamma + DD, beta + DD, p_sum + DD, p_sq + DD, out);
}

// round 10
// speedup vs baseline: 2.1650x; 1.0583x over previous
#include <cuda_runtime.h>
#include <cuda_fp16.h>
#include <cstdint>

#define NN 50000
#define NE 800000
#define DD 128
#define MP 50048              // 391 * 128 padded rows
#define BN_EPS 1e-5f

#define SCAN_B 256
#define SCAN_G ((NN + SCAN_B - 1) / SCAN_B)   // 196

// ---------------- scratch (device globals) ----------------
__device__ float g_h[NN * DD];                // layer-0 aggregation input (fp32)
__device__ float g_h2[NN * DD];               // layer-1 pre-BN output (fp32)
__device__ uint16_t g_h2h[(size_t)NN * DD];   // layer-0 pre-BN output (fp16)
__device__ uint16_t g_a1[(size_t)MP * 256];   // GEMM1 A fp16: [hi(128)|lo(128)]
__device__ uint16_t g_a2[(size_t)MP * 512];   // GEMM2 A fp16: [hi(256)|lo(256)]
__device__ uint16_t g_b1[2 * 256 * 256];      // GEMM1 B fp16 per layer: [n, hi|hi]
__device__ uint16_t g_b2[2 * 128 * 512];      // GEMM2 B fp16 per layer: [n, hi|hi]
__device__ int   g_rowptr[NN + 1];
__device__ int   g_wr[NN];
__device__ int   g_col[NE];
__device__ int   g_cnt1[NN * 7];
__device__ int   g_cnt2[NN * 3];
__device__ float g_colsum[2 * DD];
__device__ float g_colsq[2 * DD];
__device__ int   g_bsum[SCAN_G];
__device__ int   g_boff[SCAN_G];

// ---------------- helpers ----------------
__device__ __forceinline__ uint32_t s2u(const void* p) {
    uint32_t a;
    asm("{ .reg .u64 t; cvta.to.shared.u64 t, %1; cvt.u32.u64 %0, t; }" : "=r"(a) : "l"(p));
    return a;
}
#define SWZ(x) ((x) ^ (((x) >> 3) & 0x70))

#define CP_A16(dst, src) \
    asm volatile("cp.async.cg.shared.global [%0], [%1], 16;" :: "r"(dst), "l"(src))
#define CP_COMMIT() asm volatile("cp.async.commit_group;")
#define CP_WAIT(n)  asm volatile("cp.async.wait_group %0;" :: "n"(n))

#define LDSM_X4(r0, r1, r2, r3, addr) \
    asm volatile("ldmatrix.sync.aligned.m8n8.x4.shared.b16 {%0,%1,%2,%3}, [%4];" \
        : "=r"(r0), "=r"(r1), "=r"(r2), "=r"(r3) : "r"(addr))
#define MMA16816(d, a, b) \
    asm volatile("mma.sync.aligned.m16n8k16.row.col.f32.f16.f16.f32 " \
        "{%0,%1,%2,%3}, {%4,%5,%6,%7}, {%8,%9}, {%0,%1,%2,%3};" \
        : "+f"((d)[0]), "+f"((d)[1]), "+f"((d)[2]), "+f"((d)[3]) \
        : "r"((a)[0]), "r"((a)[1]), "r"((a)[2]), "r"((a)[3]), \
          "r"((b)[0]), "r"((b)[1]))

__device__ __forceinline__ void split_f16(float v, uint16_t& hi, uint16_t& lo) {
    __half h = __float2half_rn(v);
    float rem = v - __half2float(h);
    __half l = __float2half_rn(rem);
    hi = __half_as_ushort(h);
    lo = __half_as_ushort(l);
}

// ---------------- fused setup: zeros + weight builds (both layers) ----------
#define SZ0 (NN * 7)                      // cnt1
#define SZ1 (SZ0 + NN * 3)                // cnt2
#define SZ2 (SZ1 + (MP - NN) * 256)       // a1 pad rows
#define SZ3 (SZ2 + 512)                   // BN stats (2 layers sum+sq)
#define SZ4 (SZ3 + 2 * 128 * 256)         // b1 builds
#define SZ5 (SZ4 + 2 * 256 * 128)         // b2 builds
__global__ void setup_kernel(const float* __restrict__ W1,
                             const float* __restrict__ W2) {
    int i = blockIdx.x * blockDim.x + threadIdx.x;
    if (i >= SZ5) return;
    if (i < SZ0) {
        g_cnt1[i] = 0;
    } else if (i < SZ1) {
        g_cnt2[i - SZ0] = 0;
    } else if (i < SZ2) {
        g_a1[(size_t)NN * 256 + (i - SZ1)] = 0;
    } else if (i < SZ3) {
        int j = i - SZ2;
        if (j < 256) g_colsum[j] = 0.f;
        else g_colsq[j - 256] = 0.f;
    } else if (i < SZ4) {
        int j = i - SZ3;
        int l = j >> 15;            // layer
        int r = j & 32767;          // k*256+n
        int k = r >> 8, n = r & 255;
        uint16_t hv = __half_as_ushort(__float2half_rn(W1[(size_t)l * 32768 + r]));
        g_b1[(size_t)l * 65536 + n * 256 + k]       = hv;
        g_b1[(size_t)l * 65536 + n * 256 + 128 + k] = hv;
    } else {
        int j = i - SZ4;
        int l = j >> 15;
        int r = j & 32767;          // k*128+n
        int k = r >> 7, n = r & 127;
        uint16_t hv = __half_as_ushort(__float2half_rn(W2[(size_t)l * 32768 + r]));
        g_b2[(size_t)l * 65536 + n * 512 + k]       = hv;
        g_b2[(size_t)l * 65536 + n * 512 + 256 + k] = hv;
    }
}

__global__ void embed_kernel(const int* __restrict__ x,
                             const float* __restrict__ xemb1,
                             const float* __restrict__ xemb2) {
    int idx = blockIdx.x * blockDim.x + threadIdx.x;
    if (idx >= NN * (DD / 4)) return;
    int v = idx >> 5;
    int c4 = idx & 31;
    int a = x[2 * v];
    int b = x[2 * v + 1];
    float4 va = ((const float4*)(xemb1 + (size_t)a * DD))[c4];
    float4 vb = ((const float4*)(xemb2 + (size_t)b * DD))[c4];
    float4 o;
    o.x = va.x + vb.x; o.y = va.y + vb.y; o.z = va.z + vb.z; o.w = va.w + vb.w;
    ((float4*)(g_h + (size_t)v * DD))[c4] = o;
}
__global__ void hist_kernel(const int* __restrict__ edge_index,
                            const int* __restrict__ edge_attr) {
    int e = blockIdx.x * blockDim.x + threadIdx.x;
    if (e >= NE) return;
    int dst = edge_index[NE + e];
    atomicAdd(&g_cnt1[dst * 7 + edge_attr[2 * e]], 1);
    atomicAdd(&g_cnt2[dst * 3 + edge_attr[2 * e + 1]], 1);
}
__device__ __forceinline__ int node_deg(int i) {
    int d = 0;
#pragma unroll
    for (int t = 0; t < 7; t++) d += g_cnt1[i * 7 + t];
    return d;
}
__global__ void scan1_kernel() {
    __shared__ int sh[SCAN_B];
    int t = threadIdx.x;
    int i = blockIdx.x * SCAN_B + t;
    sh[t] = (i < NN) ? node_deg(i) : 0;
    __syncthreads();
    for (int off = SCAN_B / 2; off > 0; off >>= 1) {
        if (t < off) sh[t] += sh[t + off];
        __syncthreads();
    }
    if (t == 0) g_bsum[blockIdx.x] = sh[0];
}
__global__ void scan2_kernel() {
    __shared__ int sh[SCAN_B];
    int t = threadIdx.x;
    sh[t] = (t < SCAN_G) ? g_bsum[t] : 0;
    __syncthreads();
    for (int off = 1; off < SCAN_B; off <<= 1) {
        int v = (t >= off) ? sh[t - off] : 0;
        __syncthreads();
        sh[t] += v;
        __syncthreads();
    }
    if (t < SCAN_G) g_boff[t] = (t == 0) ? 0 : sh[t - 1];
}
__global__ void scan3_kernel() {
    __shared__ int sh[SCAN_B];
    int t = threadIdx.x;
    int i = blockIdx.x * SCAN_B + t;
    int d = (i < NN) ? node_deg(i) : 0;
    sh[t] = d;
    __syncthreads();
    for (int off = 1; off < SCAN_B; off <<= 1) {
        int v = (t >= off) ? sh[t - off] : 0;
        __syncthreads();
        sh[t] += v;
        __syncthreads();
    }
    if (i < NN) {
        int excl = g_boff[blockIdx.x] + sh[t] - d;
        g_rowptr[i] = excl;
        g_wr[i] = excl;
        if (i == NN - 1) g_rowptr[NN] = excl + d;
    }
}
__global__ void scatter_kernel(const int* __restrict__ edge_index) {
    int e = blockIdx.x * blockDim.x + threadIdx.x;
    if (e >= NE) return;
    int src = edge_index[e];
    int dst = edge_index[NE + e];
    int pos = atomicAdd(&g_wr[dst], 1);
    g_col[pos] = src;
}

// ---------------- aggregation ----------------
// FP16BN=false: reads fp32 H, no BN. FP16BN=true: reads fp16 H, fused BN+relu.
template <bool FP16BN>
__global__ __launch_bounds__(256) void aggregate_kernel(
        const void* __restrict__ Hv,
        const float* __restrict__ e1l, const float* __restrict__ e2l,
        const float* __restrict__ gamma, const float* __restrict__ beta,
        const float* __restrict__ ssum, const float* __restrict__ ssq) {
    __shared__ float4 se[(7 + 3) * 32];
    for (int i = threadIdx.x; i < (7 + 3) * 32; i += blockDim.x) {
        se[i] = (i < 7 * 32) ? ((const float4*)e1l)[i]
                             : ((const float4*)e2l)[i - 7 * 32];
    }
    __syncthreads();

    int tid = threadIdx.x;
    int warp = tid >> 5;
    int lane = tid & 31;
    int v = blockIdx.x * 8 + warp;
    if (v >= NN) return;

    float4 scl = make_float4(0, 0, 0, 0), sft = make_float4(0, 0, 0, 0);
    if (FP16BN) {
        int c = lane * 4;
        float invn = 1.0f / (float)NN;
        float s[4], f[4];
#pragma unroll
        for (int k = 0; k < 4; k++) {
            float mu = ssum[c + k] * invn;
            float var = ssq[c + k] * invn - mu * mu;
            float rs = rsqrtf(var + BN_EPS);
            s[k] = gamma[c + k] * rs;
            f[k] = beta[c + k] - mu * s[k];
        }
        scl = make_float4(s[0], s[1], s[2], s[3]);
        sft = make_float4(f[0], f[1], f[2], f[3]);
    }

    const float* Hf = (const float*)Hv;
    const uint16_t* Hh = (const uint16_t*)Hv;
    auto ldT = [&](int s) -> float4 {
        if (FP16BN) {
            uint2 raw = *(const uint2*)(Hh + (size_t)s * DD + lane * 4);
            float2 f0 = __half22float2(*reinterpret_cast<const __half2*>(&raw.x));
            float2 f1 = __half22float2(*reinterpret_cast<const __half2*>(&raw.y));
            float4 x;
            x.x = fmaxf(fmaf(f0.x, scl.x, sft.x), 0.f);
            x.y = fmaxf(fmaf(f0.y, scl.y, sft.y), 0.f);
            x.z = fmaxf(fmaf(f1.x, scl.z, sft.z), 0.f);
            x.w = fmaxf(fmaf(f1.y, scl.w, sft.w), 0.f);
            return x;
        } else {
            return ((const float4*)(Hf + (size_t)s * DD))[lane];
        }
    };

    float4 acc = ldT(v);
    float4 t4 = se[4 * 32 + lane];
    acc.x += t4.x; acc.y += t4.y; acc.z += t4.z; acc.w += t4.w;
    t4 = se[7 * 32 + lane];
    acc.x += t4.x; acc.y += t4.y; acc.z += t4.z; acc.w += t4.w;

    float4 acc2 = make_float4(0.f, 0.f, 0.f, 0.f);
    int beg = g_rowptr[v];
    int end = g_rowptr[v + 1];
    int j = beg;
    for (; j + 3 < end; j += 4) {
        int s0 = g_col[j], s1 = g_col[j + 1], s2 = g_col[j + 2], s3 = g_col[j + 3];
        float4 a0 = ldT(s0);
        float4 a1 = ldT(s1);
        float4 a2 = ldT(s2);
        float4 a3 = ldT(s3);
        acc.x += a0.x + a1.x; acc.y += a0.y + a1.y;
        acc.z += a0.z + a1.z; acc.w += a0.w + a1.w;
        acc2.x += a2.x + a3.x; acc2.y += a2.y + a3.y;
        acc2.z += a2.z + a3.z; acc2.w += a2.w + a3.w;
    }
    for (; j < end; j++) {
        float4 hv = ldT(g_col[j]);
        acc.x += hv.x; acc.y += hv.y; acc.z += hv.z; acc.w += hv.w;
    }
    acc.x += acc2.x; acc.y += acc2.y; acc.z += acc2.z; acc.w += acc2.w;

#pragma unroll
    for (int t = 0; t < 7; t++) {
        int c = g_cnt1[v * 7 + t];
        if (c) {
            float fc = (float)c;
            float4 ev = se[t * 32 + lane];
            acc.x += fc * ev.x; acc.y += fc * ev.y; acc.z += fc * ev.z; acc.w += fc * ev.w;
        }
    }
#pragma unroll
    for (int t = 0; t < 3; t++) {
        int c = g_cnt2[v * 3 + t];
        if (c) {
            float fc = (float)c;
            float4 ev = se[(7 + t) * 32 + lane];
            acc.x += fc * ev.x; acc.y += fc * ev.y; acc.z += fc * ev.z; acc.w += fc * ev.w;
        }
    }
    uint16_t h0, h1, h2, h3, l0, l1, l2, l3;
    split_f16(acc.x, h0, l0);
    split_f16(acc.y, h1, l1);
    split_f16(acc.z, h2, l2);
    split_f16(acc.w, h3, l3);
    uint2 hv2, lv2;
    hv2.x = (uint32_t)h0 | ((uint32_t)h1 << 16);
    hv2.y = (uint32_t)h2 | ((uint32_t)h3 << 16);
    lv2.x = (uint32_t)l0 | ((uint32_t)l1 << 16);
    lv2.y = (uint32_t)l2 | ((uint32_t)l3 << 16);
    *(uint2*)(g_a1 + (size_t)v * 256 + lane * 4) = hv2;
    *(uint2*)(g_a1 + (size_t)v * 256 + 128 + lane * 4) = lv2;
}

// ---------------- warp-MMA GEMM (HMMA fp16, fp32 accum, 2-stage) ----------
template <int NC, int KA, int KB, bool G1, bool OUT16>
__global__ void __launch_bounds__(256)
gemm_mma_kernel(const uint16_t* __restrict__ A,
                const uint16_t* __restrict__ Bm,
                const float* __restrict__ bias,
                uint16_t* __restrict__ outHL,
                float* __restrict__ outF,
                uint16_t* __restrict__ outF16,
                float* __restrict__ statSum,
                float* __restrict__ statSq) {
    extern __shared__ char smem[];
    float* sBias = (float*)smem;                  // 1024 B
    char* Abuf = smem + 1024;                     // 2 x 16 KB
    char* Bbuf = smem + 1024 + 2 * 16384;         // 2 x 16 KB
    const int tid = threadIdx.x;
    const int wid = tid >> 5;
    const int lane = tid & 31;
    const int m0 = blockIdx.x * 128;
    const int n0 = blockIdx.y * 128;
    const int wm = (wid >> 2) * 64;
    const int wn = (wid & 3) * 32;

    if (tid < 128) sBias[tid] = bias[n0 + tid];

    float acc[4][4][4];
#pragma unroll
    for (int i = 0; i < 4; i++)
#pragma unroll
        for (int j = 0; j < 4; j++)
#pragma unroll
            for (int k = 0; k < 4; k++) acc[i][j][k] = 0.f;

    auto loadChunk = [&](int c, int buf) {
        const uint16_t* Ag = A + (size_t)m0 * KA + c * 64;
        const uint16_t* Bg = Bm + (size_t)n0 * KB + c * 64;
        uint32_t ab = s2u(Abuf + buf * 16384);
        uint32_t bb = s2u(Bbuf + buf * 16384);
#pragma unroll
        for (int i = 0; i < 4; i++) {
            int idx = tid + i * 256;
            int r = idx >> 3, c16 = idx & 7;
            CP_A16(ab + SWZ(r * 128 + c16 * 16), Ag + (size_t)r * KA + c16 * 8);
        }
#pragma unroll
        for (int i = 0; i < 4; i++) {
            int idx = tid + i * 256;
            int r = idx >> 3, c16 = idx & 7;
            CP_A16(bb + SWZ(r * 128 + c16 * 16), Bg + (size_t)r * KB + c16 * 8);
        }
    };

    loadChunk(0, 0);
    CP_COMMIT();
    for (int c = 0; c < NC; c++) {
        int buf = c & 1;
        if (c + 1 < NC) {
            loadChunk(c + 1, buf ^ 1);
            CP_COMMIT();
            CP_WAIT(1);
        } else {
            CP_WAIT(0);
        }
        __syncthreads();
        uint32_t aBase = s2u(Abuf + buf * 16384);
        uint32_t bBase = s2u(Bbuf + buf * 16384);
#pragma unroll
        for (int ks = 0; ks < 4; ks++) {
            int k0b = ks * 32;
            uint32_t af[4][4];
#pragma unroll
            for (int mt = 0; mt < 4; mt++) {
                int row = wm + mt * 16 + (lane & 15);
                uint32_t addr = aBase + SWZ(row * 128 + k0b + ((lane >> 4) << 4));
                LDSM_X4(af[mt][0], af[mt][1], af[mt][2], af[mt][3], addr);
            }
            uint32_t bfr[4][2];
#pragma unroll
            for (int p = 0; p < 2; p++) {
                int g = lane >> 3;
                int nrow = wn + p * 16 + (lane & 7) + ((g >> 1) << 3);
                uint32_t addr = bBase + SWZ(nrow * 128 + k0b + ((g & 1) << 4));
                uint32_t r0, r1, r2, r3;
                LDSM_X4(r0, r1, r2, r3, addr);
                bfr[2 * p][0] = r0; bfr[2 * p][1] = r1;
                bfr[2 * p + 1][0] = r2; bfr[2 * p + 1][1] = r3;
            }
#pragma unroll
            for (int mt = 0; mt < 4; mt++)
#pragma unroll
                for (int nt = 0; nt < 4; nt++)
                    MMA16816(acc[mt][nt], af[mt], bfr[nt]);
        }
        __syncthreads();
    }

    // ---- epilogue ----
#pragma unroll
    for (int nt = 0; nt < 4; nt++) {
        int cl = wn + nt * 8 + 2 * (lane & 3);
        int cg = n0 + cl;
        float b0 = sBias[cl], b1 = sBias[cl + 1];
        float s0 = 0.f, s1 = 0.f, q0 = 0.f, q1 = 0.f;
#pragma unroll
        for (int mt = 0; mt < 4; mt++) {
#pragma unroll
            for (int h = 0; h < 2; h++) {
                int m = m0 + wm + mt * 16 + (lane >> 2) + h * 8;
                float v0 = acc[mt][nt][2 * h] + b0;
                float v1 = acc[mt][nt][2 * h + 1] + b1;
                if (G1) {
                    v0 = fmaxf(v0, 0.f);
                    v1 = fmaxf(v1, 0.f);
                    uint16_t h0, l0, h1, l1;
                    split_f16(v0, h0, l0);
                    split_f16(v1, h1, l1);
                    if (m >= NN) { h0 = l0 = h1 = l1 = 0; }
                    *(uint32_t*)(outHL + (size_t)m * 512 + cg) =
                        (uint32_t)h0 | ((uint32_t)h1 << 16);
                    *(uint32_t*)(outHL + (size_t)m * 512 + 256 + cg) =
                        (uint32_t)l0 | ((uint32_t)l1 << 16);
                } else {
                    if (m < NN) {
                        if (OUT16) {
                            __half2 hp = __floats2half2_rn(v0, v1);
                            *(uint32_t*)(outF16 + (size_t)m * 128 + cg) =
                                *reinterpret_cast<uint32_t*>(&hp);
                        } else {
                            float2 v; v.x = v0; v.y = v1;
                            *(float2*)(outF + (size_t)m * 128 + cg) = v;
                        }
                        s0 += v0; s1 += v1;
                        q0 += v0 * v0; q1 += v1 * v1;
                    }
                }
            }
        }
        if (!G1) {
#pragma unroll
            for (int off = 16; off >= 4; off >>= 1) {
                s0 += __shfl_down_sync(0xffffffff, s0, off);
                s1 += __shfl_down_sync(0xffffffff, s1, off);
                q0 += __shfl_down_sync(0xffffffff, q0, off);
                q1 += __shfl_down_sync(0xffffffff, q1, off);
            }
            if (lane < 4) {
                atomicAdd(&statSum[cg], s0);
                atomicAdd(&statSum[cg + 1], s1);
                atomicAdd(&statSq[cg], q0);
                atomicAdd(&statSq[cg + 1], q1);
            }
        }
    }
}

// ---------------- final BN apply ----------------
__global__ void bn_apply_kernel(const float* __restrict__ X,
                                const float* __restrict__ gamma,
                                const float* __restrict__ beta,
                                const float* __restrict__ ssum,
                                const float* __restrict__ ssq,
                                float* __restrict__ Y) {
    int idx = blockIdx.x * blockDim.x + threadIdx.x;
    if (idx >= NN * (DD / 4)) return;
    int v = idx >> 5;
    int c4 = idx & 31;
    int c = c4 * 4;
    float4 x = ((const float4*)(X + (size_t)v * DD))[c4];
    float invn = 1.0f / (float)NN;
    float o[4];
    float xi[4] = {x.x, x.y, x.z, x.w};
#pragma unroll
    for (int k = 0; k < 4; k++) {
        float mu = ssum[c + k] * invn;
        float var = ssq[c + k] * invn - mu * mu;
        float rs = rsqrtf(var + BN_EPS);
        o[k] = gamma[c + k] * (xi[k] - mu) * rs + beta[c + k];
    }
    ((float4*)(Y + (size_t)v * DD))[c4] = make_float4(o[0], o[1], o[2], o[3]);
}

// ---------------- launch ----------------
extern "C" void kernel_launch(void* const* d_in, const int* in_sizes, int n_in,
                              void* d_out, int out_size) {
    const int* x          = (const int*)d_in[0];
    const int* edge_index = (const int*)d_in[1];
    const int* edge_attr  = (const int*)d_in[2];
    const float* xemb1 = (const float*)d_in[4];
    const float* xemb2 = (const float*)d_in[5];
    const float* e1    = (const float*)d_in[6];
    const float* e2    = (const float*)d_in[7];
    const float* W1    = (const float*)d_in[8];
    const float* b1    = (const float*)d_in[9];
    const float* W2    = (const float*)d_in[10];
    const float* b2    = (const float*)d_in[11];
    const float* gamma = (const float*)d_in[12];
    const float* beta  = (const float*)d_in[13];
    float* out = (float*)d_out;

    float *p_h, *p_h2, *p_sum, *p_sq;
    uint16_t *p_h2h, *p_a1, *p_a2, *p_b1, *p_b2;
    cudaGetSymbolAddress((void**)&p_h,   g_h);
    cudaGetSymbolAddress((void**)&p_h2,  g_h2);
    cudaGetSymbolAddress((void**)&p_h2h, g_h2h);
    cudaGetSymbolAddress((void**)&p_a1,  g_a1);
    cudaGetSymbolAddress((void**)&p_a2,  g_a2);
    cudaGetSymbolAddress((void**)&p_b1,  g_b1);
    cudaGetSymbolAddress((void**)&p_b2,  g_b2);
    cudaGetSymbolAddress((void**)&p_sum, g_colsum);
    cudaGetSymbolAddress((void**)&p_sq,  g_colsq);

    constexpr int SMEM_SZ = 1024 + 4 * 16384;   // 66560 (2-stage)
    cudaFuncSetAttribute(gemm_mma_kernel<4, 256, 256, true, false>,
                         cudaFuncAttributeMaxDynamicSharedMemorySize, SMEM_SZ);
    cudaFuncSetAttribute(gemm_mma_kernel<8, 512, 512, false, true>,
                         cudaFuncAttributeMaxDynamicSharedMemorySize, SMEM_SZ);
    cudaFuncSetAttribute(gemm_mma_kernel<8, 512, 512, false, false>,
                         cudaFuncAttributeMaxDynamicSharedMemorySize, SMEM_SZ);

    setup_kernel<<<(SZ5 + 255) / 256, 256>>>(W1, W2);
    embed_kernel<<<(NN * 32 + 255) / 256, 256>>>(x, xemb1, xemb2);
    hist_kernel<<<(NE + 255) / 256, 256>>>(edge_index, edge_attr);
    scan1_kernel<<<SCAN_G, SCAN_B>>>();
    scan2_kernel<<<1, SCAN_B>>>();
    scan3_kernel<<<SCAN_G, SCAN_B>>>();
    scatter_kernel<<<(NE + 255) / 256, 256>>>(edge_index);

    for (int l = 0; l < 2; l++) {
        const float* e1l = e1 + (size_t)l * 7 * DD;
        const float* e2l = e2 + (size_t)l * 3 * DD;
        const float* b1l = b1 + (size_t)l * 2 * DD;
        const float* b2l = b2 + (size_t)l * DD;
        float* sumL = p_sum + l * DD;
        float* sqL  = p_sq + l * DD;
        uint16_t* b1w = p_b1 + (size_t)l * 65536;
        uint16_t* b2w = p_b2 + (size_t)l * 65536;

        if (l == 0) {
            aggregate_kernel<false><<<(NN + 7) / 8, 256>>>(
                p_h, e1l, e2l, nullptr, nullptr, nullptr, nullptr);
        } else {
            aggregate_kernel<true><<<(NN + 7) / 8, 256>>>(
                p_h2h, e1l, e2l, gamma, beta, p_sum, p_sq);   // layer-0 stats/params
        }
        gemm_mma_kernel<4, 256, 256, true, false><<<dim3(MP / 128, 2), 256, SMEM_SZ>>>(
            p_a1, b1w, b1l, p_a2, nullptr, nullptr, nullptr, nullptr);
        if (l == 0) {
            gemm_mma_kernel<8, 512, 512, false, true><<<dim3(MP / 128, 1), 256, SMEM_SZ>>>(
                p_a2, b2w, b2l, nullptr, nullptr, p_h2h, sumL, sqL);
        } else {
            gemm_mma_kernel<8, 512, 512, false, false><<<dim3(MP / 128, 1), 256, SMEM_SZ>>>(
                p_a2, b2w, b2l, nullptr, p_h2, nullptr, sumL, sqL);
        }
    }
    bn_apply_kernel<<<(NN * 32 + 255) / 256, 256>>>(
        p_h2, gamma + DD, beta + DD, p_sum + DD, p_sq + DD, out);
}

// round 11
// speedup vs baseline: 2.2646x; 1.0460x over previous
#include <cuda_runtime.h>
#include <cuda_fp16.h>
#include <cstdint>

#define NN 50000
#define NE 800000
#define DD 128
#define MP 50048              // 391 * 128 padded rows
#define BN_EPS 1e-5f

#define SCAN_B 256
#define SCAN_G ((NN + SCAN_B - 1) / SCAN_B)   // 196

// ---------------- scratch (device globals) ----------------
__device__ float g_h2[NN * DD];               // layer-1 pre-BN output (fp32)
__device__ uint16_t g_h2h[(size_t)NN * DD];   // layer-0 pre-BN output (fp16)
__device__ uint16_t g_a1[(size_t)MP * 256];   // GEMM1 A fp16: [hi(128)|lo(128)]
__device__ uint16_t g_a2[(size_t)MP * 512];   // GEMM2 A fp16: [hi(256)|lo(256)]
__device__ uint16_t g_b1[2 * 256 * 256];      // GEMM1 B fp16 per layer: [n, hi|hi]
__device__ uint16_t g_b2[2 * 128 * 512];      // GEMM2 B fp16 per layer: [n, hi|hi]
__device__ uint8_t  g_ctab[NN];               // combined embedding index (0..8)
__device__ float    g_htab[9 * 128];          // 9 distinct node embeddings (fp32)
__device__ int   g_rowptr[NN + 1];
__device__ int   g_wr[NN];
__device__ int   g_col[NE];
__device__ int   g_cnt1[NN * 7];
__device__ int   g_cnt2[NN * 3];
__device__ float g_colsum[2 * DD];
__device__ float g_colsq[2 * DD];
__device__ int   g_bsum[SCAN_G];
__device__ int   g_boff[SCAN_G];

// ---------------- helpers ----------------
__device__ __forceinline__ uint32_t s2u(const void* p) {
    uint32_t a;
    asm("{ .reg .u64 t; cvta.to.shared.u64 t, %1; cvt.u32.u64 %0, t; }" : "=r"(a) : "l"(p));
    return a;
}
#define SWZ(x) ((x) ^ (((x) >> 3) & 0x70))

#define CP_A16(dst, src) \
    asm volatile("cp.async.cg.shared.global [%0], [%1], 16;" :: "r"(dst), "l"(src))
#define CP_COMMIT() asm volatile("cp.async.commit_group;")
#define CP_WAIT(n)  asm volatile("cp.async.wait_group %0;" :: "n"(n))

#define LDSM_X4(r0, r1, r2, r3, addr) \
    asm volatile("ldmatrix.sync.aligned.m8n8.x4.shared.b16 {%0,%1,%2,%3}, [%4];" \
        : "=r"(r0), "=r"(r1), "=r"(r2), "=r"(r3) : "r"(addr))
#define MMA16816(d, a, b) \
    asm volatile("mma.sync.aligned.m16n8k16.row.col.f32.f16.f16.f32 " \
        "{%0,%1,%2,%3}, {%4,%5,%6,%7}, {%8,%9}, {%0,%1,%2,%3};" \
        : "+f"((d)[0]), "+f"((d)[1]), "+f"((d)[2]), "+f"((d)[3]) \
        : "r"((a)[0]), "r"((a)[1]), "r"((a)[2]), "r"((a)[3]), \
          "r"((b)[0]), "r"((b)[1]))

__device__ __forceinline__ void split_f16(float v, uint16_t& hi, uint16_t& lo) {
    __half h = __float2half_rn(v);
    float rem = v - __half2float(h);
    __half l = __float2half_rn(rem);
    hi = __half_as_ushort(h);
    lo = __half_as_ushort(l);
}

// ---------------- fused setup ----------------
#define SS0 (NN * 7)                      // cnt1
#define SS1 (SS0 + NN * 3)                // cnt2
#define SS2 (SS1 + (MP - NN) * 256)       // a1 pad rows
#define SS3 (SS2 + 512)                   // BN stats
#define SS4 (SS3 + NN)                    // ctab
#define SS5 (SS4 + 9 * 128)               // htab
#define SS6 (SS5 + 2 * 128 * 256)         // b1 builds
#define SS7 (SS6 + 2 * 256 * 128)         // b2 builds
__global__ void setup_kernel(const int* __restrict__ x,
                             const float* __restrict__ xemb1,
                             const float* __restrict__ xemb2,
                             const float* __restrict__ W1,
                             const float* __restrict__ W2) {
    int i = blockIdx.x * blockDim.x + threadIdx.x;
    if (i >= SS7) return;
    if (i < SS0) {
        g_cnt1[i] = 0;
    } else if (i < SS1) {
        g_cnt2[i - SS0] = 0;
    } else if (i < SS2) {
        g_a1[(size_t)NN * 256 + (i - SS1)] = 0;
    } else if (i < SS3) {
        int j = i - SS2;
        if (j < 256) g_colsum[j] = 0.f;
        else g_colsq[j - 256] = 0.f;
    } else if (i < SS4) {
        int v = i - SS3;
        int c = x[2 * v] * 3 + x[2 * v + 1];
        g_ctab[v] = (uint8_t)min(c, 8);
    } else if (i < SS5) {
        int j = i - SS4;
        int c = j >> 7, d = j & 127;
        g_htab[j] = xemb1[(c / 3) * DD + d] + xemb2[(c % 3) * DD + d];
    } else if (i < SS6) {
        int j = i - SS5;
        int l = j >> 15;
        int r = j & 32767;          // k*256+n
        int k = r >> 8, n = r & 255;
        uint16_t hv = __half_as_ushort(__float2half_rn(W1[(size_t)l * 32768 + r]));
        g_b1[(size_t)l * 65536 + n * 256 + k]       = hv;
        g_b1[(size_t)l * 65536 + n * 256 + 128 + k] = hv;
    } else {
        int j = i - SS6;
        int l = j >> 15;
        int r = j & 32767;          // k*128+n
        int k = r >> 7, n = r & 127;
        uint16_t hv = __half_as_ushort(__float2half_rn(W2[(size_t)l * 32768 + r]));
        g_b2[(size_t)l * 65536 + n * 512 + k]       = hv;
        g_b2[(size_t)l * 65536 + n * 512 + 256 + k] = hv;
    }
}

__global__ void hist_kernel(const int* __restrict__ edge_index,
                            const int* __restrict__ edge_attr) {
    int e = blockIdx.x * blockDim.x + threadIdx.x;
    if (e >= NE) return;
    int dst = edge_index[NE + e];
    atomicAdd(&g_cnt1[dst * 7 + edge_attr[2 * e]], 1);
    atomicAdd(&g_cnt2[dst * 3 + edge_attr[2 * e + 1]], 1);
}
__device__ __forceinline__ int node_deg(int i) {
    int d = 0;
#pragma unroll
    for (int t = 0; t < 7; t++) d += g_cnt1[i * 7 + t];
    return d;
}
__global__ void scan1_kernel() {
    __shared__ int sh[SCAN_B];
    int t = threadIdx.x;
    int i = blockIdx.x * SCAN_B + t;
    sh[t] = (i < NN) ? node_deg(i) : 0;
    __syncthreads();
    for (int off = SCAN_B / 2; off > 0; off >>= 1) {
        if (t < off) sh[t] += sh[t + off];
        __syncthreads();
    }
    if (t == 0) g_bsum[blockIdx.x] = sh[0];
}
__global__ void scan2_kernel() {
    __shared__ int sh[SCAN_B];
    int t = threadIdx.x;
    sh[t] = (t < SCAN_G) ? g_bsum[t] : 0;
    __syncthreads();
    for (int off = 1; off < SCAN_B; off <<= 1) {
        int v = (t >= off) ? sh[t - off] : 0;
        __syncthreads();
        sh[t] += v;
        __syncthreads();
    }
    if (t < SCAN_G) g_boff[t] = (t == 0) ? 0 : sh[t - 1];
}
__global__ void scan3_kernel() {
    __shared__ int sh[SCAN_B];
    int t = threadIdx.x;
    int i = blockIdx.x * SCAN_B + t;
    int d = (i < NN) ? node_deg(i) : 0;
    sh[t] = d;
    __syncthreads();
    for (int off = 1; off < SCAN_B; off <<= 1) {
        int v = (t >= off) ? sh[t - off] : 0;
        __syncthreads();
        sh[t] += v;
        __syncthreads();
    }
    if (i < NN) {
        int excl = g_boff[blockIdx.x] + sh[t] - d;
        g_rowptr[i] = excl;
        g_wr[i] = excl;
        if (i == NN - 1) g_rowptr[NN] = excl + d;
    }
}
__global__ void scatter_kernel(const int* __restrict__ edge_index) {
    int e = blockIdx.x * blockDim.x + threadIdx.x;
    if (e >= NE) return;
    int src = edge_index[e];
    int dst = edge_index[NE + e];
    int pos = atomicAdd(&g_wr[dst], 1);
    g_col[pos] = src;
}

// ---------------- layer-0 aggregation: table-based (h has only 9 values) ----
__global__ __launch_bounds__(512) void aggregate0_kernel(
        const float* __restrict__ e1l, const float* __restrict__ e2l) {
    __shared__ float4 ht[9 * 32];
    __shared__ float4 se[(7 + 3) * 32];
    int tid = threadIdx.x;
    for (int i = tid; i < 9 * 32; i += 512) ht[i] = ((const float4*)g_htab)[i];
    for (int i = tid; i < 320; i += 512)
        se[i] = (i < 224) ? ((const float4*)e1l)[i] : ((const float4*)e2l)[i - 224];
    __syncthreads();

    int warp = tid >> 5;
    int lane = tid & 31;
    int v = blockIdx.x * 16 + warp;
    if (v >= NN) return;

    float4 acc = ht[g_ctab[v] * 32 + lane];
    float4 t4 = se[4 * 32 + lane];
    acc.x += t4.x; acc.y += t4.y; acc.z += t4.z; acc.w += t4.w;
    t4 = se[7 * 32 + lane];
    acc.x += t4.x; acc.y += t4.y; acc.z += t4.z; acc.w += t4.w;

    float4 acc2 = make_float4(0.f, 0.f, 0.f, 0.f);
    int beg = g_rowptr[v];
    int end = g_rowptr[v + 1];
    int j = beg;
    for (; j + 3 < end; j += 4) {
        int c0 = g_ctab[g_col[j]];
        int c1 = g_ctab[g_col[j + 1]];
        int c2 = g_ctab[g_col[j + 2]];
        int c3 = g_ctab[g_col[j + 3]];
        float4 a0 = ht[c0 * 32 + lane];
        float4 a1 = ht[c1 * 32 + lane];
        float4 a2 = ht[c2 * 32 + lane];
        float4 a3 = ht[c3 * 32 + lane];
        acc.x += a0.x + a1.x; acc.y += a0.y + a1.y;
        acc.z += a0.z + a1.z; acc.w += a0.w + a1.w;
        acc2.x += a2.x + a3.x; acc2.y += a2.y + a3.y;
        acc2.z += a2.z + a3.z; acc2.w += a2.w + a3.w;
    }
    for (; j < end; j++) {
        float4 hv = ht[g_ctab[g_col[j]] * 32 + lane];
        acc.x += hv.x; acc.y += hv.y; acc.z += hv.z; acc.w += hv.w;
    }
    acc.x += acc2.x; acc.y += acc2.y; acc.z += acc2.z; acc.w += acc2.w;

#pragma unroll
    for (int t = 0; t < 7; t++) {
        int c = g_cnt1[v * 7 + t];
        if (c) {
            float fc = (float)c;
            float4 ev = se[t * 32 + lane];
            acc.x += fc * ev.x; acc.y += fc * ev.y; acc.z += fc * ev.z; acc.w += fc * ev.w;
        }
    }
#pragma unroll
    for (int t = 0; t < 3; t++) {
        int c = g_cnt2[v * 3 + t];
        if (c) {
            float fc = (float)c;
            float4 ev = se[(7 + t) * 32 + lane];
            acc.x += fc * ev.x; acc.y += fc * ev.y; acc.z += fc * ev.z; acc.w += fc * ev.w;
        }
    }
    uint16_t h0, h1, h2, h3, l0, l1, l2, l3;
    split_f16(acc.x, h0, l0);
    split_f16(acc.y, h1, l1);
    split_f16(acc.z, h2, l2);
    split_f16(acc.w, h3, l3);
    uint2 hv2, lv2;
    hv2.x = (uint32_t)h0 | ((uint32_t)h1 << 16);
    hv2.y = (uint32_t)h2 | ((uint32_t)h3 << 16);
    lv2.x = (uint32_t)l0 | ((uint32_t)l1 << 16);
    lv2.y = (uint32_t)l2 | ((uint32_t)l3 << 16);
    *(uint2*)(g_a1 + (size_t)v * 256 + lane * 4) = hv2;
    *(uint2*)(g_a1 + (size_t)v * 256 + 128 + lane * 4) = lv2;
}

// ---------------- layer-1 aggregation: fp16 gathers + fused BN+relu --------
__global__ __launch_bounds__(256) void aggregate1_kernel(
        const uint16_t* __restrict__ Hh,
        const float* __restrict__ e1l, const float* __restrict__ e2l,
        const float* __restrict__ gamma, const float* __restrict__ beta,
        const float* __restrict__ ssum, const float* __restrict__ ssq) {
    __shared__ float4 se[(7 + 3) * 32];
    for (int i = threadIdx.x; i < 320; i += 256)
        se[i] = (i < 224) ? ((const float4*)e1l)[i] : ((const float4*)e2l)[i - 224];
    __syncthreads();

    int tid = threadIdx.x;
    int warp = tid >> 5;
    int lane = tid & 31;
    int v = blockIdx.x * 8 + warp;
    if (v >= NN) return;

    int cc = lane * 4;
    float invn = 1.0f / (float)NN;
    float scl[4], sft[4];
#pragma unroll
    for (int k = 0; k < 4; k++) {
        float mu = ssum[cc + k] * invn;
        float var = ssq[cc + k] * invn - mu * mu;
        float rs = rsqrtf(var + BN_EPS);
        scl[k] = gamma[cc + k] * rs;
        sft[k] = beta[cc + k] - mu * scl[k];
    }

    auto cvt = [&](uint2 raw) -> float4 {
        float2 f0 = __half22float2(*reinterpret_cast<const __half2*>(&raw.x));
        float2 f1 = __half22float2(*reinterpret_cast<const __half2*>(&raw.y));
        float4 x;
        x.x = fmaxf(fmaf(f0.x, scl[0], sft[0]), 0.f);
        x.y = fmaxf(fmaf(f0.y, scl[1], sft[1]), 0.f);
        x.z = fmaxf(fmaf(f1.x, scl[2], sft[2]), 0.f);
        x.w = fmaxf(fmaf(f1.y, scl[3], sft[3]), 0.f);
        return x;
    };

    float4 acc = cvt(*(const uint2*)(Hh + (size_t)v * DD + lane * 4));
    float4 t4 = se[4 * 32 + lane];
    acc.x += t4.x; acc.y += t4.y; acc.z += t4.z; acc.w += t4.w;
    t4 = se[7 * 32 + lane];
    acc.x += t4.x; acc.y += t4.y; acc.z += t4.z; acc.w += t4.w;

    float4 acc2 = make_float4(0.f, 0.f, 0.f, 0.f);
    int beg = g_rowptr[v];
    int end = g_rowptr[v + 1];
    int j = beg;
    for (; j + 7 < end; j += 8) {
        uint2 raw[8];
#pragma unroll
        for (int q = 0; q < 8; q++)
            raw[q] = *(const uint2*)(Hh + (size_t)g_col[j + q] * DD + lane * 4);
#pragma unroll
        for (int q = 0; q < 8; q += 2) {
            float4 a0 = cvt(raw[q]);
            float4 a1 = cvt(raw[q + 1]);
            if (q & 2) {
                acc2.x += a0.x + a1.x; acc2.y += a0.y + a1.y;
                acc2.z += a0.z + a1.z; acc2.w += a0.w + a1.w;
            } else {
                acc.x += a0.x + a1.x; acc.y += a0.y + a1.y;
                acc.z += a0.z + a1.z; acc.w += a0.w + a1.w;
            }
        }
    }
    for (; j < end; j++) {
        float4 hv = cvt(*(const uint2*)(Hh + (size_t)g_col[j] * DD + lane * 4));
        acc.x += hv.x; acc.y += hv.y; acc.z += hv.z; acc.w += hv.w;
    }
    acc.x += acc2.x; acc.y += acc2.y; acc.z += acc2.z; acc.w += acc2.w;

#pragma unroll
    for (int t = 0; t < 7; t++) {
        int c = g_cnt1[v * 7 + t];
        if (c) {
            float fc = (float)c;
            float4 ev = se[t * 32 + lane];
            acc.x += fc * ev.x; acc.y += fc * ev.y; acc.z += fc * ev.z; acc.w += fc * ev.w;
        }
    }
#pragma unroll
    for (int t = 0; t < 3; t++) {
        int c = g_cnt2[v * 3 + t];
        if (c) {
            float fc = (float)c;
            float4 ev = se[(7 + t) * 32 + lane];
            acc.x += fc * ev.x; acc.y += fc * ev.y; acc.z += fc * ev.z; acc.w += fc * ev.w;
        }
    }
    uint16_t h0, h1, h2, h3, l0, l1, l2, l3;
    split_f16(acc.x, h0, l0);
    split_f16(acc.y, h1, l1);
    split_f16(acc.z, h2, l2);
    split_f16(acc.w, h3, l3);
    uint2 hv2, lv2;
    hv2.x = (uint32_t)h0 | ((uint32_t)h1 << 16);
    hv2.y = (uint32_t)h2 | ((uint32_t)h3 << 16);
    lv2.x = (uint32_t)l0 | ((uint32_t)l1 << 16);
    lv2.y = (uint32_t)l2 | ((uint32_t)l3 << 16);
    *(uint2*)(g_a1 + (size_t)v * 256 + lane * 4) = hv2;
    *(uint2*)(g_a1 + (size_t)v * 256 + 128 + lane * 4) = lv2;
}

// ---------------- warp-MMA GEMM (HMMA fp16, fp32 accum, 2-stage) ----------
template <int NC, int KA, int KB, bool G1, bool OUT16>
__global__ void __launch_bounds__(256)
gemm_mma_kernel(const uint16_t* __restrict__ A,
                const uint16_t* __restrict__ Bm,
                const float* __restrict__ bias,
                uint16_t* __restrict__ outHL,
                float* __restrict__ outF,
                uint16_t* __restrict__ outF16,
                float* __restrict__ statSum,
                float* __restrict__ statSq) {
    extern __shared__ char smem[];
    float* sBias = (float*)smem;
    char* Abuf = smem + 1024;
    char* Bbuf = smem + 1024 + 2 * 16384;
    const int tid = threadIdx.x;
    const int wid = tid >> 5;
    const int lane = tid & 31;
    const int m0 = blockIdx.x * 128;
    const int n0 = blockIdx.y * 128;
    const int wm = (wid >> 2) * 64;
    const int wn = (wid & 3) * 32;

    if (tid < 128) sBias[tid] = bias[n0 + tid];

    float acc[4][4][4];
#pragma unroll
    for (int i = 0; i < 4; i++)
#pragma unroll
        for (int j = 0; j < 4; j++)
#pragma unroll
            for (int k = 0; k < 4; k++) acc[i][j][k] = 0.f;

    auto loadChunk = [&](int c, int buf) {
        const uint16_t* Ag = A + (size_t)m0 * KA + c * 64;
        const uint16_t* Bg = Bm + (size_t)n0 * KB + c * 64;
        uint32_t ab = s2u(Abuf + buf * 16384);
        uint32_t bb = s2u(Bbuf + buf * 16384);
#pragma unroll
        for (int i = 0; i < 4; i++) {
            int idx = tid + i * 256;
            int r = idx >> 3, c16 = idx & 7;
            CP_A16(ab + SWZ(r * 128 + c16 * 16), Ag + (size_t)r * KA + c16 * 8);
        }
#pragma unroll
        for (int i = 0; i < 4; i++) {
            int idx = tid + i * 256;
            int r = idx >> 3, c16 = idx & 7;
            CP_A16(bb + SWZ(r * 128 + c16 * 16), Bg + (size_t)r * KB + c16 * 8);
        }
    };

    loadChunk(0, 0);
    CP_COMMIT();
    for (int c = 0; c < NC; c++) {
        int buf = c & 1;
        if (c + 1 < NC) {
            loadChunk(c + 1, buf ^ 1);
            CP_COMMIT();
            CP_WAIT(1);
        } else {
            CP_WAIT(0);
        }
        __syncthreads();
        uint32_t aBase = s2u(Abuf + buf * 16384);
        uint32_t bBase = s2u(Bbuf + buf * 16384);
#pragma unroll
        for (int ks = 0; ks < 4; ks++) {
            int k0b = ks * 32;
            uint32_t af[4][4];
#pragma unroll
            for (int mt = 0; mt < 4; mt++) {
                int row = wm + mt * 16 + (lane & 15);
                uint32_t addr = aBase + SWZ(row * 128 + k0b + ((lane >> 4) << 4));
                LDSM_X4(af[mt][0], af[mt][1], af[mt][2], af[mt][3], addr);
            }
            uint32_t bfr[4][2];
#pragma unroll
            for (int p = 0; p < 2; p++) {
                int g = lane >> 3;
                int nrow = wn + p * 16 + (lane & 7) + ((g >> 1) << 3);
                uint32_t addr = bBase + SWZ(nrow * 128 + k0b + ((g & 1) << 4));
                uint32_t r0, r1, r2, r3;
                LDSM_X4(r0, r1, r2, r3, addr);
                bfr[2 * p][0] = r0; bfr[2 * p][1] = r1;
                bfr[2 * p + 1][0] = r2; bfr[2 * p + 1][1] = r3;
            }
#pragma unroll
            for (int mt = 0; mt < 4; mt++)
#pragma unroll
                for (int nt = 0; nt < 4; nt++)
                    MMA16816(acc[mt][nt], af[mt], bfr[nt]);
        }
        __syncthreads();
    }

#pragma unroll
    for (int nt = 0; nt < 4; nt++) {
        int cl = wn + nt * 8 + 2 * (lane & 3);
        int cg = n0 + cl;
        float b0 = sBias[cl], b1 = sBias[cl + 1];
        float s0 = 0.f, s1 = 0.f, q0 = 0.f, q1 = 0.f;
#pragma unroll
        for (int mt = 0; mt < 4; mt++) {
#pragma unroll
            for (int h = 0; h < 2; h++) {
                int m = m0 + wm + mt * 16 + (lane >> 2) + h * 8;
                float v0 = acc[mt][nt][2 * h] + b0;
                float v1 = acc[mt][nt][2 * h + 1] + b1;
                if (G1) {
                    v0 = fmaxf(v0, 0.f);
                    v1 = fmaxf(v1, 0.f);
                    uint16_t h0, l0, h1, l1;
                    split_f16(v0, h0, l0);
                    split_f16(v1, h1, l1);
                    if (m >= NN) { h0 = l0 = h1 = l1 = 0; }
                    *(uint32_t*)(outHL + (size_t)m * 512 + cg) =
                        (uint32_t)h0 | ((uint32_t)h1 << 16);
                    *(uint32_t*)(outHL + (size_t)m * 512 + 256 + cg) =
                        (uint32_t)l0 | ((uint32_t)l1 << 16);
                } else {
                    if (m < NN) {
                        if (OUT16) {
                            __half2 hp = __floats2half2_rn(v0, v1);
                            *(uint32_t*)(outF16 + (size_t)m * 128 + cg) =
                                *reinterpret_cast<uint32_t*>(&hp);
                        } else {
                            float2 v; v.x = v0; v.y = v1;
                            *(float2*)(outF + (size_t)m * 128 + cg) = v;
                        }
                        s0 += v0; s1 += v1;
                        q0 += v0 * v0; q1 += v1 * v1;
                    }
                }
            }
        }
        if (!G1) {
#pragma unroll
            for (int off = 16; off >= 4; off >>= 1) {
                s0 += __shfl_down_sync(0xffffffff, s0, off);
                s1 += __shfl_down_sync(0xffffffff, s1, off);
                q0 += __shfl_down_sync(0xffffffff, q0, off);
                q1 += __shfl_down_sync(0xffffffff, q1, off);
            }
            if (lane < 4) {
                atomicAdd(&statSum[cg], s0);
                atomicAdd(&statSum[cg + 1], s1);
                atomicAdd(&statSq[cg], q0);
                atomicAdd(&statSq[cg + 1], q1);
            }
        }
    }
}

// ---------------- final BN apply ----------------
__global__ void bn_apply_kernel(const float* __restrict__ X,
                                const float* __restrict__ gamma,
                                const float* __restrict__ beta,
                                const float* __restrict__ ssum,
                                const float* __restrict__ ssq,
                                float* __restrict__ Y) {
    int idx = blockIdx.x * blockDim.x + threadIdx.x;
    if (idx >= NN * (DD / 4)) return;
    int v = idx >> 5;
    int c4 = idx & 31;
    int c = c4 * 4;
    float4 x = ((const float4*)(X + (size_t)v * DD))[c4];
    float invn = 1.0f / (float)NN;
    float o[4];
    float xi[4] = {x.x, x.y, x.z, x.w};
#pragma unroll
    for (int k = 0; k < 4; k++) {
        float mu = ssum[c + k] * invn;
        float var = ssq[c + k] * invn - mu * mu;
        float rs = rsqrtf(var + BN_EPS);
        o[k] = gamma[c + k] * (xi[k] - mu) * rs + beta[c + k];
    }
    ((float4*)(Y + (size_t)v * DD))[c4] = make_float4(o[0], o[1], o[2], o[3]);
}

// ---------------- launch ----------------
extern "C" void kernel_launch(void* const* d_in, const int* in_sizes, int n_in,
                              void* d_out, int out_size) {
    const int* x          = (const int*)d_in[0];
    const int* edge_index = (const int*)d_in[1];
    const int* edge_attr  = (const int*)d_in[2];
    const float* xemb1 = (const float*)d_in[4];
    const float* xemb2 = (const float*)d_in[5];
    const float* e1    = (const float*)d_in[6];
    const float* e2    = (const float*)d_in[7];
    const float* W1    = (const float*)d_in[8];
    const float* b1    = (const float*)d_in[9];
    const float* W2    = (const float*)d_in[10];
    const float* b2    = (const float*)d_in[11];
    const float* gamma = (const float*)d_in[12];
    const float* beta  = (const float*)d_in[13];
    float* out = (float*)d_out;

    float *p_h2, *p_sum, *p_sq;
    uint16_t *p_h2h, *p_a1, *p_a2, *p_b1, *p_b2;
    cudaGetSymbolAddress((void**)&p_h2,  g_h2);
    cudaGetSymbolAddress((void**)&p_h2h, g_h2h);
    cudaGetSymbolAddress((void**)&p_a1,  g_a1);
    cudaGetSymbolAddress((void**)&p_a2,  g_a2);
    cudaGetSymbolAddress((void**)&p_b1,  g_b1);
    cudaGetSymbolAddress((void**)&p_b2,  g_b2);
    cudaGetSymbolAddress((void**)&p_sum, g_colsum);
    cudaGetSymbolAddress((void**)&p_sq,  g_colsq);

    constexpr int SMEM_SZ = 1024 + 4 * 16384;   // 66560 (2-stage)
    cudaFuncSetAttribute(gemm_mma_kernel<4, 256, 256, true, false>,
                         cudaFuncAttributeMaxDynamicSharedMemorySize, SMEM_SZ);
    cudaFuncSetAttribute(gemm_mma_kernel<8, 512, 512, false, true>,
                         cudaFuncAttributeMaxDynamicSharedMemorySize, SMEM_SZ);
    cudaFuncSetAttribute(gemm_mma_kernel<8, 512, 512, false, false>,
                         cudaFuncAttributeMaxDynamicSharedMemorySize, SMEM_SZ);

    setup_kernel<<<(SS7 + 255) / 256, 256>>>(x, xemb1, xemb2, W1, W2);
    hist_kernel<<<(NE + 255) / 256, 256>>>(edge_index, edge_attr);
    scan1_kernel<<<SCAN_G, SCAN_B>>>();
    scan2_kernel<<<1, SCAN_B>>>();
    scan3_kernel<<<SCAN_G, SCAN_B>>>();
    scatter_kernel<<<(NE + 255) / 256, 256>>>(edge_index);

    for (int l = 0; l < 2; l++) {
        const float* e1l = e1 + (size_t)l * 7 * DD;
        const float* e2l = e2 + (size_t)l * 3 * DD;
        const float* b1l = b1 + (size_t)l * 2 * DD;
        const float* b2l = b2 + (size_t)l * DD;
        float* sumL = p_sum + l * DD;
        float* sqL  = p_sq + l * DD;
        uint16_t* b1w = p_b1 + (size_t)l * 65536;
        uint16_t* b2w = p_b2 + (size_t)l * 65536;

        if (l == 0) {
            aggregate0_kernel<<<(NN + 15) / 16, 512>>>(e1l, e2l);
        } else {
            aggregate1_kernel<<<(NN + 7) / 8, 256>>>(
                p_h2h, e1l, e2l, gamma, beta, p_sum, p_sq);
        }
        gemm_mma_kernel<4, 256, 256, true, false><<<dim3(MP / 128, 2), 256, SMEM_SZ>>>(
            p_a1, b1w, b1l, p_a2, nullptr, nullptr, nullptr, nullptr);
        if (l == 0) {
            gemm_mma_kernel<8, 512, 512, false, true><<<dim3(MP / 128, 1), 256, SMEM_SZ>>>(
                p_a2, b2w, b2l, nullptr, nullptr, p_h2h, sumL, sqL);
        } else {
            gemm_mma_kernel<8, 512, 512, false, false><<<dim3(MP / 128, 1), 256, SMEM_SZ>>>(
                p_a2, b2w, b2l, nullptr, p_h2, nullptr, sumL, sqL);
        }
    }
    bn_apply_kernel<<<(NN * 32 + 255) / 256, 256>>>(
        p_h2, gamma + DD, beta + DD, p_sum + DD, p_sq + DD, out);
}

// round 12
// speedup vs baseline: 2.4158x; 1.0667x over previous
#include <cuda_runtime.h>
#include <cuda_fp16.h>
#include <cstdint>

#define NN 50000
#define NE 800000
#define DD 128
#define MP 50048              // 391 * 128 padded rows
#define BN_EPS 1e-5f

#define SCAN_B 256
#define SCAN_G ((NN + SCAN_B - 1) / SCAN_B)   // 196

// ---------------- scratch (device globals) ----------------
__device__ float g_h2[NN * DD];               // layer-1 pre-BN output (fp32)
__device__ uint16_t g_h2h[(size_t)NN * DD];   // layer-0 pre-BN output (fp16)
__device__ uint16_t g_a1[(size_t)MP * 256];   // GEMM1 A fp16: [hi(128)|lo(128)]
__device__ uint16_t g_a2[(size_t)MP * 512];   // GEMM2 A fp16: [hi(256)|lo(256)]
__device__ uint16_t g_b1[2 * 256 * 256];      // GEMM1 B fp16 per layer: [n, hi|hi]
__device__ uint16_t g_b2[2 * 128 * 512];      // GEMM2 B fp16 per layer: [n, hi|hi]
__device__ uint8_t  g_ctab[NN];               // combined embedding index (0..8)
__device__ float    g_htab[9 * 128];          // 9 distinct node embeddings (fp32)
__device__ unsigned long long g_pk1[NN];      // cnt1: 7 fields x 9 bits
__device__ unsigned long long g_pk2[NN];      // cnt2: 3x6 bits | cnt3: 9x5 bits @18
__device__ int   g_rowptr[NN + 1];
__device__ int   g_wr[NN];
__device__ int   g_col[NE];
__device__ float g_colsum[2 * DD];
__device__ float g_colsq[2 * DD];
__device__ int   g_bsum[SCAN_G];
__device__ int   g_boff[SCAN_G];
__device__ unsigned int g_tick;

// ---------------- helpers ----------------
__device__ __forceinline__ uint32_t s2u(const void* p) {
    uint32_t a;
    asm("{ .reg .u64 t; cvta.to.shared.u64 t, %1; cvt.u32.u64 %0, t; }" : "=r"(a) : "l"(p));
    return a;
}
#define SWZ(x) ((x) ^ (((x) >> 3) & 0x70))

#define CP_A16(dst, src) \
    asm volatile("cp.async.cg.shared.global [%0], [%1], 16;" :: "r"(dst), "l"(src))
#define CP_COMMIT() asm volatile("cp.async.commit_group;")
#define CP_WAIT(n)  asm volatile("cp.async.wait_group %0;" :: "n"(n))

#define LDSM_X4(r0, r1, r2, r3, addr) \
    asm volatile("ldmatrix.sync.aligned.m8n8.x4.shared.b16 {%0,%1,%2,%3}, [%4];" \
        : "=r"(r0), "=r"(r1), "=r"(r2), "=r"(r3) : "r"(addr))
#define MMA16816(d, a, b) \
    asm volatile("mma.sync.aligned.m16n8k16.row.col.f32.f16.f16.f32 " \
        "{%0,%1,%2,%3}, {%4,%5,%6,%7}, {%8,%9}, {%0,%1,%2,%3};" \
        : "+f"((d)[0]), "+f"((d)[1]), "+f"((d)[2]), "+f"((d)[3]) \
        : "r"((a)[0]), "r"((a)[1]), "r"((a)[2]), "r"((a)[3]), \
          "r"((b)[0]), "r"((b)[1]))

__device__ __forceinline__ void split_f16(float v, uint16_t& hi, uint16_t& lo) {
    __half h = __float2half_rn(v);
    float rem = v - __half2float(h);
    __half l = __float2half_rn(rem);
    hi = __half_as_ushort(h);
    lo = __half_as_ushort(l);
}

// ---------------- fused setup ----------------
#define TT0 (2 * NN)                      // pk1 + pk2 zero
#define TT1 (TT0 + (MP - NN) * 256)       // a1 pad rows
#define TT2 (TT1 + 512)                   // BN stats
#define TT3 (TT2 + NN)                    // ctab
#define TT4 (TT3 + 9 * 128)               // htab
#define TT5 (TT4 + 2 * 128 * 256)         // b1 builds
#define TT6 (TT5 + 2 * 256 * 128)         // b2 builds
#define TT7 (TT6 + 1)                     // tick zero
__global__ void setup_kernel(const int* __restrict__ x,
                             const float* __restrict__ xemb1,
                             const float* __restrict__ xemb2,
                             const float* __restrict__ W1,
                             const float* __restrict__ W2) {
    int i = blockIdx.x * blockDim.x + threadIdx.x;
    if (i >= TT7) return;
    if (i < TT0) {
        if (i < NN) g_pk1[i] = 0ull;
        else g_pk2[i - NN] = 0ull;
    } else if (i < TT1) {
        g_a1[(size_t)NN * 256 + (i - TT0)] = 0;
    } else if (i < TT2) {
        int j = i - TT1;
        if (j < 256) g_colsum[j] = 0.f;
        else g_colsq[j - 256] = 0.f;
    } else if (i < TT3) {
        int v = i - TT2;
        int c = x[2 * v] * 3 + x[2 * v + 1];
        g_ctab[v] = (uint8_t)min(c, 8);
    } else if (i < TT4) {
        int j = i - TT3;
        int c = j >> 7, d = j & 127;
        g_htab[j] = xemb1[(c / 3) * DD + d] + xemb2[(c % 3) * DD + d];
    } else if (i < TT5) {
        int j = i - TT4;
        int l = j >> 15;
        int r = j & 32767;          // k*256+n
        int k = r >> 8, n = r & 255;
        uint16_t hv = __half_as_ushort(__float2half_rn(W1[(size_t)l * 32768 + r]));
        g_b1[(size_t)l * 65536 + n * 256 + k]       = hv;
        g_b1[(size_t)l * 65536 + n * 256 + 128 + k] = hv;
    } else if (i < TT6) {
        int j = i - TT5;
        int l = j >> 15;
        int r = j & 32767;          // k*128+n
        int k = r >> 7, n = r & 127;
        uint16_t hv = __half_as_ushort(__float2half_rn(W2[(size_t)l * 32768 + r]));
        g_b2[(size_t)l * 65536 + n * 512 + k]       = hv;
        g_b2[(size_t)l * 65536 + n * 512 + 256 + k] = hv;
    } else {
        g_tick = 0u;
    }
}

// ---------------- histogram: 2 packed u64 atomics per edge ----------------
__global__ void hist_kernel(const int* __restrict__ edge_index,
                            const int* __restrict__ edge_attr) {
    int e = blockIdx.x * blockDim.x + threadIdx.x;
    if (e >= NE) return;
    int src = edge_index[e];
    int dst = edge_index[NE + e];
    int a0 = edge_attr[2 * e];
    int a1 = edge_attr[2 * e + 1];
    int c  = g_ctab[src];
    atomicAdd(&g_pk1[dst], 1ull << (9 * a0));
    atomicAdd(&g_pk2[dst], (1ull << (6 * a1)) + (1ull << (18 + 5 * c)));
}

__device__ __forceinline__ int node_deg(int i) {
    unsigned long long p = g_pk1[i];
    int d = 0;
#pragma unroll
    for (int t = 0; t < 7; t++) d += (int)((p >> (9 * t)) & 511ull);
    return d;
}

// ---------------- fused scan1+scan2 (last-block ticket) ----------------
__global__ void scanA_kernel() {
    __shared__ int sh[SCAN_B];
    __shared__ bool isLast;
    int t = threadIdx.x;
    int i = blockIdx.x * SCAN_B + t;
    sh[t] = (i < NN) ? node_deg(i) : 0;
    __syncthreads();
    for (int off = SCAN_B / 2; off > 0; off >>= 1) {
        if (t < off) sh[t] += sh[t + off];
        __syncthreads();
    }
    if (t == 0) {
        g_bsum[blockIdx.x] = sh[0];
        __threadfence();
        unsigned tk = atomicAdd(&g_tick, 1u);
        isLast = (tk == gridDim.x - 1);
    }
    __syncthreads();
    if (isLast) {
        __threadfence();
        int v = (t < SCAN_G) ? g_bsum[t] : 0;
        sh[t] = v;
        __syncthreads();
        for (int off = 1; off < SCAN_B; off <<= 1) {
            int u = (t >= off) ? sh[t - off] : 0;
            __syncthreads();
            sh[t] += u;
            __syncthreads();
        }
        if (t < SCAN_G) g_boff[t] = (t == 0) ? 0 : sh[t - 1];
    }
}

__global__ void scan3_kernel() {
    __shared__ int sh[SCAN_B];
    int t = threadIdx.x;
    int i = blockIdx.x * SCAN_B + t;
    int d = (i < NN) ? node_deg(i) : 0;
    sh[t] = d;
    __syncthreads();
    for (int off = 1; off < SCAN_B; off <<= 1) {
        int v = (t >= off) ? sh[t - off] : 0;
        __syncthreads();
        sh[t] += v;
        __syncthreads();
    }
    if (i < NN) {
        int excl = g_boff[blockIdx.x] + sh[t] - d;
        g_rowptr[i] = excl;
        g_wr[i] = excl;
        if (i == NN - 1) g_rowptr[NN] = excl + d;
    }
}
__global__ void scatter_kernel(const int* __restrict__ edge_index) {
    int e = blockIdx.x * blockDim.x + threadIdx.x;
    if (e >= NE) return;
    int src = edge_index[e];
    int dst = edge_index[NE + e];
    int pos = atomicAdd(&g_wr[dst], 1);
    g_col[pos] = src;
}

// ---------------- layer-0 aggregation: pure count-based (no CSR!) ---------
__global__ __launch_bounds__(256) void aggregate0_kernel(
        const float* __restrict__ e1l, const float* __restrict__ e2l) {
    __shared__ float4 ht[9 * 32];
    __shared__ float4 se[(7 + 3) * 32];
    int tid = threadIdx.x;
    for (int i = tid; i < 9 * 32; i += 256) ht[i] = ((const float4*)g_htab)[i];
    for (int i = tid; i < 320; i += 256)
        se[i] = (i < 224) ? ((const float4*)e1l)[i] : ((const float4*)e2l)[i - 224];
    __syncthreads();

    int warp = tid >> 5;
    int lane = tid & 31;
    int v = blockIdx.x * 8 + warp;
    if (v >= NN) return;

    unsigned long long p1 = g_pk1[v];
    unsigned long long p2 = g_pk2[v];

    float4 acc = ht[g_ctab[v] * 32 + lane];
    float4 t4 = se[4 * 32 + lane];
    acc.x += t4.x; acc.y += t4.y; acc.z += t4.z; acc.w += t4.w;
    t4 = se[7 * 32 + lane];
    acc.x += t4.x; acc.y += t4.y; acc.z += t4.z; acc.w += t4.w;

#pragma unroll
    for (int t = 0; t < 7; t++) {
        int c = (int)((p1 >> (9 * t)) & 511ull);
        if (c) {
            float fc = (float)c;
            float4 ev = se[t * 32 + lane];
            acc.x += fc * ev.x; acc.y += fc * ev.y; acc.z += fc * ev.z; acc.w += fc * ev.w;
        }
    }
#pragma unroll
    for (int t = 0; t < 3; t++) {
        int c = (int)((p2 >> (6 * t)) & 63ull);
        if (c) {
            float fc = (float)c;
            float4 ev = se[(7 + t) * 32 + lane];
            acc.x += fc * ev.x; acc.y += fc * ev.y; acc.z += fc * ev.z; acc.w += fc * ev.w;
        }
    }
#pragma unroll
    for (int c = 0; c < 9; c++) {
        int k = (int)((p2 >> (18 + 5 * c)) & 31ull);
        if (k) {
            float fk = (float)k;
            float4 ev = ht[c * 32 + lane];
            acc.x += fk * ev.x; acc.y += fk * ev.y; acc.z += fk * ev.z; acc.w += fk * ev.w;
        }
    }
    uint16_t h0, h1, h2, h3, l0, l1, l2, l3;
    split_f16(acc.x, h0, l0);
    split_f16(acc.y, h1, l1);
    split_f16(acc.z, h2, l2);
    split_f16(acc.w, h3, l3);
    uint2 hv2, lv2;
    hv2.x = (uint32_t)h0 | ((uint32_t)h1 << 16);
    hv2.y = (uint32_t)h2 | ((uint32_t)h3 << 16);
    lv2.x = (uint32_t)l0 | ((uint32_t)l1 << 16);
    lv2.y = (uint32_t)l2 | ((uint32_t)l3 << 16);
    *(uint2*)(g_a1 + (size_t)v * 256 + lane * 4) = hv2;
    *(uint2*)(g_a1 + (size_t)v * 256 + 128 + lane * 4) = lv2;
}

// ---------------- layer-1 aggregation: fp16 gathers + fused BN+relu --------
__global__ __launch_bounds__(256) void aggregate1_kernel(
        const uint16_t* __restrict__ Hh,
        const float* __restrict__ e1l, const float* __restrict__ e2l,
        const float* __restrict__ gamma, const float* __restrict__ beta,
        const float* __restrict__ ssum, const float* __restrict__ ssq) {
    __shared__ float4 se[(7 + 3) * 32];
    for (int i = threadIdx.x; i < 320; i += 256)
        se[i] = (i < 224) ? ((const float4*)e1l)[i] : ((const float4*)e2l)[i - 224];
    __syncthreads();

    int tid = threadIdx.x;
    int warp = tid >> 5;
    int lane = tid & 31;
    int v = blockIdx.x * 8 + warp;
    if (v >= NN) return;

    int cc = lane * 4;
    float invn = 1.0f / (float)NN;
    float scl[4], sft[4];
#pragma unroll
    for (int k = 0; k < 4; k++) {
        float mu = ssum[cc + k] * invn;
        float var = ssq[cc + k] * invn - mu * mu;
        float rs = rsqrtf(var + BN_EPS);
        scl[k] = gamma[cc + k] * rs;
        sft[k] = beta[cc + k] - mu * scl[k];
    }

    auto cvt = [&](uint2 raw) -> float4 {
        float2 f0 = __half22float2(*reinterpret_cast<const __half2*>(&raw.x));
        float2 f1 = __half22float2(*reinterpret_cast<const __half2*>(&raw.y));
        float4 x;
        x.x = fmaxf(fmaf(f0.x, scl[0], sft[0]), 0.f);
        x.y = fmaxf(fmaf(f0.y, scl[1], sft[1]), 0.f);
        x.z = fmaxf(fmaf(f1.x, scl[2], sft[2]), 0.f);
        x.w = fmaxf(fmaf(f1.y, scl[3], sft[3]), 0.f);
        return x;
    };

    float4 acc = cvt(*(const uint2*)(Hh + (size_t)v * DD + lane * 4));
    float4 t4 = se[4 * 32 + lane];
    acc.x += t4.x; acc.y += t4.y; acc.z += t4.z; acc.w += t4.w;
    t4 = se[7 * 32 + lane];
    acc.x += t4.x; acc.y += t4.y; acc.z += t4.z; acc.w += t4.w;

    float4 acc2 = make_float4(0.f, 0.f, 0.f, 0.f);
    int beg = g_rowptr[v];
    int end = g_rowptr[v + 1];
    int j = beg;
    for (; j + 7 < end; j += 8) {
        uint2 raw[8];
#pragma unroll
        for (int q = 0; q < 8; q++)
            raw[q] = *(const uint2*)(Hh + (size_t)g_col[j + q] * DD + lane * 4);
#pragma unroll
        for (int q = 0; q < 8; q += 2) {
            float4 a0 = cvt(raw[q]);
            float4 a1 = cvt(raw[q + 1]);
            if (q & 2) {
                acc2.x += a0.x + a1.x; acc2.y += a0.y + a1.y;
                acc2.z += a0.z + a1.z; acc2.w += a0.w + a1.w;
            } else {
                acc.x += a0.x + a1.x; acc.y += a0.y + a1.y;
                acc.z += a0.z + a1.z; acc.w += a0.w + a1.w;
            }
        }
    }
    for (; j < end; j++) {
        float4 hv = cvt(*(const uint2*)(Hh + (size_t)g_col[j] * DD + lane * 4));
        acc.x += hv.x; acc.y += hv.y; acc.z += hv.z; acc.w += hv.w;
    }
    acc.x += acc2.x; acc.y += acc2.y; acc.z += acc2.z; acc.w += acc2.w;

    unsigned long long p1 = g_pk1[v];
    unsigned long long p2 = g_pk2[v];
#pragma unroll
    for (int t = 0; t < 7; t++) {
        int c = (int)((p1 >> (9 * t)) & 511ull);
        if (c) {
            float fc = (float)c;
            float4 ev = se[t * 32 + lane];
            acc.x += fc * ev.x; acc.y += fc * ev.y; acc.z += fc * ev.z; acc.w += fc * ev.w;
        }
    }
#pragma unroll
    for (int t = 0; t < 3; t++) {
        int c = (int)((p2 >> (6 * t)) & 63ull);
        if (c) {
            float fc = (float)c;
            float4 ev = se[(7 + t) * 32 + lane];
            acc.x += fc * ev.x; acc.y += fc * ev.y; acc.z += fc * ev.z; acc.w += fc * ev.w;
        }
    }
    uint16_t h0, h1, h2, h3, l0, l1, l2, l3;
    split_f16(acc.x, h0, l0);
    split_f16(acc.y, h1, l1);
    split_f16(acc.z, h2, l2);
    split_f16(acc.w, h3, l3);
    uint2 hv2, lv2;
    hv2.x = (uint32_t)h0 | ((uint32_t)h1 << 16);
    hv2.y = (uint32_t)h2 | ((uint32_t)h3 << 16);
    lv2.x = (uint32_t)l0 | ((uint32_t)l1 << 16);
    lv2.y = (uint32_t)l2 | ((uint32_t)l3 << 16);
    *(uint2*)(g_a1 + (size_t)v * 256 + lane * 4) = hv2;
    *(uint2*)(g_a1 + (size_t)v * 256 + 128 + lane * 4) = lv2;
}

// ---------------- warp-MMA GEMM (HMMA fp16, fp32 accum, 2-stage) ----------
template <int NC, int KA, int KB, bool G1, bool OUT16>
__global__ void __launch_bounds__(256)
gemm_mma_kernel(const uint16_t* __restrict__ A,
                const uint16_t* __restrict__ Bm,
                const float* __restrict__ bias,
                uint16_t* __restrict__ outHL,
                float* __restrict__ outF,
                uint16_t* __restrict__ outF16,
                float* __restrict__ statSum,
                float* __restrict__ statSq) {
    extern __shared__ char smem[];
    float* sBias = (float*)smem;
    char* Abuf = smem + 1024;
    char* Bbuf = smem + 1024 + 2 * 16384;
    const int tid = threadIdx.x;
    const int wid = tid >> 5;
    const int lane = tid & 31;
    const int m0 = blockIdx.x * 128;
    const int n0 = blockIdx.y * 128;
    const int wm = (wid >> 2) * 64;
    const int wn = (wid & 3) * 32;

    if (tid < 128) sBias[tid] = bias[n0 + tid];

    float acc[4][4][4];
#pragma unroll
    for (int i = 0; i < 4; i++)
#pragma unroll
        for (int j = 0; j < 4; j++)
#pragma unroll
            for (int k = 0; k < 4; k++) acc[i][j][k] = 0.f;

    auto loadChunk = [&](int c, int buf) {
        const uint16_t* Ag = A + (size_t)m0 * KA + c * 64;
        const uint16_t* Bg = Bm + (size_t)n0 * KB + c * 64;
        uint32_t ab = s2u(Abuf + buf * 16384);
        uint32_t bb = s2u(Bbuf + buf * 16384);
#pragma unroll
        for (int i = 0; i < 4; i++) {
            int idx = tid + i * 256;
            int r = idx >> 3, c16 = idx & 7;
            CP_A16(ab + SWZ(r * 128 + c16 * 16), Ag + (size_t)r * KA + c16 * 8);
        }
#pragma unroll
        for (int i = 0; i < 4; i++) {
            int idx = tid + i * 256;
            int r = idx >> 3, c16 = idx & 7;
            CP_A16(bb + SWZ(r * 128 + c16 * 16), Bg + (size_t)r * KB + c16 * 8);
        }
    };

    loadChunk(0, 0);
    CP_COMMIT();
    for (int c = 0; c < NC; c++) {
        int buf = c & 1;
        if (c + 1 < NC) {
            loadChunk(c + 1, buf ^ 1);
            CP_COMMIT();
            CP_WAIT(1);
        } else {
            CP_WAIT(0);
        }
        __syncthreads();
        uint32_t aBase = s2u(Abuf + buf * 16384);
        uint32_t bBase = s2u(Bbuf + buf * 16384);
#pragma unroll
        for (int ks = 0; ks < 4; ks++) {
            int k0b = ks * 32;
            uint32_t af[4][4];
#pragma unroll
            for (int mt = 0; mt < 4; mt++) {
                int row = wm + mt * 16 + (lane & 15);
                uint32_t addr = aBase + SWZ(row * 128 + k0b + ((lane >> 4) << 4));
                LDSM_X4(af[mt][0], af[mt][1], af[mt][2], af[mt][3], addr);
            }
            uint32_t bfr[4][2];
#pragma unroll
            for (int p = 0; p < 2; p++) {
                int g = lane >> 3;
                int nrow = wn + p * 16 + (lane & 7) + ((g >> 1) << 3);
                uint32_t addr = bBase + SWZ(nrow * 128 + k0b + ((g & 1) << 4));
                uint32_t r0, r1, r2, r3;
                LDSM_X4(r0, r1, r2, r3, addr);
                bfr[2 * p][0] = r0; bfr[2 * p][1] = r1;
                bfr[2 * p + 1][0] = r2; bfr[2 * p + 1][1] = r3;
            }
#pragma unroll
            for (int mt = 0; mt < 4; mt++)
#pragma unroll
                for (int nt = 0; nt < 4; nt++)
                    MMA16816(acc[mt][nt], af[mt], bfr[nt]);
        }
        __syncthreads();
    }

#pragma unroll
    for (int nt = 0; nt < 4; nt++) {
        int cl = wn + nt * 8 + 2 * (lane & 3);
        int cg = n0 + cl;
        float b0 = sBias[cl], b1 = sBias[cl + 1];
        float s0 = 0.f, s1 = 0.f, q0 = 0.f, q1 = 0.f;
#pragma unroll
        for (int mt = 0; mt < 4; mt++) {
#pragma unroll
            for (int h = 0; h < 2; h++) {
                int m = m0 + wm + mt * 16 + (lane >> 2) + h * 8;
                float v0 = acc[mt][nt][2 * h] + b0;
                float v1 = acc[mt][nt][2 * h + 1] + b1;
                if (G1) {
                    v0 = fmaxf(v0, 0.f);
                    v1 = fmaxf(v1, 0.f);
                    uint16_t h0, l0, h1, l1;
                    split_f16(v0, h0, l0);
                    split_f16(v1, h1, l1);
                    if (m >= NN) { h0 = l0 = h1 = l1 = 0; }
                    *(uint32_t*)(outHL + (size_t)m * 512 + cg) =
                        (uint32_t)h0 | ((uint32_t)h1 << 16);
                    *(uint32_t*)(outHL + (size_t)m * 512 + 256 + cg) =
                        (uint32_t)l0 | ((uint32_t)l1 << 16);
                } else {
                    if (m < NN) {
                        if (OUT16) {
                            __half2 hp = __floats2half2_rn(v0, v1);
                            *(uint32_t*)(outF16 + (size_t)m * 128 + cg) =
                                *reinterpret_cast<uint32_t*>(&hp);
                        } else {
                            float2 v; v.x = v0; v.y = v1;
                            *(float2*)(outF + (size_t)m * 128 + cg) = v;
                        }
                        s0 += v0; s1 += v1;
                        q0 += v0 * v0; q1 += v1 * v1;
                    }
                }
            }
        }
        if (!G1) {
#pragma unroll
            for (int off = 16; off >= 4; off >>= 1) {
                s0 += __shfl_down_sync(0xffffffff, s0, off);
                s1 += __shfl_down_sync(0xffffffff, s1, off);
                q0 += __shfl_down_sync(0xffffffff, q0, off);
                q1 += __shfl_down_sync(0xffffffff, q1, off);
            }
            if (lane < 4) {
                atomicAdd(&statSum[cg], s0);
                atomicAdd(&statSum[cg + 1], s1);
                atomicAdd(&statSq[cg], q0);
                atomicAdd(&statSq[cg + 1], q1);
            }
        }
    }
}

// ---------------- final BN apply ----------------
__global__ void bn_apply_kernel(const float* __restrict__ X,
                                const float* __restrict__ gamma,
                                const float* __restrict__ beta,
                                const float* __restrict__ ssum,
                                const float* __restrict__ ssq,
                                float* __restrict__ Y) {
    int idx = blockIdx.x * blockDim.x + threadIdx.x;
    if (idx >= NN * (DD / 4)) return;
    int v = idx >> 5;
    int c4 = idx & 31;
    int c = c4 * 4;
    float4 x = ((const float4*)(X + (size_t)v * DD))[c4];
    float invn = 1.0f / (float)NN;
    float o[4];
    float xi[4] = {x.x, x.y, x.z, x.w};
#pragma unroll
    for (int k = 0; k < 4; k++) {
        float mu = ssum[c + k] * invn;
        float var = ssq[c + k] * invn - mu * mu;
        float rs = rsqrtf(var + BN_EPS);
        o[k] = gamma[c + k] * (xi[k] - mu) * rs + beta[c + k];
    }
    ((float4*)(Y + (size_t)v * DD))[c4] = make_float4(o[0], o[1], o[2], o[3]);
}

// ---------------- launch ----------------
extern "C" void kernel_launch(void* const* d_in, const int* in_sizes, int n_in,
                              void* d_out, int out_size) {
    const int* x          = (const int*)d_in[0];
    const int* edge_index = (const int*)d_in[1];
    const int* edge_attr  = (const int*)d_in[2];
    const float* xemb1 = (const float*)d_in[4];
    const float* xemb2 = (const float*)d_in[5];
    const float* e1    = (const float*)d_in[6];
    const float* e2    = (const float*)d_in[7];
    const float* W1    = (const float*)d_in[8];
    const float* b1    = (const float*)d_in[9];
    const float* W2    = (const float*)d_in[10];
    const float* b2    = (const float*)d_in[11];
    const float* gamma = (const float*)d_in[12];
    const float* beta  = (const float*)d_in[13];
    float* out = (float*)d_out;

    float *p_h2, *p_sum, *p_sq;
    uint16_t *p_h2h, *p_a1, *p_a2, *p_b1, *p_b2;
    cudaGetSymbolAddress((void**)&p_h2,  g_h2);
    cudaGetSymbolAddress((void**)&p_h2h, g_h2h);
    cudaGetSymbolAddress((void**)&p_a1,  g_a1);
    cudaGetSymbolAddress((void**)&p_a2,  g_a2);
    cudaGetSymbolAddress((void**)&p_b1,  g_b1);
    cudaGetSymbolAddress((void**)&p_b2,  g_b2);
    cudaGetSymbolAddress((void**)&p_sum, g_colsum);
    cudaGetSymbolAddress((void**)&p_sq,  g_colsq);

    constexpr int SMEM_SZ = 1024 + 4 * 16384;   // 66560 (2-stage)
    cudaFuncSetAttribute(gemm_mma_kernel<4, 256, 256, true, false>,
                         cudaFuncAttributeMaxDynamicSharedMemorySize, SMEM_SZ);
    cudaFuncSetAttribute(gemm_mma_kernel<8, 512, 512, false, true>,
                         cudaFuncAttributeMaxDynamicSharedMemorySize, SMEM_SZ);
    cudaFuncSetAttribute(gemm_mma_kernel<8, 512, 512, false, false>,
                         cudaFuncAttributeMaxDynamicSharedMemorySize, SMEM_SZ);

    setup_kernel<<<(TT7 + 255) / 256, 256>>>(x, xemb1, xemb2, W1, W2);
    hist_kernel<<<(NE + 255) / 256, 256>>>(edge_index, edge_attr);
    scanA_kernel<<<SCAN_G, SCAN_B>>>();
    scan3_kernel<<<SCAN_G, SCAN_B>>>();
    scatter_kernel<<<(NE + 255) / 256, 256>>>(edge_index);

    for (int l = 0; l < 2; l++) {
        const float* e1l = e1 + (size_t)l * 7 * DD;
        const float* e2l = e2 + (size_t)l * 3 * DD;
        const float* b1l = b1 + (size_t)l * 2 * DD;
        const float* b2l = b2 + (size_t)l * DD;
        float* sumL = p_sum + l * DD;
        float* sqL  = p_sq + l * DD;
        uint16_t* b1w = p_b1 + (size_t)l * 65536;
        uint16_t* b2w = p_b2 + (size_t)l * 65536;

        if (l == 0) {
            aggregate0_kernel<<<(NN + 7) / 8, 256>>>(e1l, e2l);
        } else {
            aggregate1_kernel<<<(NN + 7) / 8, 256>>>(
                p_h2h, e1l, e2l, gamma, beta, p_sum, p_sq);
        }
        gemm_mma_kernel<4, 256, 256, true, false><<<dim3(MP / 128, 2), 256, SMEM_SZ>>>(
            p_a1, b1w, b1l, p_a2, nullptr, nullptr, nullptr, nullptr);
        if (l == 0) {
            gemm_mma_kernel<8, 512, 512, false, true><<<dim3(MP / 128, 1), 256, SMEM_SZ>>>(
                p_a2, b2w, b2l, nullptr, nullptr, p_h2h, sumL, sqL);
        } else {
            gemm_mma_kernel<8, 512, 512, false, false><<<dim3(MP / 128, 1), 256, SMEM_SZ>>>(
                p_a2, b2w, b2l, nullptr, p_h2, nullptr, sumL, sqL);
        }
    }
    bn_apply_kernel<<<(NN * 32 + 255) / 256, 256>>>(
        p_h2, gamma + DD, beta + DD, p_sum + DD, p_sq + DD, out);
}

// round 13
// speedup vs baseline: 2.5011x; 1.0353x over previous
#include <cuda_runtime.h>
#include <cuda_fp16.h>
#include <cstdint>

#define NN 50000
#define NE 800000
#define DD 128
#define MP 50048              // 391 * 128 padded rows
#define BN_EPS 1e-5f

#define SCAN_B 256
#define SCAN_G ((NN + SCAN_B - 1) / SCAN_B)   // 196

// ---------------- scratch (device globals) ----------------
__device__ float g_h2[NN * DD];               // layer-1 pre-BN output (fp32)
__device__ uint16_t g_h2h[(size_t)NN * DD];   // layer-0 pre-BN output (fp16)
__device__ uint16_t g_a1[(size_t)MP * 256];   // GEMM1 A fp16: [hi(128)|lo(128)]
__device__ uint16_t g_a2[(size_t)MP * 512];   // GEMM2 A fp16: [hi(256)|lo(256)]
__device__ uint16_t g_b1[2 * 256 * 256];      // GEMM1 B fp16 per layer: [n, hi|hi]
__device__ uint16_t g_b2[2 * 128 * 512];      // GEMM2 B fp16 per layer: [n, hi|hi]
__device__ uint8_t  g_ctab[NN];               // combined embedding index (0..8)
__device__ float    g_htab[9 * 128];          // 9 distinct node embeddings (fp32)
__device__ unsigned long long g_pk1[NN];      // cnt1: 7 fields x 9 bits
__device__ unsigned long long g_pk2[NN];      // cnt2: 3x6 bits | cnt3: 9x5 bits @18
__device__ int   g_rowptr[NN + 1];
__device__ int   g_wr[NN];
__device__ int   g_col[NE];
__device__ float g_colsum[2 * DD];
__device__ float g_colsq[2 * DD];
__device__ int   g_bsum[SCAN_G];
__device__ int   g_boff[SCAN_G];
__device__ unsigned int g_tick;

// ---------------- helpers ----------------
__device__ __forceinline__ uint32_t s2u(const void* p) {
    uint32_t a;
    asm("{ .reg .u64 t; cvta.to.shared.u64 t, %1; cvt.u32.u64 %0, t; }" : "=r"(a) : "l"(p));
    return a;
}
#define SWZ(x) ((x) ^ (((x) >> 3) & 0x70))

#define CP_A16(dst, src) \
    asm volatile("cp.async.cg.shared.global [%0], [%1], 16;" :: "r"(dst), "l"(src))
#define CP_COMMIT() asm volatile("cp.async.commit_group;")
#define CP_WAIT(n)  asm volatile("cp.async.wait_group %0;" :: "n"(n))

#define LDSM_X4(r0, r1, r2, r3, addr) \
    asm volatile("ldmatrix.sync.aligned.m8n8.x4.shared.b16 {%0,%1,%2,%3}, [%4];" \
        : "=r"(r0), "=r"(r1), "=r"(r2), "=r"(r3) : "r"(addr))
#define MMA16816(d, a, b) \
    asm volatile("mma.sync.aligned.m16n8k16.row.col.f32.f16.f16.f32 " \
        "{%0,%1,%2,%3}, {%4,%5,%6,%7}, {%8,%9}, {%0,%1,%2,%3};" \
        : "+f"((d)[0]), "+f"((d)[1]), "+f"((d)[2]), "+f"((d)[3]) \
        : "r"((a)[0]), "r"((a)[1]), "r"((a)[2]), "r"((a)[3]), \
          "r"((b)[0]), "r"((b)[1]))

__device__ __forceinline__ void split_f16(float v, uint16_t& hi, uint16_t& lo) {
    __half h = __float2half_rn(v);
    float rem = v - __half2float(h);
    __half l = __float2half_rn(rem);
    hi = __half_as_ushort(h);
    lo = __half_as_ushort(l);
}

// ---------------- setupA: prerequisites of hist/agg0 ----------------
#define UA0 (2 * NN)                      // pk1 + pk2 zero
#define UA1 (UA0 + 512)                   // BN stats
#define UA2 (UA1 + NN)                    // ctab
#define UA3 (UA2 + 9 * 128)               // htab
#define UA4 (UA3 + 1)                     // tick
__global__ void setupA_kernel(const int* __restrict__ x,
                              const float* __restrict__ xemb1,
                              const float* __restrict__ xemb2) {
    int i = blockIdx.x * blockDim.x + threadIdx.x;
    if (i >= UA4) return;
    if (i < UA0) {
        if (i < NN) g_pk1[i] = 0ull;
        else g_pk2[i - NN] = 0ull;
    } else if (i < UA1) {
        int j = i - UA0;
        if (j < 256) g_colsum[j] = 0.f;
        else g_colsq[j - 256] = 0.f;
    } else if (i < UA2) {
        int v = i - UA1;
        int c = x[2 * v] * 3 + x[2 * v + 1];
        g_ctab[v] = (uint8_t)min(c, 8);
    } else if (i < UA3) {
        int j = i - UA2;
        int c = j >> 7, d = j & 127;
        g_htab[j] = xemb1[(c / 3) * DD + d] + xemb2[(c % 3) * DD + d];
    } else {
        g_tick = 0u;
    }
}

// ---------------- setupB: prerequisites of GEMM1 only ----------------
#define UB0 ((MP - NN) * 256)             // a1 pad rows
#define UB1 (UB0 + 2 * 128 * 256)         // b1 builds
#define UB2 (UB1 + 2 * 256 * 128)         // b2 builds
__global__ void setupB_kernel(const float* __restrict__ W1,
                              const float* __restrict__ W2) {
    int i = blockIdx.x * blockDim.x + threadIdx.x;
    if (i >= UB2) return;
    if (i < UB0) {
        g_a1[(size_t)NN * 256 + i] = 0;
    } else if (i < UB1) {
        int j = i - UB0;
        int l = j >> 15;
        int r = j & 32767;          // k*256+n
        int k = r >> 8, n = r & 255;
        uint16_t hv = __half_as_ushort(__float2half_rn(W1[(size_t)l * 32768 + r]));
        g_b1[(size_t)l * 65536 + n * 256 + k]       = hv;
        g_b1[(size_t)l * 65536 + n * 256 + 128 + k] = hv;
    } else {
        int j = i - UB1;
        int l = j >> 15;
        int r = j & 32767;          // k*128+n
        int k = r >> 7, n = r & 127;
        uint16_t hv = __half_as_ushort(__float2half_rn(W2[(size_t)l * 32768 + r]));
        g_b2[(size_t)l * 65536 + n * 512 + k]       = hv;
        g_b2[(size_t)l * 65536 + n * 512 + 256 + k] = hv;
    }
}

// ---------------- histogram: 2 packed u64 atomics per edge ----------------
__global__ void hist_kernel(const int* __restrict__ edge_index,
                            const int* __restrict__ edge_attr) {
    int e = blockIdx.x * blockDim.x + threadIdx.x;
    if (e >= NE) return;
    int src = edge_index[e];
    int dst = edge_index[NE + e];
    int a0 = edge_attr[2 * e];
    int a1 = edge_attr[2 * e + 1];
    int c  = g_ctab[src];
    atomicAdd(&g_pk1[dst], 1ull << (9 * a0));
    atomicAdd(&g_pk2[dst], (1ull << (6 * a1)) + (1ull << (18 + 5 * c)));
}

__device__ __forceinline__ int node_deg(int i) {
    unsigned long long p = g_pk1[i];
    int d = 0;
#pragma unroll
    for (int t = 0; t < 7; t++) d += (int)((p >> (9 * t)) & 511ull);
    return d;
}

// ---------------- fused scan1+scan2 (last-block ticket) ----------------
__global__ void scanA_kernel() {
    __shared__ int sh[SCAN_B];
    __shared__ bool isLast;
    int t = threadIdx.x;
    int i = blockIdx.x * SCAN_B + t;
    sh[t] = (i < NN) ? node_deg(i) : 0;
    __syncthreads();
    for (int off = SCAN_B / 2; off > 0; off >>= 1) {
        if (t < off) sh[t] += sh[t + off];
        __syncthreads();
    }
    if (t == 0) {
        g_bsum[blockIdx.x] = sh[0];
        __threadfence();
        unsigned tk = atomicAdd(&g_tick, 1u);
        isLast = (tk == gridDim.x - 1);
    }
    __syncthreads();
    if (isLast) {
        __threadfence();
        int v = (t < SCAN_G) ? g_bsum[t] : 0;
        sh[t] = v;
        __syncthreads();
        for (int off = 1; off < SCAN_B; off <<= 1) {
            int u = (t >= off) ? sh[t - off] : 0;
            __syncthreads();
            sh[t] += u;
            __syncthreads();
        }
        if (t < SCAN_G) g_boff[t] = (t == 0) ? 0 : sh[t - 1];
    }
}

__global__ void scan3_kernel() {
    __shared__ int sh[SCAN_B];
    int t = threadIdx.x;
    int i = blockIdx.x * SCAN_B + t;
    int d = (i < NN) ? node_deg(i) : 0;
    sh[t] = d;
    __syncthreads();
    for (int off = 1; off < SCAN_B; off <<= 1) {
        int v = (t >= off) ? sh[t - off] : 0;
        __syncthreads();
        sh[t] += v;
        __syncthreads();
    }
    if (i < NN) {
        int excl = g_boff[blockIdx.x] + sh[t] - d;
        g_rowptr[i] = excl;
        g_wr[i] = excl;
        if (i == NN - 1) g_rowptr[NN] = excl + d;
    }
}
__global__ void scatter_kernel(const int* __restrict__ edge_index) {
    int e = blockIdx.x * blockDim.x + threadIdx.x;
    if (e >= NE) return;
    int src = edge_index[e];
    int dst = edge_index[NE + e];
    int pos = atomicAdd(&g_wr[dst], 1);
    g_col[pos] = src;
}

// ---------------- layer-0 aggregation: pure count-based (no CSR!) ---------
__global__ __launch_bounds__(256) void aggregate0_kernel(
        const float* __restrict__ e1l, const float* __restrict__ e2l) {
    __shared__ float4 ht[9 * 32];
    __shared__ float4 se[(7 + 3) * 32];
    int tid = threadIdx.x;
    for (int i = tid; i < 9 * 32; i += 256) ht[i] = ((const float4*)g_htab)[i];
    for (int i = tid; i < 320; i += 256)
        se[i] = (i < 224) ? ((const float4*)e1l)[i] : ((const float4*)e2l)[i - 224];
    __syncthreads();

    int warp = tid >> 5;
    int lane = tid & 31;
    int v = blockIdx.x * 8 + warp;
    if (v >= NN) return;

    unsigned long long p1 = g_pk1[v];
    unsigned long long p2 = g_pk2[v];

    float4 acc = ht[g_ctab[v] * 32 + lane];
    float4 t4 = se[4 * 32 + lane];
    acc.x += t4.x; acc.y += t4.y; acc.z += t4.z; acc.w += t4.w;
    t4 = se[7 * 32 + lane];
    acc.x += t4.x; acc.y += t4.y; acc.z += t4.z; acc.w += t4.w;

#pragma unroll
    for (int t = 0; t < 7; t++) {
        int c = (int)((p1 >> (9 * t)) & 511ull);
        if (c) {
            float fc = (float)c;
            float4 ev = se[t * 32 + lane];
            acc.x += fc * ev.x; acc.y += fc * ev.y; acc.z += fc * ev.z; acc.w += fc * ev.w;
        }
    }
#pragma unroll
    for (int t = 0; t < 3; t++) {
        int c = (int)((p2 >> (6 * t)) & 63ull);
        if (c) {
            float fc = (float)c;
            float4 ev = se[(7 + t) * 32 + lane];
            acc.x += fc * ev.x; acc.y += fc * ev.y; acc.z += fc * ev.z; acc.w += fc * ev.w;
        }
    }
#pragma unroll
    for (int c = 0; c < 9; c++) {
        int k = (int)((p2 >> (18 + 5 * c)) & 31ull);
        if (k) {
            float fk = (float)k;
            float4 ev = ht[c * 32 + lane];
            acc.x += fk * ev.x; acc.y += fk * ev.y; acc.z += fk * ev.z; acc.w += fk * ev.w;
        }
    }
    uint16_t h0, h1, h2, h3, l0, l1, l2, l3;
    split_f16(acc.x, h0, l0);
    split_f16(acc.y, h1, l1);
    split_f16(acc.z, h2, l2);
    split_f16(acc.w, h3, l3);
    uint2 hv2, lv2;
    hv2.x = (uint32_t)h0 | ((uint32_t)h1 << 16);
    hv2.y = (uint32_t)h2 | ((uint32_t)h3 << 16);
    lv2.x = (uint32_t)l0 | ((uint32_t)l1 << 16);
    lv2.y = (uint32_t)l2 | ((uint32_t)l3 << 16);
    *(uint2*)(g_a1 + (size_t)v * 256 + lane * 4) = hv2;
    *(uint2*)(g_a1 + (size_t)v * 256 + 128 + lane * 4) = lv2;
}

// ---------------- layer-1 aggregation: fp16 gathers + fused BN+relu --------
__global__ __launch_bounds__(256) void aggregate1_kernel(
        const uint16_t* __restrict__ Hh,
        const float* __restrict__ e1l, const float* __restrict__ e2l,
        const float* __restrict__ gamma, const float* __restrict__ beta,
        const float* __restrict__ ssum, const float* __restrict__ ssq) {
    __shared__ float4 se[(7 + 3) * 32];
    for (int i = threadIdx.x; i < 320; i += 256)
        se[i] = (i < 224) ? ((const float4*)e1l)[i] : ((const float4*)e2l)[i - 224];
    __syncthreads();

    int tid = threadIdx.x;
    int warp = tid >> 5;
    int lane = tid & 31;
    int v = blockIdx.x * 8 + warp;
    if (v >= NN) return;

    int cc = lane * 4;
    float invn = 1.0f / (float)NN;
    float scl[4], sft[4];
#pragma unroll
    for (int k = 0; k < 4; k++) {
        float mu = ssum[cc + k] * invn;
        float var = ssq[cc + k] * invn - mu * mu;
        float rs = rsqrtf(var + BN_EPS);
        scl[k] = gamma[cc + k] * rs;
        sft[k] = beta[cc + k] - mu * scl[k];
    }

    auto cvt = [&](uint2 raw) -> float4 {
        float2 f0 = __half22float2(*reinterpret_cast<const __half2*>(&raw.x));
        float2 f1 = __half22float2(*reinterpret_cast<const __half2*>(&raw.y));
        float4 x;
        x.x = fmaxf(fmaf(f0.x, scl[0], sft[0]), 0.f);
        x.y = fmaxf(fmaf(f0.y, scl[1], sft[1]), 0.f);
        x.z = fmaxf(fmaf(f1.x, scl[2], sft[2]), 0.f);
        x.w = fmaxf(fmaf(f1.y, scl[3], sft[3]), 0.f);
        return x;
    };

    float4 acc = cvt(*(const uint2*)(Hh + (size_t)v * DD + lane * 4));
    float4 t4 = se[4 * 32 + lane];
    acc.x += t4.x; acc.y += t4.y; acc.z += t4.z; acc.w += t4.w;
    t4 = se[7 * 32 + lane];
    acc.x += t4.x; acc.y += t4.y; acc.z += t4.z; acc.w += t4.w;

    float4 acc2 = make_float4(0.f, 0.f, 0.f, 0.f);
    int beg = g_rowptr[v];
    int end = g_rowptr[v + 1];
    int j = beg;
    for (; j + 7 < end; j += 8) {
        uint2 raw[8];
#pragma unroll
        for (int q = 0; q < 8; q++)
            raw[q] = *(const uint2*)(Hh + (size_t)g_col[j + q] * DD + lane * 4);
#pragma unroll
        for (int q = 0; q < 8; q += 2) {
            float4 a0 = cvt(raw[q]);
            float4 a1 = cvt(raw[q + 1]);
            if (q & 2) {
                acc2.x += a0.x + a1.x; acc2.y += a0.y + a1.y;
                acc2.z += a0.z + a1.z; acc2.w += a0.w + a1.w;
            } else {
                acc.x += a0.x + a1.x; acc.y += a0.y + a1.y;
                acc.z += a0.z + a1.z; acc.w += a0.w + a1.w;
            }
        }
    }
    for (; j < end; j++) {
        float4 hv = cvt(*(const uint2*)(Hh + (size_t)g_col[j] * DD + lane * 4));
        acc.x += hv.x; acc.y += hv.y; acc.z += hv.z; acc.w += hv.w;
    }
    acc.x += acc2.x; acc.y += acc2.y; acc.z += acc2.z; acc.w += acc2.w;

    unsigned long long p1 = g_pk1[v];
    unsigned long long p2 = g_pk2[v];
#pragma unroll
    for (int t = 0; t < 7; t++) {
        int c = (int)((p1 >> (9 * t)) & 511ull);
        if (c) {
            float fc = (float)c;
            float4 ev = se[t * 32 + lane];
            acc.x += fc * ev.x; acc.y += fc * ev.y; acc.z += fc * ev.z; acc.w += fc * ev.w;
        }
    }
#pragma unroll
    for (int t = 0; t < 3; t++) {
        int c = (int)((p2 >> (6 * t)) & 63ull);
        if (c) {
            float fc = (float)c;
            float4 ev = se[(7 + t) * 32 + lane];
            acc.x += fc * ev.x; acc.y += fc * ev.y; acc.z += fc * ev.z; acc.w += fc * ev.w;
        }
    }
    uint16_t h0, h1, h2, h3, l0, l1, l2, l3;
    split_f16(acc.x, h0, l0);
    split_f16(acc.y, h1, l1);
    split_f16(acc.z, h2, l2);
    split_f16(acc.w, h3, l3);
    uint2 hv2, lv2;
    hv2.x = (uint32_t)h0 | ((uint32_t)h1 << 16);
    hv2.y = (uint32_t)h2 | ((uint32_t)h3 << 16);
    lv2.x = (uint32_t)l0 | ((uint32_t)l1 << 16);
    lv2.y = (uint32_t)l2 | ((uint32_t)l3 << 16);
    *(uint2*)(g_a1 + (size_t)v * 256 + lane * 4) = hv2;
    *(uint2*)(g_a1 + (size_t)v * 256 + 128 + lane * 4) = lv2;
}

// ---------------- warp-MMA GEMM (HMMA fp16, fp32 accum, 2-stage) ----------
template <int NC, int KA, int KB, bool G1, bool OUT16>
__global__ void __launch_bounds__(256)
gemm_mma_kernel(const uint16_t* __restrict__ A,
                const uint16_t* __restrict__ Bm,
                const float* __restrict__ bias,
                uint16_t* __restrict__ outHL,
                float* __restrict__ outF,
                uint16_t* __restrict__ outF16,
                float* __restrict__ statSum,
                float* __restrict__ statSq) {
    extern __shared__ char smem[];
    float* sBias = (float*)smem;
    char* Abuf = smem + 1024;
    char* Bbuf = smem + 1024 + 2 * 16384;
    const int tid = threadIdx.x;
    const int wid = tid >> 5;
    const int lane = tid & 31;
    const int m0 = blockIdx.x * 128;
    const int n0 = blockIdx.y * 128;
    const int wm = (wid >> 2) * 64;
    const int wn = (wid & 3) * 32;

    if (tid < 128) sBias[tid] = bias[n0 + tid];

    float acc[4][4][4];
#pragma unroll
    for (int i = 0; i < 4; i++)
#pragma unroll
        for (int j = 0; j < 4; j++)
#pragma unroll
            for (int k = 0; k < 4; k++) acc[i][j][k] = 0.f;

    auto loadChunk = [&](int c, int buf) {
        const uint16_t* Ag = A + (size_t)m0 * KA + c * 64;
        const uint16_t* Bg = Bm + (size_t)n0 * KB + c * 64;
        uint32_t ab = s2u(Abuf + buf * 16384);
        uint32_t bb = s2u(Bbuf + buf * 16384);
#pragma unroll
        for (int i = 0; i < 4; i++) {
            int idx = tid + i * 256;
            int r = idx >> 3, c16 = idx & 7;
            CP_A16(ab + SWZ(r * 128 + c16 * 16), Ag + (size_t)r * KA + c16 * 8);
        }
#pragma unroll
        for (int i = 0; i < 4; i++) {
            int idx = tid + i * 256;
            int r = idx >> 3, c16 = idx & 7;
            CP_A16(bb + SWZ(r * 128 + c16 * 16), Bg + (size_t)r * KB + c16 * 8);
        }
    };

    loadChunk(0, 0);
    CP_COMMIT();
    for (int c = 0; c < NC; c++) {
        int buf = c & 1;
        if (c + 1 < NC) {
            loadChunk(c + 1, buf ^ 1);
            CP_COMMIT();
            CP_WAIT(1);
        } else {
            CP_WAIT(0);
        }
        __syncthreads();
        uint32_t aBase = s2u(Abuf + buf * 16384);
        uint32_t bBase = s2u(Bbuf + buf * 16384);
#pragma unroll
        for (int ks = 0; ks < 4; ks++) {
            int k0b = ks * 32;
            uint32_t af[4][4];
#pragma unroll
            for (int mt = 0; mt < 4; mt++) {
                int row = wm + mt * 16 + (lane & 15);
                uint32_t addr = aBase + SWZ(row * 128 + k0b + ((lane >> 4) << 4));
                LDSM_X4(af[mt][0], af[mt][1], af[mt][2], af[mt][3], addr);
            }
            uint32_t bfr[4][2];
#pragma unroll
            for (int p = 0; p < 2; p++) {
                int g = lane >> 3;
                int nrow = wn + p * 16 + (lane & 7) + ((g >> 1) << 3);
                uint32_t addr = bBase + SWZ(nrow * 128 + k0b + ((g & 1) << 4));
                uint32_t r0, r1, r2, r3;
                LDSM_X4(r0, r1, r2, r3, addr);
                bfr[2 * p][0] = r0; bfr[2 * p][1] = r1;
                bfr[2 * p + 1][0] = r2; bfr[2 * p + 1][1] = r3;
            }
#pragma unroll
            for (int mt = 0; mt < 4; mt++)
#pragma unroll
                for (int nt = 0; nt < 4; nt++)
                    MMA16816(acc[mt][nt], af[mt], bfr[nt]);
        }
        __syncthreads();
    }

#pragma unroll
    for (int nt = 0; nt < 4; nt++) {
        int cl = wn + nt * 8 + 2 * (lane & 3);
        int cg = n0 + cl;
        float b0 = sBias[cl], b1 = sBias[cl + 1];
        float s0 = 0.f, s1 = 0.f, q0 = 0.f, q1 = 0.f;
#pragma unroll
        for (int mt = 0; mt < 4; mt++) {
#pragma unroll
            for (int h = 0; h < 2; h++) {
                int m = m0 + wm + mt * 16 + (lane >> 2) + h * 8;
                float v0 = acc[mt][nt][2 * h] + b0;
                float v1 = acc[mt][nt][2 * h + 1] + b1;
                if (G1) {
                    v0 = fmaxf(v0, 0.f);
                    v1 = fmaxf(v1, 0.f);
                    uint16_t h0, l0, h1, l1;
                    split_f16(v0, h0, l0);
                    split_f16(v1, h1, l1);
                    if (m >= NN) { h0 = l0 = h1 = l1 = 0; }
                    *(uint32_t*)(outHL + (size_t)m * 512 + cg) =
                        (uint32_t)h0 | ((uint32_t)h1 << 16);
                    *(uint32_t*)(outHL + (size_t)m * 512 + 256 + cg) =
                        (uint32_t)l0 | ((uint32_t)l1 << 16);
                } else {
                    if (m < NN) {
                        if (OUT16) {
                            __half2 hp = __floats2half2_rn(v0, v1);
                            *(uint32_t*)(outF16 + (size_t)m * 128 + cg) =
                                *reinterpret_cast<uint32_t*>(&hp);
                        } else {
                            float2 v; v.x = v0; v.y = v1;
                            *(float2*)(outF + (size_t)m * 128 + cg) = v;
                        }
                        s0 += v0; s1 += v1;
                        q0 += v0 * v0; q1 += v1 * v1;
                    }
                }
            }
        }
        if (!G1) {
#pragma unroll
            for (int off = 16; off >= 4; off >>= 1) {
                s0 += __shfl_down_sync(0xffffffff, s0, off);
                s1 += __shfl_down_sync(0xffffffff, s1, off);
                q0 += __shfl_down_sync(0xffffffff, q0, off);
                q1 += __shfl_down_sync(0xffffffff, q1, off);
            }
            if (lane < 4) {
                atomicAdd(&statSum[cg], s0);
                atomicAdd(&statSum[cg + 1], s1);
                atomicAdd(&statSq[cg], q0);
                atomicAdd(&statSq[cg + 1], q1);
            }
        }
    }
}

// ---------------- final BN apply ----------------
__global__ void bn_apply_kernel(const float* __restrict__ X,
                                const float* __restrict__ gamma,
                                const float* __restrict__ beta,
                                const float* __restrict__ ssum,
                                const float* __restrict__ ssq,
                                float* __restrict__ Y) {
    int idx = blockIdx.x * blockDim.x + threadIdx.x;
    if (idx >= NN * (DD / 4)) return;
    int v = idx >> 5;
    int c4 = idx & 31;
    int c = c4 * 4;
    float4 x = ((const float4*)(X + (size_t)v * DD))[c4];
    float invn = 1.0f / (float)NN;
    float o[4];
    float xi[4] = {x.x, x.y, x.z, x.w};
#pragma unroll
    for (int k = 0; k < 4; k++) {
        float mu = ssum[c + k] * invn;
        float var = ssq[c + k] * invn - mu * mu;
        float rs = rsqrtf(var + BN_EPS);
        o[k] = gamma[c + k] * (xi[k] - mu) * rs + beta[c + k];
    }
    ((float4*)(Y + (size_t)v * DD))[c4] = make_float4(o[0], o[1], o[2], o[3]);
}

// ---------------- launch ----------------
extern "C" void kernel_launch(void* const* d_in, const int* in_sizes, int n_in,
                              void* d_out, int out_size) {
    const int* x          = (const int*)d_in[0];
    const int* edge_index = (const int*)d_in[1];
    const int* edge_attr  = (const int*)d_in[2];
    const float* xemb1 = (const float*)d_in[4];
    const float* xemb2 = (const float*)d_in[5];
    const float* e1    = (const float*)d_in[6];
    const float* e2    = (const float*)d_in[7];
    const float* W1    = (const float*)d_in[8];
    const float* b1    = (const float*)d_in[9];
    const float* W2    = (const float*)d_in[10];
    const float* b2    = (const float*)d_in[11];
    const float* gamma = (const float*)d_in[12];
    const float* beta  = (const float*)d_in[13];
    float* out = (float*)d_out;

    float *p_h2, *p_sum, *p_sq;
    uint16_t *p_h2h, *p_a1, *p_a2, *p_b1, *p_b2;
    cudaGetSymbolAddress((void**)&p_h2,  g_h2);
    cudaGetSymbolAddress((void**)&p_h2h, g_h2h);
    cudaGetSymbolAddress((void**)&p_a1,  g_a1);
    cudaGetSymbolAddress((void**)&p_a2,  g_a2);
    cudaGetSymbolAddress((void**)&p_b1,  g_b1);
    cudaGetSymbolAddress((void**)&p_b2,  g_b2);
    cudaGetSymbolAddress((void**)&p_sum, g_colsum);
    cudaGetSymbolAddress((void**)&p_sq,  g_colsq);

    constexpr int SMEM_SZ = 1024 + 4 * 16384;   // 66560 (2-stage)
    cudaFuncSetAttribute(gemm_mma_kernel<4, 256, 256, true, false>,
                         cudaFuncAttributeMaxDynamicSharedMemorySize, SMEM_SZ);
    cudaFuncSetAttribute(gemm_mma_kernel<8, 512, 512, false, true>,
                         cudaFuncAttributeMaxDynamicSharedMemorySize, SMEM_SZ);
    cudaFuncSetAttribute(gemm_mma_kernel<8, 512, 512, false, false>,
                         cudaFuncAttributeMaxDynamicSharedMemorySize, SMEM_SZ);

    // side streams + events (host resources; created once; capture-legal)
    static cudaStream_t sCSR = nullptr, sWB = nullptr;
    static cudaEvent_t evInit = nullptr, evHist = nullptr, evWB = nullptr, evCSR = nullptr;
    if (!sCSR) {
        cudaStreamCreateWithFlags(&sCSR, cudaStreamNonBlocking);
        cudaStreamCreateWithFlags(&sWB, cudaStreamNonBlocking);
        cudaEventCreateWithFlags(&evInit, cudaEventDisableTiming);
        cudaEventCreateWithFlags(&evHist, cudaEventDisableTiming);
        cudaEventCreateWithFlags(&evWB, cudaEventDisableTiming);
        cudaEventCreateWithFlags(&evCSR, cudaEventDisableTiming);
    }

    // fork point: weight-build stream starts immediately
    cudaEventRecord(evInit, 0);
    cudaStreamWaitEvent(sWB, evInit, 0);
    setupB_kernel<<<(UB2 + 255) / 256, 256, 0, sWB>>>(W1, W2);
    cudaEventRecord(evWB, sWB);

    // main chain: setupA -> hist
    setupA_kernel<<<(UA4 + 255) / 256, 256>>>(x, xemb1, xemb2);
    hist_kernel<<<(NE + 255) / 256, 256>>>(edge_index, edge_attr);
    cudaEventRecord(evHist, 0);

    // CSR chain on side stream (only needed by layer-1 aggregation)
    cudaStreamWaitEvent(sCSR, evHist, 0);
    scanA_kernel<<<SCAN_G, SCAN_B, 0, sCSR>>>();
    scan3_kernel<<<SCAN_G, SCAN_B, 0, sCSR>>>();
    scatter_kernel<<<(NE + 255) / 256, 256, 0, sCSR>>>(edge_index);
    cudaEventRecord(evCSR, sCSR);

    // layer 0 compute (overlaps CSR chain)
    aggregate0_kernel<<<(NN + 7) / 8, 256>>>(e1, e2);
    cudaStreamWaitEvent(0, evWB, 0);
    gemm_mma_kernel<4, 256, 256, true, false><<<dim3(MP / 128, 2), 256, SMEM_SZ>>>(
        p_a1, p_b1, b1, p_a2, nullptr, nullptr, nullptr, nullptr);
    gemm_mma_kernel<8, 512, 512, false, true><<<dim3(MP / 128, 1), 256, SMEM_SZ>>>(
        p_a2, p_b2, b2, nullptr, nullptr, p_h2h, p_sum, p_sq);

    // join CSR, then layer 1
    cudaStreamWaitEvent(0, evCSR, 0);
    aggregate1_kernel<<<(NN + 7) / 8, 256>>>(
        p_h2h, e1 + 7 * DD, e2 + 3 * DD, gamma, beta, p_sum, p_sq);
    gemm_mma_kernel<4, 256, 256, true, false><<<dim3(MP / 128, 2), 256, SMEM_SZ>>>(
        p_a1, p_b1 + 65536, b1 + 2 * DD, p_a2, nullptr, nullptr, nullptr, nullptr);
    gemm_mma_kernel<8, 512, 512, false, false><<<dim3(MP / 128, 1), 256, SMEM_SZ>>>(
        p_a2, p_b2 + 65536, b2 + DD, nullptr, p_h2, nullptr, p_sum + DD, p_sq + DD);

    bn_apply_kernel<<<(NN * 32 + 255) / 256, 256>>>(
        p_h2, gamma + DD, beta + DD, p_sum + DD, p_sq + DD, out);
}

// round 14
// speedup vs baseline: 2.8106x; 1.1238x over previous
#include <cuda_runtime.h>
#include <cuda_fp16.h>
#include <cstdint>

#define NN 50000
#define NE 800000
#define DD 128
#define MP 50048              // 391 * 128 padded rows
#define BN_EPS 1e-5f

#define SCAN_B 256
#define SCAN_G ((NN + SCAN_B - 1) / SCAN_B)   // 196

// ---------------- scratch (device globals) ----------------
__device__ float g_h2[NN * DD];               // layer-1 pre-BN output (fp32)
__device__ uint16_t g_h2h[(size_t)NN * DD];   // layer-0 pre-BN output (fp16)
__device__ uint16_t g_a1[(size_t)MP * 256];   // MLP A fp16: [hi(128)|lo(128)]
__device__ uint16_t g_b1[2 * 256 * 256];      // W1 fp16 per layer: [n, hi|hi]
__device__ uint16_t g_b2[2 * 128 * 512];      // W2 fp16 per layer: [n, k(256 used)]
__device__ uint8_t  g_ctab[NN];               // combined embedding index (0..8)
__device__ float    g_htab[9 * 128];          // 9 distinct node embeddings (fp32)
__device__ unsigned long long g_pk1[NN];      // cnt1: 7 fields x 9 bits
__device__ unsigned long long g_pk2[NN];      // cnt2: 3x6 bits | cnt3: 9x5 bits @18
__device__ int   g_rowptr[NN + 1];
__device__ int   g_wr[NN];
__device__ int   g_col[NE];
__device__ float g_colsum[2 * DD];
__device__ float g_colsq[2 * DD];
__device__ int   g_bsum[SCAN_G];
__device__ int   g_boff[SCAN_G];
__device__ unsigned int g_tick;
__device__ unsigned int g_flag;

// ---------------- helpers ----------------
__device__ __forceinline__ uint32_t s2u(const void* p) {
    uint32_t a;
    asm("{ .reg .u64 t; cvta.to.shared.u64 t, %1; cvt.u32.u64 %0, t; }" : "=r"(a) : "l"(p));
    return a;
}
#define SWZ(x) ((x) ^ (((x) >> 3) & 0x70))

#define CP_A16(dst, src) \
    asm volatile("cp.async.cg.shared.global [%0], [%1], 16;" :: "r"(dst), "l"(src))
#define CP_COMMIT() asm volatile("cp.async.commit_group;")
#define CP_WAIT(n)  asm volatile("cp.async.wait_group %0;" :: "n"(n))

#define LDSM_X4(r0, r1, r2, r3, addr) \
    asm volatile("ldmatrix.sync.aligned.m8n8.x4.shared.b16 {%0,%1,%2,%3}, [%4];" \
        : "=r"(r0), "=r"(r1), "=r"(r2), "=r"(r3) : "r"(addr))
#define MMA16816(d, a, b) \
    asm volatile("mma.sync.aligned.m16n8k16.row.col.f32.f16.f16.f32 " \
        "{%0,%1,%2,%3}, {%4,%5,%6,%7}, {%8,%9}, {%0,%1,%2,%3};" \
        : "+f"((d)[0]), "+f"((d)[1]), "+f"((d)[2]), "+f"((d)[3]) \
        : "r"((a)[0]), "r"((a)[1]), "r"((a)[2]), "r"((a)[3]), \
          "r"((b)[0]), "r"((b)[1]))

__device__ __forceinline__ void split_f16(float v, uint16_t& hi, uint16_t& lo) {
    __half h = __float2half_rn(v);
    float rem = v - __half2float(h);
    __half l = __float2half_rn(rem);
    hi = __half_as_ushort(h);
    lo = __half_as_ushort(l);
}

// ---------------- setupA: prerequisites of hist/agg0 ----------------
#define UA0 (2 * NN)                      // pk1 + pk2 zero
#define UA1 (UA0 + 512)                   // BN stats
#define UA2 (UA1 + NN)                    // ctab
#define UA3 (UA2 + 9 * 128)               // htab
#define UA4 (UA3 + 2)                     // tick + flag
__global__ void setupA_kernel(const int* __restrict__ x,
                              const float* __restrict__ xemb1,
                              const float* __restrict__ xemb2) {
    int i = blockIdx.x * blockDim.x + threadIdx.x;
    if (i >= UA4) return;
    if (i < UA0) {
        if (i < NN) g_pk1[i] = 0ull;
        else g_pk2[i - NN] = 0ull;
    } else if (i < UA1) {
        int j = i - UA0;
        if (j < 256) g_colsum[j] = 0.f;
        else g_colsq[j - 256] = 0.f;
    } else if (i < UA2) {
        int v = i - UA1;
        int c = x[2 * v] * 3 + x[2 * v + 1];
        g_ctab[v] = (uint8_t)min(c, 8);
    } else if (i < UA3) {
        int j = i - UA2;
        int c = j >> 7, d = j & 127;
        g_htab[j] = xemb1[(c / 3) * DD + d] + xemb2[(c % 3) * DD + d];
    } else if (i == UA3) {
        g_tick = 0u;
    } else {
        g_flag = 0u;
    }
}

// ---------------- setupB: fp16 weight builds ----------------
#define UB0 (2 * 128 * 256)               // b1 builds
#define UB1 (UB0 + 2 * 256 * 128)         // b2 builds
__global__ void setupB_kernel(const float* __restrict__ W1,
                              const float* __restrict__ W2) {
    int i = blockIdx.x * blockDim.x + threadIdx.x;
    if (i >= UB1) return;
    if (i < UB0) {
        int l = i >> 15;
        int r = i & 32767;          // k*256+n
        int k = r >> 8, n = r & 255;
        uint16_t hv = __half_as_ushort(__float2half_rn(W1[(size_t)l * 32768 + r]));
        g_b1[(size_t)l * 65536 + n * 256 + k]       = hv;
        g_b1[(size_t)l * 65536 + n * 256 + 128 + k] = hv;
    } else {
        int j = i - UB0;
        int l = j >> 15;
        int r = j & 32767;          // k*128+n
        int k = r >> 7, n = r & 127;
        uint16_t hv = __half_as_ushort(__float2half_rn(W2[(size_t)l * 32768 + r]));
        g_b2[(size_t)l * 65536 + n * 512 + k] = hv;
    }
}

// ---------------- histogram: 2 packed u64 atomics per edge ----------------
__global__ void hist_kernel(const int* __restrict__ edge_index,
                            const int* __restrict__ edge_attr) {
    int e = blockIdx.x * blockDim.x + threadIdx.x;
    if (e >= NE) return;
    int src = edge_index[e];
    int dst = edge_index[NE + e];
    int a0 = edge_attr[2 * e];
    int a1 = edge_attr[2 * e + 1];
    int c  = g_ctab[src];
    atomicAdd(&g_pk1[dst], 1ull << (9 * a0));
    atomicAdd(&g_pk2[dst], (1ull << (6 * a1)) + (1ull << (18 + 5 * c)));
}

__device__ __forceinline__ int node_deg(int i) {
    unsigned long long p = g_pk1[i];
    int d = 0;
#pragma unroll
    for (int t = 0; t < 7; t++) d += (int)((p >> (9 * t)) & 511ull);
    return d;
}

// ---------------- single-kernel CSR scan (ticket + flag release) ----------
__global__ void scanF_kernel() {
    __shared__ int sh[SCAN_B];
    __shared__ bool lastBlk;
    int t = threadIdx.x;
    int i = blockIdx.x * SCAN_B + t;
    int d = (i < NN) ? node_deg(i) : 0;
    sh[t] = d;
    __syncthreads();
    for (int off = SCAN_B / 2; off > 0; off >>= 1) {
        if (t < off) sh[t] += sh[t + off];
        __syncthreads();
    }
    if (t == 0) {
        g_bsum[blockIdx.x] = sh[0];
        __threadfence();
        unsigned tk = atomicAdd(&g_tick, 1u);
        lastBlk = (tk == gridDim.x - 1);
    }
    __syncthreads();
    if (lastBlk) {
        __threadfence();
        int v = (t < SCAN_G) ? g_bsum[t] : 0;
        sh[t] = v;
        __syncthreads();
        for (int off = 1; off < SCAN_B; off <<= 1) {
            int u = (t >= off) ? sh[t - off] : 0;
            __syncthreads();
            sh[t] += u;
            __syncthreads();
        }
        if (t < SCAN_G) g_boff[t] = (t == 0) ? 0 : sh[t - 1];
        __threadfence();
        __syncthreads();
        if (t == 0) atomicExch(&g_flag, 1u);
    }
    if (t == 0) {
        while (atomicAdd(&g_flag, 0u) == 0u) {}
    }
    __syncthreads();
    __threadfence();
    // final phase: local inclusive scan + block offset
    sh[t] = d;
    __syncthreads();
    for (int off = 1; off < SCAN_B; off <<= 1) {
        int v = (t >= off) ? sh[t - off] : 0;
        __syncthreads();
        sh[t] += v;
        __syncthreads();
    }
    if (i < NN) {
        int excl = g_boff[blockIdx.x] + sh[t] - d;
        g_rowptr[i] = excl;
        g_wr[i] = excl;
        if (i == NN - 1) g_rowptr[NN] = excl + d;
    }
}

__global__ void scatter_kernel(const int* __restrict__ edge_index) {
    int e = blockIdx.x * blockDim.x + threadIdx.x;
    if (e >= NE) return;
    int src = edge_index[e];
    int dst = edge_index[NE + e];
    int pos = atomicAdd(&g_wr[dst], 1);
    g_col[pos] = src;
}

// ---------------- layer-0 aggregation: pure count-based ----------
__global__ __launch_bounds__(256) void aggregate0_kernel(
        const float* __restrict__ e1l, const float* __restrict__ e2l) {
    __shared__ float4 ht[9 * 32];
    __shared__ float4 se[(7 + 3) * 32];
    int tid = threadIdx.x;
    for (int i = tid; i < 9 * 32; i += 256) ht[i] = ((const float4*)g_htab)[i];
    for (int i = tid; i < 320; i += 256)
        se[i] = (i < 224) ? ((const float4*)e1l)[i] : ((const float4*)e2l)[i - 224];
    __syncthreads();

    int warp = tid >> 5;
    int lane = tid & 31;
    int v = blockIdx.x * 8 + warp;
    if (v >= NN) return;

    unsigned long long p1 = g_pk1[v];
    unsigned long long p2 = g_pk2[v];

    float4 acc = ht[g_ctab[v] * 32 + lane];
    float4 t4 = se[4 * 32 + lane];
    acc.x += t4.x; acc.y += t4.y; acc.z += t4.z; acc.w += t4.w;
    t4 = se[7 * 32 + lane];
    acc.x += t4.x; acc.y += t4.y; acc.z += t4.z; acc.w += t4.w;

#pragma unroll
    for (int t = 0; t < 7; t++) {
        int c = (int)((p1 >> (9 * t)) & 511ull);
        if (c) {
            float fc = (float)c;
            float4 ev = se[t * 32 + lane];
            acc.x += fc * ev.x; acc.y += fc * ev.y; acc.z += fc * ev.z; acc.w += fc * ev.w;
        }
    }
#pragma unroll
    for (int t = 0; t < 3; t++) {
        int c = (int)((p2 >> (6 * t)) & 63ull);
        if (c) {
            float fc = (float)c;
            float4 ev = se[(7 + t) * 32 + lane];
            acc.x += fc * ev.x; acc.y += fc * ev.y; acc.z += fc * ev.z; acc.w += fc * ev.w;
        }
    }
#pragma unroll
    for (int c = 0; c < 9; c++) {
        int k = (int)((p2 >> (18 + 5 * c)) & 31ull);
        if (k) {
            float fk = (float)k;
            float4 ev = ht[c * 32 + lane];
            acc.x += fk * ev.x; acc.y += fk * ev.y; acc.z += fk * ev.z; acc.w += fk * ev.w;
        }
    }
    uint16_t h0, h1, h2, h3, l0, l1, l2, l3;
    split_f16(acc.x, h0, l0);
    split_f16(acc.y, h1, l1);
    split_f16(acc.z, h2, l2);
    split_f16(acc.w, h3, l3);
    uint2 hv2, lv2;
    hv2.x = (uint32_t)h0 | ((uint32_t)h1 << 16);
    hv2.y = (uint32_t)h2 | ((uint32_t)h3 << 16);
    lv2.x = (uint32_t)l0 | ((uint32_t)l1 << 16);
    lv2.y = (uint32_t)l2 | ((uint32_t)l3 << 16);
    *(uint2*)(g_a1 + (size_t)v * 256 + lane * 4) = hv2;
    *(uint2*)(g_a1 + (size_t)v * 256 + 128 + lane * 4) = lv2;
}

// ---------------- layer-1 aggregation: fp16 gathers + fused BN+relu --------
__global__ __launch_bounds__(256) void aggregate1_kernel(
        const uint16_t* __restrict__ Hh,
        const float* __restrict__ e1l, const float* __restrict__ e2l,
        const float* __restrict__ gamma, const float* __restrict__ beta,
        const float* __restrict__ ssum, const float* __restrict__ ssq) {
    __shared__ float4 se[(7 + 3) * 32];
    for (int i = threadIdx.x; i < 320; i += 256)
        se[i] = (i < 224) ? ((const float4*)e1l)[i] : ((const float4*)e2l)[i - 224];
    __syncthreads();

    int tid = threadIdx.x;
    int warp = tid >> 5;
    int lane = tid & 31;
    int v = blockIdx.x * 8 + warp;
    if (v >= NN) return;

    int cc = lane * 4;
    float invn = 1.0f / (float)NN;
    float scl[4], sft[4];
#pragma unroll
    for (int k = 0; k < 4; k++) {
        float mu = ssum[cc + k] * invn;
        float var = ssq[cc + k] * invn - mu * mu;
        float rs = rsqrtf(var + BN_EPS);
        scl[k] = gamma[cc + k] * rs;
        sft[k] = beta[cc + k] - mu * scl[k];
    }

    auto cvt = [&](uint2 raw) -> float4 {
        float2 f0 = __half22float2(*reinterpret_cast<const __half2*>(&raw.x));
        float2 f1 = __half22float2(*reinterpret_cast<const __half2*>(&raw.y));
        float4 x;
        x.x = fmaxf(fmaf(f0.x, scl[0], sft[0]), 0.f);
        x.y = fmaxf(fmaf(f0.y, scl[1], sft[1]), 0.f);
        x.z = fmaxf(fmaf(f1.x, scl[2], sft[2]), 0.f);
        x.w = fmaxf(fmaf(f1.y, scl[3], sft[3]), 0.f);
        return x;
    };

    float4 acc = cvt(*(const uint2*)(Hh + (size_t)v * DD + lane * 4));
    float4 t4 = se[4 * 32 + lane];
    acc.x += t4.x; acc.y += t4.y; acc.z += t4.z; acc.w += t4.w;
    t4 = se[7 * 32 + lane];
    acc.x += t4.x; acc.y += t4.y; acc.z += t4.z; acc.w += t4.w;

    float4 acc2 = make_float4(0.f, 0.f, 0.f, 0.f);
    int beg = g_rowptr[v];
    int end = g_rowptr[v + 1];
    int j = beg;
    for (; j + 7 < end; j += 8) {
        uint2 raw[8];
#pragma unroll
        for (int q = 0; q < 8; q++)
            raw[q] = *(const uint2*)(Hh + (size_t)g_col[j + q] * DD + lane * 4);
#pragma unroll
        for (int q = 0; q < 8; q += 2) {
            float4 a0 = cvt(raw[q]);
            float4 a1 = cvt(raw[q + 1]);
            if (q & 2) {
                acc2.x += a0.x + a1.x; acc2.y += a0.y + a1.y;
                acc2.z += a0.z + a1.z; acc2.w += a0.w + a1.w;
            } else {
                acc.x += a0.x + a1.x; acc.y += a0.y + a1.y;
                acc.z += a0.z + a1.z; acc.w += a0.w + a1.w;
            }
        }
    }
    for (; j < end; j++) {
        float4 hv = cvt(*(const uint2*)(Hh + (size_t)g_col[j] * DD + lane * 4));
        acc.x += hv.x; acc.y += hv.y; acc.z += hv.z; acc.w += hv.w;
    }
    acc.x += acc2.x; acc.y += acc2.y; acc.z += acc2.z; acc.w += acc2.w;

    unsigned long long p1 = g_pk1[v];
    unsigned long long p2 = g_pk2[v];
#pragma unroll
    for (int t = 0; t < 7; t++) {
        int c = (int)((p1 >> (9 * t)) & 511ull);
        if (c) {
            float fc = (float)c;
            float4 ev = se[t * 32 + lane];
            acc.x += fc * ev.x; acc.y += fc * ev.y; acc.z += fc * ev.z; acc.w += fc * ev.w;
        }
    }
#pragma unroll
    for (int t = 0; t < 3; t++) {
        int c = (int)((p2 >> (6 * t)) & 63ull);
        if (c) {
            float fc = (float)c;
            float4 ev = se[(7 + t) * 32 + lane];
            acc.x += fc * ev.x; acc.y += fc * ev.y; acc.z += fc * ev.z; acc.w += fc * ev.w;
        }
    }
    uint16_t h0, h1, h2, h3, l0, l1, l2, l3;
    split_f16(acc.x, h0, l0);
    split_f16(acc.y, h1, l1);
    split_f16(acc.z, h2, l2);
    split_f16(acc.w, h3, l3);
    uint2 hv2, lv2;
    hv2.x = (uint32_t)h0 | ((uint32_t)h1 << 16);
    hv2.y = (uint32_t)h2 | ((uint32_t)h3 << 16);
    lv2.x = (uint32_t)l0 | ((uint32_t)l1 << 16);
    lv2.y = (uint32_t)l2 | ((uint32_t)l3 << 16);
    *(uint2*)(g_a1 + (size_t)v * 256 + lane * 4) = hv2;
    *(uint2*)(g_a1 + (size_t)v * 256 + 128 + lane * 4) = lv2;
}

// ---------------- fused MLP: mid = relu(A x W1 + b1); out = mid x W2 + b2 --
// A [MP,256] fp16 (hi|lo). B1 [256n, 256k] (hi|hi dup). B2 [128n, 512k] (cols
// [0,256) used; each B2 chunk serves both hi and lo mid tiles).
// mid kept in smem as 8 SW128 tiles of [128,64] fp16 (hi 0..3, lo 4..7).
template <bool OUT16>
__global__ void __launch_bounds__(256, 1)
mlp_fused_kernel(const uint16_t* __restrict__ A,
                 const uint16_t* __restrict__ B1m,
                 const uint16_t* __restrict__ B2m,
                 const float* __restrict__ bias1,
                 const float* __restrict__ bias2,
                 float* __restrict__ outF,
                 uint16_t* __restrict__ outF16,
                 float* __restrict__ statSum,
                 float* __restrict__ statSq) {
    extern __shared__ char smem[];
    float* sB1 = (float*)smem;                   // 256 f
    float* sB2 = (float*)(smem + 1024);          // 128 f
    char* scrA = smem + 2048;                    // 2 x 16KB (ph1 A / ph2 B2)
    char* scrB = smem + 2048 + 32768;            // 32KB (ph1 B1, single buf)
    char* mid  = smem + 67584;                   // 8 x 16KB
    const int tid = threadIdx.x;
    const int wid = tid >> 5;
    const int lane = tid & 31;
    const int m0 = blockIdx.x * 128;
    const int wm = (wid >> 2) * 64;
    const int wn2 = (wid & 3) * 64;              // phase 1 (N=256)
    const int wn3 = (wid & 3) * 32;              // phase 2 (N=128)

    sB1[tid] = bias1[tid];
    if (tid < 128) sB2[tid] = bias2[tid];

    // ================= phase 1 =================
    float acc1[4][8][4];
#pragma unroll
    for (int i = 0; i < 4; i++)
#pragma unroll
        for (int j = 0; j < 8; j++)
#pragma unroll
            for (int k = 0; k < 4; k++) acc1[i][j][k] = 0.f;

    auto loadA1 = [&](int c, int buf) {
        const uint16_t* Ag = A + (size_t)m0 * 256 + c * 64;
        uint32_t ab = s2u(scrA + buf * 16384);
#pragma unroll
        for (int i = 0; i < 4; i++) {
            int idx = tid + i * 256;
            int r = idx >> 3, u = idx & 7;
            CP_A16(ab + SWZ(r * 128 + u * 16), Ag + (size_t)r * 256 + u * 8);
        }
    };
    auto loadB1c = [&](int c) {
        const uint16_t* Bg = B1m + c * 64;
        uint32_t bb = s2u(scrB);
#pragma unroll
        for (int i = 0; i < 8; i++) {
            int idx = tid + i * 256;
            int r = idx >> 3, u = idx & 7;
            CP_A16(bb + SWZ(r * 128 + u * 16), Bg + (size_t)r * 256 + u * 8);
        }
    };

    loadA1(0, 0); CP_COMMIT();
    for (int c = 0; c < 4; c++) {
        int buf = c & 1;
        loadB1c(c); CP_COMMIT();
        if (c < 3) { loadA1(c + 1, buf ^ 1); CP_COMMIT(); CP_WAIT(1); }
        else CP_WAIT(0);
        __syncthreads();
        uint32_t aBase = s2u(scrA + buf * 16384);
        uint32_t bBase = s2u(scrB);
#pragma unroll
        for (int ks = 0; ks < 4; ks++) {
            int k0b = ks * 32;
            uint32_t af[4][4];
#pragma unroll
            for (int mt = 0; mt < 4; mt++) {
                int row = wm + mt * 16 + (lane & 15);
                LDSM_X4(af[mt][0], af[mt][1], af[mt][2], af[mt][3],
                        aBase + SWZ(row * 128 + k0b + ((lane >> 4) << 4)));
            }
            uint32_t bfr[8][2];
#pragma unroll
            for (int p = 0; p < 4; p++) {
                int g = lane >> 3;
                int nrow = wn2 + p * 16 + (lane & 7) + ((g >> 1) << 3);
                uint32_t r0, r1, r2, r3;
                LDSM_X4(r0, r1, r2, r3, bBase + SWZ(nrow * 128 + k0b + ((g & 1) << 4)));
                bfr[2 * p][0] = r0; bfr[2 * p][1] = r1;
                bfr[2 * p + 1][0] = r2; bfr[2 * p + 1][1] = r3;
            }
#pragma unroll
            for (int mt = 0; mt < 4; mt++)
#pragma unroll
                for (int nt = 0; nt < 8; nt++)
                    MMA16816(acc1[mt][nt], af[mt], bfr[nt]);
        }
        __syncthreads();
    }

    // phase-1 epilogue: bias + relu + fp16 split -> mid tiles
#pragma unroll
    for (int nt = 0; nt < 8; nt++) {
        int cl = wn2 + nt * 8 + 2 * (lane & 3);   // 0..255
        float b0 = sB1[cl], b1v = sB1[cl + 1];
        int th = cl >> 6;                          // hi tile 0..3
        int ln2 = (cl & 63) * 2;                   // byte offset in 128B row
#pragma unroll
        for (int mt = 0; mt < 4; mt++) {
#pragma unroll
            for (int h = 0; h < 2; h++) {
                int m = wm + mt * 16 + (lane >> 2) + h * 8;   // local row
                float v0 = fmaxf(acc1[mt][nt][2 * h] + b0, 0.f);
                float v1 = fmaxf(acc1[mt][nt][2 * h + 1] + b1v, 0.f);
                uint16_t h0, l0, h1, l1;
                split_f16(v0, h0, l0);
                split_f16(v1, h1, l1);
                *(uint32_t*)(mid + th * 16384 + SWZ(m * 128 + ln2)) =
                    (uint32_t)h0 | ((uint32_t)h1 << 16);
                *(uint32_t*)(mid + (4 + th) * 16384 + SWZ(m * 128 + ln2)) =
                    (uint32_t)l0 | ((uint32_t)l1 << 16);
            }
        }
    }
    __syncthreads();

    // ================= phase 2 =================
    float acc2[4][4][4];
#pragma unroll
    for (int i = 0; i < 4; i++)
#pragma unroll
        for (int j = 0; j < 4; j++)
#pragma unroll
            for (int k = 0; k < 4; k++) acc2[i][j][k] = 0.f;

    auto loadB2c = [&](int c, int buf) {
        const uint16_t* Bg = B2m + c * 64;
        uint32_t bb = s2u(scrA + buf * 16384);
#pragma unroll
        for (int i = 0; i < 4; i++) {
            int idx = tid + i * 256;
            int r = idx >> 3, u = idx & 7;
            CP_A16(bb + SWZ(r * 128 + u * 16), Bg + (size_t)r * 512 + u * 8);
        }
    };

    loadB2c(0, 0); CP_COMMIT();
    for (int c = 0; c < 4; c++) {
        int buf = c & 1;
        if (c < 3) { loadB2c(c + 1, buf ^ 1); CP_COMMIT(); CP_WAIT(1); }
        else CP_WAIT(0);
        __syncthreads();
        uint32_t bBase = s2u(scrA + buf * 16384);
#pragma unroll
        for (int part = 0; part < 2; part++) {
            uint32_t aBase = s2u(mid + (part * 4 + c) * 16384);
#pragma unroll
            for (int ks = 0; ks < 4; ks++) {
                int k0b = ks * 32;
                uint32_t af[4][4];
#pragma unroll
                for (int mt = 0; mt < 4; mt++) {
                    int row = wm + mt * 16 + (lane & 15);
                    LDSM_X4(af[mt][0], af[mt][1], af[mt][2], af[mt][3],
                            aBase + SWZ(row * 128 + k0b + ((lane >> 4) << 4)));
                }
                uint32_t bfr[4][2];
#pragma unroll
                for (int p = 0; p < 2; p++) {
                    int g = lane >> 3;
                    int nrow = wn3 + p * 16 + (lane & 7) + ((g >> 1) << 3);
                    uint32_t r0, r1, r2, r3;
                    LDSM_X4(r0, r1, r2, r3,
                            bBase + SWZ(nrow * 128 + k0b + ((g & 1) << 4)));
                    bfr[2 * p][0] = r0; bfr[2 * p][1] = r1;
                    bfr[2 * p + 1][0] = r2; bfr[2 * p + 1][1] = r3;
                }
#pragma unroll
                for (int mt = 0; mt < 4; mt++)
#pragma unroll
                    for (int nt = 0; nt < 4; nt++)
                        MMA16816(acc2[mt][nt], af[mt], bfr[nt]);
            }
        }
        __syncthreads();
    }

    // phase-2 epilogue: bias + store + fused BN stats
#pragma unroll
    for (int nt = 0; nt < 4; nt++) {
        int cl = wn3 + nt * 8 + 2 * (lane & 3);
        float b0 = sB2[cl], b1v = sB2[cl + 1];
        float s0 = 0.f, s1 = 0.f, q0 = 0.f, q1 = 0.f;
#pragma unroll
        for (int mt = 0; mt < 4; mt++) {
#pragma unroll
            for (int h = 0; h < 2; h++) {
                int m = m0 + wm + mt * 16 + (lane >> 2) + h * 8;
                float v0 = acc2[mt][nt][2 * h] + b0;
                float v1 = acc2[mt][nt][2 * h + 1] + b1v;
                if (m < NN) {
                    if (OUT16) {
                        __half2 hp = __floats2half2_rn(v0, v1);
                        *(uint32_t*)(outF16 + (size_t)m * 128 + cl) =
                            *reinterpret_cast<uint32_t*>(&hp);
                    } else {
                        float2 v; v.x = v0; v.y = v1;
                        *(float2*)(outF + (size_t)m * 128 + cl) = v;
                    }
                    s0 += v0; s1 += v1;
                    q0 += v0 * v0; q1 += v1 * v1;
                }
            }
        }
#pragma unroll
        for (int off = 16; off >= 4; off >>= 1) {
            s0 += __shfl_down_sync(0xffffffff, s0, off);
            s1 += __shfl_down_sync(0xffffffff, s1, off);
            q0 += __shfl_down_sync(0xffffffff, q0, off);
            q1 += __shfl_down_sync(0xffffffff, q1, off);
        }
        if (lane < 4) {
            atomicAdd(&statSum[cl], s0);
            atomicAdd(&statSum[cl + 1], s1);
            atomicAdd(&statSq[cl], q0);
            atomicAdd(&statSq[cl + 1], q1);
        }
    }
}

// ---------------- final BN apply ----------------
__global__ void bn_apply_kernel(const float* __restrict__ X,
                                const float* __restrict__ gamma,
                                const float* __restrict__ beta,
                                const float* __restrict__ ssum,
                                const float* __restrict__ ssq,
                                float* __restrict__ Y) {
    int idx = blockIdx.x * blockDim.x + threadIdx.x;
    if (idx >= NN * (DD / 4)) return;
    int v = idx >> 5;
    int c4 = idx & 31;
    int c = c4 * 4;
    float4 x = ((const float4*)(X + (size_t)v * DD))[c4];
    float invn = 1.0f / (float)NN;
    float o[4];
    float xi[4] = {x.x, x.y, x.z, x.w};
#pragma unroll
    for (int k = 0; k < 4; k++) {
        float mu = ssum[c + k] * invn;
        float var = ssq[c + k] * invn - mu * mu;
        float rs = rsqrtf(var + BN_EPS);
        o[k] = gamma[c + k] * (xi[k] - mu) * rs + beta[c + k];
    }
    ((float4*)(Y + (size_t)v * DD))[c4] = make_float4(o[0], o[1], o[2], o[3]);
}

// ---------------- launch ----------------
extern "C" void kernel_launch(void* const* d_in, const int* in_sizes, int n_in,
                              void* d_out, int out_size) {
    const int* x          = (const int*)d_in[0];
    const int* edge_index = (const int*)d_in[1];
    const int* edge_attr  = (const int*)d_in[2];
    const float* xemb1 = (const float*)d_in[4];
    const float* xemb2 = (const float*)d_in[5];
    const float* e1    = (const float*)d_in[6];
    const float* e2    = (const float*)d_in[7];
    const float* W1    = (const float*)d_in[8];
    const float* b1    = (const float*)d_in[9];
    const float* W2    = (const float*)d_in[10];
    const float* b2    = (const float*)d_in[11];
    const float* gamma = (const float*)d_in[12];
    const float* beta  = (const float*)d_in[13];
    float* out = (float*)d_out;

    float *p_h2, *p_sum, *p_sq;
    uint16_t *p_h2h, *p_a1, *p_b1, *p_b2;
    cudaGetSymbolAddress((void**)&p_h2,  g_h2);
    cudaGetSymbolAddress((void**)&p_h2h, g_h2h);
    cudaGetSymbolAddress((void**)&p_a1,  g_a1);
    cudaGetSymbolAddress((void**)&p_b1,  g_b1);
    cudaGetSymbolAddress((void**)&p_b2,  g_b2);
    cudaGetSymbolAddress((void**)&p_sum, g_colsum);
    cudaGetSymbolAddress((void**)&p_sq,  g_colsq);

    constexpr int SMEM_F = 67584 + 8 * 16384;   // 198656 B
    cudaFuncSetAttribute(mlp_fused_kernel<true>,
                         cudaFuncAttributeMaxDynamicSharedMemorySize, SMEM_F);
    cudaFuncSetAttribute(mlp_fused_kernel<false>,
                         cudaFuncAttributeMaxDynamicSharedMemorySize, SMEM_F);

    static cudaStream_t sCSR = nullptr, sWB = nullptr;
    static cudaEvent_t evInit = nullptr, evHist = nullptr, evWB = nullptr, evCSR = nullptr;
    if (!sCSR) {
        cudaStreamCreateWithFlags(&sCSR, cudaStreamNonBlocking);
        cudaStreamCreateWithFlags(&sWB, cudaStreamNonBlocking);
        cudaEventCreateWithFlags(&evInit, cudaEventDisableTiming);
        cudaEventCreateWithFlags(&evHist, cudaEventDisableTiming);
        cudaEventCreateWithFlags(&evWB, cudaEventDisableTiming);
        cudaEventCreateWithFlags(&evCSR, cudaEventDisableTiming);
    }

    // weight builds overlap everything up to first GEMM
    cudaEventRecord(evInit, 0);
    cudaStreamWaitEvent(sWB, evInit, 0);
    setupB_kernel<<<(UB1 + 255) / 256, 256, 0, sWB>>>(W1, W2);
    cudaEventRecord(evWB, sWB);

    setupA_kernel<<<(UA4 + 255) / 256, 256>>>(x, xemb1, xemb2);
    hist_kernel<<<(NE + 255) / 256, 256>>>(edge_index, edge_attr);
    cudaEventRecord(evHist, 0);

    // CSR chain on side stream (needed only by layer-1 aggregation)
    cudaStreamWaitEvent(sCSR, evHist, 0);
    scanF_kernel<<<SCAN_G, SCAN_B, 0, sCSR>>>();
    scatter_kernel<<<(NE + 255) / 256, 256, 0, sCSR>>>(edge_index);
    cudaEventRecord(evCSR, sCSR);

    // layer 0
    aggregate0_kernel<<<(NN + 7) / 8, 256>>>(e1, e2);
    cudaStreamWaitEvent(0, evWB, 0);
    mlp_fused_kernel<true><<<MP / 128, 256, SMEM_F>>>(
        p_a1, p_b1, p_b2, b1, b2, nullptr, p_h2h, p_sum, p_sq);

    // layer 1
    cudaStreamWaitEvent(0, evCSR, 0);
    aggregate1_kernel<<<(NN + 7) / 8, 256>>>(
        p_h2h, e1 + 7 * DD, e2 + 3 * DD, gamma, beta, p_sum, p_sq);
    mlp_fused_kernel<false><<<MP / 128, 256, SMEM_F>>>(
        p_a1, p_b1 + 65536, p_b2 + 65536, b1 + 2 * DD, b2 + DD,
        p_h2, nullptr, p_sum + DD, p_sq + DD);

    bn_apply_kernel<<<(NN * 32 + 255) / 256, 256>>>(
        p_h2, gamma + DD, beta + DD, p_sum + DD, p_sq + DD, out);
}